// round 1
// baseline (speedup 1.0000x reference)
#include <cuda_runtime.h>

// ---------------- problem constants ----------------
constexpr int B   = 2;
constexpr int CI  = 256;
constexpr int CR  = 128;
constexpr int H   = 384;
constexpr int W   = 384;
constexpr int h_  = 96;
constexpr int w_  = 96;
constexpr int N   = h_ * w_;       // 9216
constexpr int D   = 64;
constexpr int WIN = 7;
constexpr int PADW= 3;
constexpr int P   = WIN * WIN;     // 49
constexpr int GRP = 8;

// ---------------- scratch (static device globals; no allocs allowed) -------
__device__ float g_img_pool[B * CI * N];   // [b, c, n]
__device__ float g_rad_pool[B * CR * N];   // [b, c, n]
__device__ float g_locc[B * N];            // 2*ln(clamp(occ,1e-6))
__device__ float g_gate[B * N];            // clamp(occ,0,1)
__device__ float g_q[B * N * D];           // [b, n, d]
__device__ float g_k[B * N * D];
__device__ float g_v[B * N * D];
__device__ float g_msg[B * N * D];         // gated message, pre-Wo
__device__ float g_msgo[B * CI * N];       // [b, co, n] channel planes
__device__ float g_qstats[B * GRP * 2];    // mu, rsig
__device__ float g_kstats[B * GRP * 2];

// ---------------- pooling ----------------
__global__ void avgpool_img(const float* __restrict__ in) {
    int t = blockIdx.x * blockDim.x + threadIdx.x;
    if (t >= B * CI * N) return;
    int x = t % w_;
    int y = (t / w_) % h_;
    int bc = t / N;
    const float* p = in + ((size_t)bc * H + y * 4) * W + x * 4;
    float s = 0.f;
#pragma unroll
    for (int r = 0; r < 4; r++) {
        float4 v = *(const float4*)(p + r * W);
        s += v.x + v.y + v.z + v.w;
    }
    g_img_pool[t] = s * 0.0625f;
}

__global__ void maxpool_rad(const float* __restrict__ in) {
    int t = blockIdx.x * blockDim.x + threadIdx.x;
    if (t >= B * CR * N) return;
    int x = t % w_;
    int y = (t / w_) % h_;
    int bc = t / N;
    const float* p = in + ((size_t)bc * H + y * 4) * W + x * 4;
    float m = -3.4e38f;
#pragma unroll
    for (int r = 0; r < 4; r++) {
        float4 v = *(const float4*)(p + r * W);
        m = fmaxf(m, fmaxf(fmaxf(v.x, v.y), fmaxf(v.z, v.w)));
    }
    g_rad_pool[t] = m;
}

__global__ void pool_occ(const float* __restrict__ occ) {
    int t = blockIdx.x * blockDim.x + threadIdx.x;
    if (t >= B * N) return;
    int x = t % w_;
    int y = (t / w_) % h_;
    int b = t / N;
    const float* p = occ + ((size_t)b * H + y * 4) * W + x * 4;
    float m = -3.4e38f;
#pragma unroll
    for (int r = 0; r < 4; r++) {
        float4 v = *(const float4*)(p + r * W);
        m = fmaxf(m, fmaxf(fmaxf(v.x, v.y), fmaxf(v.z, v.w)));
    }
    g_locc[t] = 2.f * logf(fmaxf(m, 1e-6f));
    g_gate[t] = fminf(fmaxf(m, 0.f), 1.f);
}

// ---------------- projections: out[b,n,o] = sum_c W[o,c] * in[b,c,n] -------
// which: 0 -> q (img_pool), 1 -> k (rad_pool), 2 -> v (rad_pool)
__global__ void proj_kernel(const float* __restrict__ Wm, int C, int which) {
    const float* in = (which == 0) ? g_img_pool : g_rad_pool;
    float* out = (which == 0) ? g_q : (which == 1) ? g_k : g_v;

    int b  = blockIdx.y;
    int n0 = blockIdx.x * 64;
    int tx = threadIdx.x & 15;   // n direction (x4)
    int ty = threadIdx.x >> 4;   // o direction (x4)

    __shared__ float Ws[64 * 33];  // [o][c-tile] padded
    __shared__ float Is[32 * 64];  // [c-tile][n]

    float acc[4][4] = {};

    for (int c0 = 0; c0 < C; c0 += 32) {
        for (int i = threadIdx.x; i < 64 * 32; i += 256) {
            int o = i >> 5, c = i & 31;
            Ws[o * 33 + c] = Wm[o * C + c0 + c];
        }
        for (int i = threadIdx.x; i < 32 * 64; i += 256) {
            int c = i >> 6, n = i & 63;
            Is[c * 64 + n] = in[((size_t)b * C + c0 + c) * N + n0 + n];
        }
        __syncthreads();
#pragma unroll
        for (int c = 0; c < 32; c++) {
            float a[4], bb[4];
#pragma unroll
            for (int i = 0; i < 4; i++) a[i] = Ws[(ty * 4 + i) * 33 + c];
#pragma unroll
            for (int j = 0; j < 4; j++) bb[j] = Is[c * 64 + tx * 4 + j];
#pragma unroll
            for (int i = 0; i < 4; i++)
#pragma unroll
                for (int j = 0; j < 4; j++) acc[i][j] += a[i] * bb[j];
        }
        __syncthreads();
    }
#pragma unroll
    for (int j = 0; j < 4; j++) {
        float4 o4 = make_float4(acc[0][j], acc[1][j], acc[2][j], acc[3][j]);
        *(float4*)(out + ((size_t)(b * N + n0 + tx * 4 + j)) * 64 + ty * 4) = o4;
    }
}

// ---------------- GroupNorm ----------------
__global__ void gn_stats(int which) {
    const float* x = which ? g_k : g_q;
    float* st = which ? g_kstats : g_qstats;
    int b = blockIdx.x >> 3, g = blockIdx.x & 7;
    float s = 0.f, s2 = 0.f;
    for (int i = threadIdx.x; i < N * 2; i += 256) {
        int n = i >> 1, hf = i & 1;
        float4 v = *(const float4*)(x + ((size_t)(b * N + n)) * 64 + g * 8 + hf * 4);
        s  += v.x + v.y + v.z + v.w;
        s2 += v.x * v.x + v.y * v.y + v.z * v.z + v.w * v.w;
    }
    __shared__ float ss[256], ss2[256];
    ss[threadIdx.x] = s; ss2[threadIdx.x] = s2;
    __syncthreads();
    for (int o = 128; o; o >>= 1) {
        if (threadIdx.x < o) {
            ss[threadIdx.x]  += ss[threadIdx.x + o];
            ss2[threadIdx.x] += ss2[threadIdx.x + o];
        }
        __syncthreads();
    }
    if (threadIdx.x == 0) {
        const float inv = 1.f / (float)(N * 8);
        float mu = ss[0] * inv;
        float var = ss2[0] * inv - mu * mu;
        st[(b * 8 + g) * 2 + 0] = mu;
        st[(b * 8 + g) * 2 + 1] = rsqrtf(var + 1e-5f);
    }
}

__global__ void gn_apply(int which, const float* __restrict__ gamma,
                         const float* __restrict__ beta) {
    float* x = which ? g_k : g_q;
    const float* st = which ? g_kstats : g_qstats;
    int t = blockIdx.x * blockDim.x + threadIdx.x;
    if (t >= B * N * (D / 4)) return;
    int q4 = t & 15;
    int bn = t >> 4;
    int b  = bn / N;
    int c0 = q4 * 4;
    int g  = c0 >> 3;
    float mu = st[(b * 8 + g) * 2 + 0];
    float rs = st[(b * 8 + g) * 2 + 1];
    float4 v = *(float4*)(x + (size_t)bn * 64 + c0);
    v.x = (v.x - mu) * rs * gamma[c0 + 0] + beta[c0 + 0];
    v.y = (v.y - mu) * rs * gamma[c0 + 1] + beta[c0 + 1];
    v.z = (v.z - mu) * rs * gamma[c0 + 2] + beta[c0 + 2];
    v.w = (v.w - mu) * rs * gamma[c0 + 3] + beta[c0 + 3];
    *(float4*)(x + (size_t)bn * 64 + c0) = v;
}

// ---------------- attention: warp per pixel ----------------
__global__ void attn_kernel() {
    int warp = (blockIdx.x * blockDim.x + threadIdx.x) >> 5;
    int lane = threadIdx.x & 31;
    if (warp >= B * N) return;
    int b = warp / N;
    int n = warp % N;
    int y = n / w_, x = n % w_;

    float2 q2 = ((const float2*)(g_q + (size_t)warp * D))[lane];

    const float LPAD = -27.631021115928547f;  // 2*ln(1e-6)
    float l0 = -1e30f, l1 = -1e30f;
    float m = -1e30f;

    int p = 0;
    for (int dy = -PADW; dy <= PADW; dy++) {
        for (int dx = -PADW; dx <= PADW; dx++, p++) {
            int yy = y + dy, xx = x + dx;
            float logit;
            if ((unsigned)yy < (unsigned)h_ && (unsigned)xx < (unsigned)w_) {
                int nn = b * N + yy * w_ + xx;
                float2 k2 = ((const float2*)(g_k + (size_t)nn * D))[lane];
                float part = q2.x * k2.x + q2.y * k2.y;
#pragma unroll
                for (int off = 16; off; off >>= 1)
                    part += __shfl_xor_sync(0xffffffffu, part, off);
                logit = part * 0.125f + g_locc[nn];
            } else {
                logit = LPAD;
            }
            m = fmaxf(m, logit);
            if (p < 32) { if (lane == p) l0 = logit; }
            else        { if (lane == p - 32) l1 = logit; }
        }
    }

    float e0 = expf(l0 - m);
    float e1 = (lane < P - 32) ? expf(l1 - m) : 0.f;
    float dsum = e0 + e1;
#pragma unroll
    for (int off = 16; off; off >>= 1)
        dsum += __shfl_xor_sync(0xffffffffu, dsum, off);
    float inv = 1.f / dsum;

    float2 acc = make_float2(0.f, 0.f);
    p = 0;
    for (int dy = -PADW; dy <= PADW; dy++) {
        for (int dx = -PADW; dx <= PADW; dx++, p++) {
            int yy = y + dy, xx = x + dx;
            if ((unsigned)yy < (unsigned)h_ && (unsigned)xx < (unsigned)w_) {
                float wgt = __shfl_sync(0xffffffffu, (p < 32) ? e0 : e1, p & 31);
                int nn = b * N + yy * w_ + xx;
                float2 v2 = ((const float2*)(g_v + (size_t)nn * D))[lane];
                acc.x += wgt * v2.x;
                acc.y += wgt * v2.y;
            }
        }
    }
    float gsc = inv * g_gate[warp];   // occ gate commutes with Wo (per-pixel scalar)
    acc.x *= gsc;
    acc.y *= gsc;
    ((float2*)(g_msg + (size_t)warp * D))[lane] = acc;
}

// ---------------- Wo projection: msgo[b,co,n] = sum_d Wo[co,d]*msg[b,n,d] --
__global__ void wo_kernel(const float* __restrict__ Wo) {
    int b   = blockIdx.z;
    int co0 = blockIdx.y * 64;
    int n0  = blockIdx.x * 64;
    int tx  = threadIdx.x & 15;   // n
    int ty  = threadIdx.x >> 4;   // co

    __shared__ float Ws[64 * 65];
    __shared__ float Ms[64 * 65];
    for (int i = threadIdx.x; i < 64 * 64; i += 256) {
        int r = i >> 6, c = i & 63;
        Ws[r * 65 + c] = Wo[(co0 + r) * 64 + c];
        Ms[r * 65 + c] = g_msg[((size_t)(b * N + n0 + r)) * 64 + c];
    }
    __syncthreads();

    float acc[4][4] = {};
#pragma unroll
    for (int d = 0; d < 64; d++) {
        float a[4], bb[4];
#pragma unroll
        for (int i = 0; i < 4; i++) a[i] = Ws[(ty * 4 + i) * 65 + d];
#pragma unroll
        for (int j = 0; j < 4; j++) bb[j] = Ms[(tx * 4 + j) * 65 + d];
#pragma unroll
        for (int i = 0; i < 4; i++)
#pragma unroll
            for (int j = 0; j < 4; j++) acc[i][j] += a[i] * bb[j];
    }
#pragma unroll
    for (int i = 0; i < 4; i++) {
        float4 o4 = make_float4(acc[i][0], acc[i][1], acc[i][2], acc[i][3]);
        *(float4*)(g_msgo + ((size_t)(b * CI + co0 + ty * 4 + i)) * N + n0 + tx * 4) = o4;
    }
}

// ---------------- bilinear upsample (x4, half-pixel, edge clamp) + residual
__global__ void upsample_add(const float* __restrict__ img,
                             const float* __restrict__ alpha,
                             float* __restrict__ out) {
    int t = blockIdx.x * blockDim.x + threadIdx.x;
    if (t >= B * CI * H * W) return;
    int X  = t % W;
    int Y  = (t / W) % H;
    int bc = t / (H * W);

    float fy = (Y + 0.5f) * 0.25f - 0.5f;
    float fx = (X + 0.5f) * 0.25f - 0.5f;
    int y0 = (int)floorf(fy);
    int x0 = (int)floorf(fx);
    float wy = fy - (float)y0;
    float wx = fx - (float)x0;
    int y1 = min(y0 + 1, h_ - 1);
    int x1 = min(x0 + 1, w_ - 1);
    y0 = max(y0, 0);
    x0 = max(x0, 0);

    const float* pl = g_msgo + (size_t)bc * N;
    float v00 = pl[y0 * w_ + x0];
    float v01 = pl[y0 * w_ + x1];
    float v10 = pl[y1 * w_ + x0];
    float v11 = pl[y1 * w_ + x1];
    float v = (1.f - wy) * ((1.f - wx) * v00 + wx * v01)
            +        wy  * ((1.f - wx) * v10 + wx * v11);

    out[t] = img[t] + alpha[0] * v;
}

// ---------------- launch ----------------
extern "C" void kernel_launch(void* const* d_in, const int* in_sizes, int n_in,
                              void* d_out, int out_size) {
    const float* img_bev  = (const float*)d_in[0];
    const float* rad_bev  = (const float*)d_in[1];
    const float* occ_prob = (const float*)d_in[2];
    const float* Wq    = (const float*)d_in[3];
    const float* Wk    = (const float*)d_in[4];
    const float* Wv    = (const float*)d_in[5];
    const float* Wo    = (const float*)d_in[6];
    const float* gq_w  = (const float*)d_in[7];
    const float* gq_b  = (const float*)d_in[8];
    const float* gk_w  = (const float*)d_in[9];
    const float* gk_b  = (const float*)d_in[10];
    const float* alpha = (const float*)d_in[11];
    float* out = (float*)d_out;

    avgpool_img<<<(B * CI * N + 255) / 256, 256>>>(img_bev);
    maxpool_rad<<<(B * CR * N + 255) / 256, 256>>>(rad_bev);
    pool_occ<<<(B * N + 255) / 256, 256>>>(occ_prob);

    dim3 pg(N / 64, B);
    proj_kernel<<<pg, 256>>>(Wq, CI, 0);
    proj_kernel<<<pg, 256>>>(Wk, CR, 1);
    proj_kernel<<<pg, 256>>>(Wv, CR, 2);

    gn_stats<<<B * GRP, 256>>>(0);
    gn_stats<<<B * GRP, 256>>>(1);
    gn_apply<<<(B * N * 16 + 255) / 256, 256>>>(0, gq_w, gq_b);
    gn_apply<<<(B * N * 16 + 255) / 256, 256>>>(1, gk_w, gk_b);

    attn_kernel<<<(B * N) / 8, 256>>>();

    dim3 wg(N / 64, CI / 64, B);
    wo_kernel<<<wg, 256>>>(Wo);

    upsample_add<<<(B * CI * H * W + 255) / 256, 256>>>(img_bev, alpha, out);
}

// round 2
// speedup vs baseline: 1.5417x; 1.5417x over previous
#include <cuda_runtime.h>

// ---------------- problem constants ----------------
constexpr int B   = 2;
constexpr int CI  = 256;
constexpr int CR  = 128;
constexpr int H   = 384;
constexpr int W   = 384;
constexpr int h_  = 96;
constexpr int w_  = 96;
constexpr int N   = h_ * w_;       // 9216
constexpr int D   = 64;
constexpr int WIN = 7;
constexpr int PADW= 3;
constexpr int P   = WIN * WIN;     // 49
constexpr int GRP = 8;

// ---------------- scratch ----------------
__device__ float g_locc[B * N];            // 2*ln(clamp(occ,1e-6))
__device__ float g_gate[B * N];            // clamp(occ,0,1)
__device__ float g_q[B * N * D];           // [b, n, d]
__device__ float g_k[B * N * D];
__device__ float g_v[B * N * D];
__device__ float g_msg[B * N * D];         // gated message, pre-Wo
__device__ float g_msgo[B * CI * N];       // [b, co, n]
__device__ float g_qstats[B * GRP * 2];    // raw (sum, sumsq)
__device__ float g_kstats[B * GRP * 2];

// ---------------- occ pool + stats zeroing ----------------
__global__ void pool_occ(const float* __restrict__ occ) {
    int t = blockIdx.x * blockDim.x + threadIdx.x;
    if (blockIdx.x == 0) {
        if (threadIdx.x < 32) g_qstats[threadIdx.x] = 0.f;
        else if (threadIdx.x < 64) g_kstats[threadIdx.x - 32] = 0.f;
    }
    if (t >= B * N) return;
    int x = t % w_;
    int y = (t / w_) % h_;
    int b = t / N;
    const float* p = occ + ((size_t)b * H + y * 4) * W + x * 4;
    float m = -3.4e38f;
#pragma unroll
    for (int r = 0; r < 4; r++) {
        float4 v = *(const float4*)(p + r * W);
        m = fmaxf(m, fmaxf(fmaxf(v.x, v.y), fmaxf(v.z, v.w)));
    }
    g_locc[t] = 2.f * logf(fmaxf(m, 1e-6f));
    g_gate[t] = fminf(fmaxf(m, 0.f), 1.f);
}

// ---------------- fused avgpool + q projection + GN partial stats ----------
// grid (N/32, B), 128 threads. Tile: 32 n x 64 o, K = 256.
__global__ void proj_q(const float* __restrict__ img, const float* __restrict__ Wq) {
    __shared__ __align__(16) float Ws[32 * 65];
    __shared__ __align__(16) float Is[32 * 32];
    int b  = blockIdx.y;
    int n0 = blockIdx.x * 32;
    int y  = n0 / w_, x0 = n0 % w_;
    int tid = threadIdx.x;
    int tx = tid & 7;    // n quad
    int ty = tid >> 3;   // o quad
    float acc[4][4] = {};

    for (int c0 = 0; c0 < CI; c0 += 32) {
        for (int i = tid; i < 2048; i += 128) {
            int c = i & 31, o = i >> 5;
            Ws[c * 65 + o] = Wq[o * CI + c0 + c];
        }
        for (int i = tid; i < 1024; i += 128) {
            int c = i >> 5, x = i & 31;
            const float* p = img + (((size_t)(b * CI + c0 + c) * H + y * 4) * W) + (x0 + x) * 4;
            float s = 0.f;
#pragma unroll
            for (int r = 0; r < 4; r++) {
                float4 v = *(const float4*)(p + r * W);
                s += v.x + v.y + v.z + v.w;
            }
            Is[c * 32 + x] = s * 0.0625f;
        }
        __syncthreads();
#pragma unroll
        for (int c = 0; c < 32; c++) {
            float a[4];
#pragma unroll
            for (int i = 0; i < 4; i++) a[i] = Ws[c * 65 + ty * 4 + i];
            float4 bb = *(const float4*)&Is[c * 32 + tx * 4];
#pragma unroll
            for (int i = 0; i < 4; i++) {
                acc[i][0] += a[i] * bb.x;
                acc[i][1] += a[i] * bb.y;
                acc[i][2] += a[i] * bb.z;
                acc[i][3] += a[i] * bb.w;
            }
        }
        __syncthreads();
    }

    float s = 0.f, s2 = 0.f;
#pragma unroll
    for (int j = 0; j < 4; j++) {
        float4 o4 = make_float4(acc[0][j], acc[1][j], acc[2][j], acc[3][j]);
        *(float4*)(g_q + ((size_t)(b * N + n0 + tx * 4 + j)) * 64 + ty * 4) = o4;
        s  += o4.x + o4.y + o4.z + o4.w;
        s2 += o4.x * o4.x + o4.y * o4.y + o4.z * o4.z + o4.w * o4.w;
    }
#pragma unroll
    for (int off = 8; off; off >>= 1) {
        s  += __shfl_down_sync(0xffffffffu, s,  off);
        s2 += __shfl_down_sync(0xffffffffu, s2, off);
    }
    if ((tid & 15) == 0) {
        int g = ty >> 1;   // o-range ty*4..ty*4+3 lies in one group of 8
        atomicAdd(&g_qstats[(b * 8 + g) * 2 + 0], s);
        atomicAdd(&g_qstats[(b * 8 + g) * 2 + 1], s2);
    }
}

// ---------------- fused maxpool + k,v projections + GN(k) partial stats ----
__global__ void proj_kv(const float* __restrict__ rad,
                        const float* __restrict__ Wk, const float* __restrict__ Wv) {
    __shared__ __align__(16) float Wks[32 * 65];
    __shared__ __align__(16) float Wvs[32 * 65];
    __shared__ __align__(16) float Is[32 * 32];
    int b  = blockIdx.y;
    int n0 = blockIdx.x * 32;
    int y  = n0 / w_, x0 = n0 % w_;
    int tid = threadIdx.x;
    int tx = tid & 7;
    int ty = tid >> 3;
    float ak4[4][4] = {};
    float av4[4][4] = {};

    for (int c0 = 0; c0 < CR; c0 += 32) {
        for (int i = tid; i < 2048; i += 128) {
            int c = i & 31, o = i >> 5;
            Wks[c * 65 + o] = Wk[o * CR + c0 + c];
            Wvs[c * 65 + o] = Wv[o * CR + c0 + c];
        }
        for (int i = tid; i < 1024; i += 128) {
            int c = i >> 5, x = i & 31;
            const float* p = rad + (((size_t)(b * CR + c0 + c) * H + y * 4) * W) + (x0 + x) * 4;
            float m = -3.4e38f;
#pragma unroll
            for (int r = 0; r < 4; r++) {
                float4 v = *(const float4*)(p + r * W);
                m = fmaxf(m, fmaxf(fmaxf(v.x, v.y), fmaxf(v.z, v.w)));
            }
            Is[c * 32 + x] = m;
        }
        __syncthreads();
#pragma unroll
        for (int c = 0; c < 32; c++) {
            float ka[4], va[4];
#pragma unroll
            for (int i = 0; i < 4; i++) {
                ka[i] = Wks[c * 65 + ty * 4 + i];
                va[i] = Wvs[c * 65 + ty * 4 + i];
            }
            float4 bb = *(const float4*)&Is[c * 32 + tx * 4];
#pragma unroll
            for (int i = 0; i < 4; i++) {
                ak4[i][0] += ka[i] * bb.x; ak4[i][1] += ka[i] * bb.y;
                ak4[i][2] += ka[i] * bb.z; ak4[i][3] += ka[i] * bb.w;
                av4[i][0] += va[i] * bb.x; av4[i][1] += va[i] * bb.y;
                av4[i][2] += va[i] * bb.z; av4[i][3] += va[i] * bb.w;
            }
        }
        __syncthreads();
    }

    float s = 0.f, s2 = 0.f;
#pragma unroll
    for (int j = 0; j < 4; j++) {
        size_t row = ((size_t)(b * N + n0 + tx * 4 + j)) * 64 + ty * 4;
        float4 k4 = make_float4(ak4[0][j], ak4[1][j], ak4[2][j], ak4[3][j]);
        float4 v4 = make_float4(av4[0][j], av4[1][j], av4[2][j], av4[3][j]);
        *(float4*)(g_k + row) = k4;
        *(float4*)(g_v + row) = v4;
        s  += k4.x + k4.y + k4.z + k4.w;
        s2 += k4.x * k4.x + k4.y * k4.y + k4.z * k4.z + k4.w * k4.w;
    }
#pragma unroll
    for (int off = 8; off; off >>= 1) {
        s  += __shfl_down_sync(0xffffffffu, s,  off);
        s2 += __shfl_down_sync(0xffffffffu, s2, off);
    }
    if ((tid & 15) == 0) {
        int g = ty >> 1;
        atomicAdd(&g_kstats[(b * 8 + g) * 2 + 0], s);
        atomicAdd(&g_kstats[(b * 8 + g) * 2 + 1], s2);
    }
}

// ---------------- GroupNorm apply (q and k in one launch) ----------------
__global__ void gn_apply2(const float* __restrict__ gq_w, const float* __restrict__ gq_b,
                          const float* __restrict__ gk_w, const float* __restrict__ gk_b) {
    int t = blockIdx.x * 256 + threadIdx.x;
    const int per = B * N * 16;
    if (t >= 2 * per) return;
    int which = t >= per;
    int u = which ? t - per : t;
    float* x = which ? g_k : g_q;
    const float* st = which ? g_kstats : g_qstats;
    const float* gw = which ? gk_w : gq_w;
    const float* gb = which ? gk_b : gq_b;
    int q4 = u & 15;
    int bn = u >> 4;
    int b  = bn / N;
    int c0 = q4 * 4;
    int g  = c0 >> 3;
    float su  = st[(b * 8 + g) * 2 + 0];
    float su2 = st[(b * 8 + g) * 2 + 1];
    const float inv = 1.f / (float)(N * 8);
    float mu = su * inv;
    float var = su2 * inv - mu * mu;
    float rs = rsqrtf(var + 1e-5f);
    float4 v = *(float4*)(x + (size_t)bn * 64 + c0);
    v.x = (v.x - mu) * rs * gw[c0 + 0] + gb[c0 + 0];
    v.y = (v.y - mu) * rs * gw[c0 + 1] + gb[c0 + 1];
    v.z = (v.z - mu) * rs * gw[c0 + 2] + gb[c0 + 2];
    v.w = (v.w - mu) * rs * gw[c0 + 3] + gb[c0 + 3];
    *(float4*)(x + (size_t)bn * 64 + c0) = v;
}

// ---------------- attention: warp per pixel ----------------
__global__ void attn_kernel() {
    int warp = (blockIdx.x * blockDim.x + threadIdx.x) >> 5;
    int lane = threadIdx.x & 31;
    if (warp >= B * N) return;
    int b = warp / N;
    int n = warp % N;
    int y = n / w_, x = n % w_;

    float2 q2 = ((const float2*)(g_q + (size_t)warp * D))[lane];

    const float LPAD = -27.631021115928547f;  // 2*ln(1e-6)
    float l0 = -1e30f, l1 = -1e30f;
    float m = -1e30f;

    int p = 0;
    for (int dy = -PADW; dy <= PADW; dy++) {
        for (int dx = -PADW; dx <= PADW; dx++, p++) {
            int yy = y + dy, xx = x + dx;
            float logit;
            if ((unsigned)yy < (unsigned)h_ && (unsigned)xx < (unsigned)w_) {
                int nn = b * N + yy * w_ + xx;
                float2 k2 = ((const float2*)(g_k + (size_t)nn * D))[lane];
                float part = q2.x * k2.x + q2.y * k2.y;
#pragma unroll
                for (int off = 16; off; off >>= 1)
                    part += __shfl_xor_sync(0xffffffffu, part, off);
                logit = part * 0.125f + g_locc[nn];
            } else {
                logit = LPAD;
            }
            m = fmaxf(m, logit);
            if (p < 32) { if (lane == p) l0 = logit; }
            else        { if (lane == p - 32) l1 = logit; }
        }
    }

    float e0 = expf(l0 - m);
    float e1 = (lane < P - 32) ? expf(l1 - m) : 0.f;
    float dsum = e0 + e1;
#pragma unroll
    for (int off = 16; off; off >>= 1)
        dsum += __shfl_xor_sync(0xffffffffu, dsum, off);
    float inv = 1.f / dsum;

    float2 acc = make_float2(0.f, 0.f);
    p = 0;
    for (int dy = -PADW; dy <= PADW; dy++) {
        for (int dx = -PADW; dx <= PADW; dx++, p++) {
            int yy = y + dy, xx = x + dx;
            if ((unsigned)yy < (unsigned)h_ && (unsigned)xx < (unsigned)w_) {
                float wgt = __shfl_sync(0xffffffffu, (p < 32) ? e0 : e1, p & 31);
                int nn = b * N + yy * w_ + xx;
                float2 v2 = ((const float2*)(g_v + (size_t)nn * D))[lane];
                acc.x += wgt * v2.x;
                acc.y += wgt * v2.y;
            }
        }
    }
    float gsc = inv * g_gate[warp];   // occ gate commutes with Wo
    acc.x *= gsc;
    acc.y *= gsc;
    ((float2*)(g_msg + (size_t)warp * D))[lane] = acc;
}

// ---------------- Wo projection: msgo[b,co,n] = sum_d Wo[co,d]*msg[b,n,d] --
__global__ void wo_kernel(const float* __restrict__ Wo) {
    int b   = blockIdx.z;
    int co0 = blockIdx.y * 64;
    int n0  = blockIdx.x * 64;
    int tx  = threadIdx.x & 15;   // n
    int ty  = threadIdx.x >> 4;   // co

    __shared__ float Ws[64 * 65];
    __shared__ float Ms[64 * 65];
    for (int i = threadIdx.x; i < 64 * 64; i += 256) {
        int r = i >> 6, c = i & 63;
        Ws[r * 65 + c] = Wo[(co0 + r) * 64 + c];
        Ms[r * 65 + c] = g_msg[((size_t)(b * N + n0 + r)) * 64 + c];
    }
    __syncthreads();

    float acc[4][4] = {};
#pragma unroll
    for (int d = 0; d < 64; d++) {
        float a[4], bb[4];
#pragma unroll
        for (int i = 0; i < 4; i++) a[i] = Ws[(ty * 4 + i) * 65 + d];
#pragma unroll
        for (int j = 0; j < 4; j++) bb[j] = Ms[(tx * 4 + j) * 65 + d];
#pragma unroll
        for (int i = 0; i < 4; i++)
#pragma unroll
            for (int j = 0; j < 4; j++) acc[i][j] += a[i] * bb[j];
    }
#pragma unroll
    for (int i = 0; i < 4; i++) {
        float4 o4 = make_float4(acc[i][0], acc[i][1], acc[i][2], acc[i][3]);
        *(float4*)(g_msgo + ((size_t)(b * CI + co0 + ty * 4 + i)) * N + n0 + tx * 4) = o4;
    }
}

// ------- bilinear x4 upsample + residual: 1 thread = 4 output px ----------
// t = bc*(H*96) + Y*96 + k  ->  outputs at flat index t*4 .. t*4+3
__global__ void upsample_add(const float* __restrict__ img,
                             const float* __restrict__ alpha,
                             float* __restrict__ out) {
    int t = blockIdx.x * blockDim.x + threadIdx.x;
    if (t >= B * CI * H * (W / 4)) return;
    int k  = t % 96;
    int Y  = (t / 96) % H;
    int bc = t / (96 * H);

    int m = Y >> 2, i = Y & 3;
    int y0, y1;
    float wy;
    if (i < 2) { y0 = max(m - 1, 0); y1 = m; wy = (i == 0) ? 0.625f : 0.875f; }
    else       { y0 = m; y1 = min(m + 1, h_ - 1); wy = (i == 2) ? 0.125f : 0.375f; }

    const float* pl = g_msgo + (size_t)bc * N;
    int kl = max(k - 1, 0), kr = min(k + 1, w_ - 1);
    float l0 = pl[y0 * w_ + kl], c0 = pl[y0 * w_ + k], r0 = pl[y0 * w_ + kr];
    float l1 = pl[y1 * w_ + kl], c1 = pl[y1 * w_ + k], r1 = pl[y1 * w_ + kr];

    float a0 = 0.375f * l0 + 0.625f * c0;
    float a1 = 0.125f * l0 + 0.875f * c0;
    float a2 = 0.875f * c0 + 0.125f * r0;
    float a3 = 0.625f * c0 + 0.375f * r0;
    float b0 = 0.375f * l1 + 0.625f * c1;
    float b1 = 0.125f * l1 + 0.875f * c1;
    float b2 = 0.875f * c1 + 0.125f * r1;
    float b3 = 0.625f * c1 + 0.375f * r1;

    float wy1 = 1.f - wy;
    float A = alpha[0];
    float4 iv = *(const float4*)(img + (size_t)t * 4);
    float4 ov;
    ov.x = iv.x + A * (wy1 * a0 + wy * b0);
    ov.y = iv.y + A * (wy1 * a1 + wy * b1);
    ov.z = iv.z + A * (wy1 * a2 + wy * b2);
    ov.w = iv.w + A * (wy1 * a3 + wy * b3);
    *(float4*)(out + (size_t)t * 4) = ov;
}

// ---------------- launch ----------------
extern "C" void kernel_launch(void* const* d_in, const int* in_sizes, int n_in,
                              void* d_out, int out_size) {
    const float* img_bev  = (const float*)d_in[0];
    const float* rad_bev  = (const float*)d_in[1];
    const float* occ_prob = (const float*)d_in[2];
    const float* Wq    = (const float*)d_in[3];
    const float* Wk    = (const float*)d_in[4];
    const float* Wv    = (const float*)d_in[5];
    const float* Wo    = (const float*)d_in[6];
    const float* gq_w  = (const float*)d_in[7];
    const float* gq_b  = (const float*)d_in[8];
    const float* gk_w  = (const float*)d_in[9];
    const float* gk_b  = (const float*)d_in[10];
    const float* alpha = (const float*)d_in[11];
    float* out = (float*)d_out;

    pool_occ<<<(B * N + 255) / 256, 256>>>(occ_prob);

    dim3 pg(N / 32, B);
    proj_q <<<pg, 128>>>(img_bev, Wq);
    proj_kv<<<pg, 128>>>(rad_bev, Wk, Wv);

    gn_apply2<<<(2 * B * N * 16 + 255) / 256, 256>>>(gq_w, gq_b, gk_w, gk_b);

    attn_kernel<<<(B * N) / 8, 256>>>();

    dim3 wg(N / 64, CI / 64, B);
    wo_kernel<<<wg, 256>>>(Wo);

    upsample_add<<<(B * CI * H * (W / 4) + 255) / 256, 256>>>(img_bev, alpha, out);
}

// round 3
// speedup vs baseline: 1.7609x; 1.1422x over previous
#include <cuda_runtime.h>

// ---------------- problem constants ----------------
constexpr int B   = 2;
constexpr int CI  = 256;
constexpr int CR  = 128;
constexpr int H   = 384;
constexpr int W   = 384;
constexpr int h_  = 96;
constexpr int w_  = 96;
constexpr int N   = h_ * w_;       // 9216
constexpr int D   = 64;
constexpr int PADW= 3;
constexpr int P   = 49;
constexpr int GRP = 8;

// ---------------- scratch ----------------
__device__ float g_locc[B * N];            // 2*ln(clamp(occ,1e-6))
__device__ float g_gate[B * N];            // clamp(occ,0,1)
__device__ float g_q[B * N * D];           // [b, n, d]  (raw, pre-GN)
__device__ float g_k[B * N * D];           // raw, pre-GN
__device__ float g_v[B * N * D];
__device__ float g_msg[B * N * D];
__device__ float g_msgo[B * CI * N];       // [b, co, n]
__device__ float g_qstats[B * GRP * 2];    // (sum, sumsq)
__device__ float g_kstats[B * GRP * 2];
__device__ float g_Aq[B * D], g_Bq[B * D]; // GN-as-affine coefficients
__device__ float g_Ak[B * D], g_Bk[B * D];

// ---------------- occ pool + stats zeroing ----------------
__global__ void pool_occ(const float* __restrict__ occ) {
    int t = blockIdx.x * blockDim.x + threadIdx.x;
    if (blockIdx.x == 0) {
        if (threadIdx.x < 32) g_qstats[threadIdx.x] = 0.f;
        else if (threadIdx.x < 64) g_kstats[threadIdx.x - 32] = 0.f;
    }
    if (t >= B * N) return;
    int x = t % w_;
    int y = (t / w_) % h_;
    int b = t / N;
    const float* p = occ + ((size_t)b * H + y * 4) * W + x * 4;
    float m = -3.4e38f;
#pragma unroll
    for (int r = 0; r < 4; r++) {
        float4 v = *(const float4*)(p + r * W);
        m = fmaxf(m, fmaxf(fmaxf(v.x, v.y), fmaxf(v.z, v.w)));
    }
    g_locc[t] = 2.f * logf(fmaxf(m, 1e-6f));
    g_gate[t] = fminf(fmaxf(m, 0.f), 1.f);
}

// ---------------- fused avgpool + q projection + GN partial stats ----------
// grid (N/32, B), 256 threads. Tile: 32 n x 64 o (2 o per thread), K-tile 32.
__global__ void proj_q(const float* __restrict__ img, const float* __restrict__ Wq) {
    __shared__ __align__(16) float Ws[32 * 65];
    __shared__ __align__(16) float Is[32 * 32];
    int b  = blockIdx.y;
    int n0 = blockIdx.x * 32;
    int y  = n0 / w_, x0 = n0 % w_;
    int tid = threadIdx.x;
    int tx = tid & 7;    // n quad
    int ty = tid >> 3;   // o pair (0..31)
    float acc[2][4] = {};

    for (int c0 = 0; c0 < CI; c0 += 32) {
        for (int i = tid; i < 2048; i += 256) {
            int c = i & 31, o = i >> 5;
            Ws[c * 65 + o] = Wq[o * CI + c0 + c];
        }
        for (int i = tid; i < 1024; i += 256) {
            int c = i >> 5, x = i & 31;
            const float* p = img + (((size_t)(b * CI + c0 + c) * H + y * 4) * W) + (x0 + x) * 4;
            float s = 0.f;
#pragma unroll
            for (int r = 0; r < 4; r++) {
                float4 v = *(const float4*)(p + r * W);
                s += v.x + v.y + v.z + v.w;
            }
            Is[c * 32 + x] = s * 0.0625f;
        }
        __syncthreads();
#pragma unroll
        for (int c = 0; c < 32; c++) {
            float a0 = Ws[c * 65 + ty * 2];
            float a1 = Ws[c * 65 + ty * 2 + 1];
            float4 bb = *(const float4*)&Is[c * 32 + tx * 4];
            acc[0][0] += a0 * bb.x; acc[0][1] += a0 * bb.y;
            acc[0][2] += a0 * bb.z; acc[0][3] += a0 * bb.w;
            acc[1][0] += a1 * bb.x; acc[1][1] += a1 * bb.y;
            acc[1][2] += a1 * bb.z; acc[1][3] += a1 * bb.w;
        }
        __syncthreads();
    }

    float s = 0.f, s2 = 0.f;
#pragma unroll
    for (int j = 0; j < 4; j++) {
        float2 o2 = make_float2(acc[0][j], acc[1][j]);
        *(float2*)(g_q + ((size_t)(b * N + n0 + tx * 4 + j)) * 64 + ty * 2) = o2;
        s  += o2.x + o2.y;
        s2 += o2.x * o2.x + o2.y * o2.y;
    }
    // warp w covers o in [w*8, w*8+7] == group w
#pragma unroll
    for (int off = 16; off; off >>= 1) {
        s  += __shfl_down_sync(0xffffffffu, s,  off);
        s2 += __shfl_down_sync(0xffffffffu, s2, off);
    }
    if ((tid & 31) == 0) {
        int g = tid >> 5;
        atomicAdd(&g_qstats[(b * 8 + g) * 2 + 0], s);
        atomicAdd(&g_qstats[(b * 8 + g) * 2 + 1], s2);
    }
}

// ---------------- fused maxpool + k,v projections + GN(k) partial stats ----
__global__ void proj_kv(const float* __restrict__ rad,
                        const float* __restrict__ Wk, const float* __restrict__ Wv) {
    __shared__ __align__(16) float Wks[32 * 65];
    __shared__ __align__(16) float Wvs[32 * 65];
    __shared__ __align__(16) float Is[32 * 32];
    int b  = blockIdx.y;
    int n0 = blockIdx.x * 32;
    int y  = n0 / w_, x0 = n0 % w_;
    int tid = threadIdx.x;
    int tx = tid & 7;
    int ty = tid >> 3;
    float ak[2][4] = {};
    float av[2][4] = {};

    for (int c0 = 0; c0 < CR; c0 += 32) {
        for (int i = tid; i < 2048; i += 256) {
            int c = i & 31, o = i >> 5;
            Wks[c * 65 + o] = Wk[o * CR + c0 + c];
            Wvs[c * 65 + o] = Wv[o * CR + c0 + c];
        }
        for (int i = tid; i < 1024; i += 256) {
            int c = i >> 5, x = i & 31;
            const float* p = rad + (((size_t)(b * CR + c0 + c) * H + y * 4) * W) + (x0 + x) * 4;
            float m = -3.4e38f;
#pragma unroll
            for (int r = 0; r < 4; r++) {
                float4 v = *(const float4*)(p + r * W);
                m = fmaxf(m, fmaxf(fmaxf(v.x, v.y), fmaxf(v.z, v.w)));
            }
            Is[c * 32 + x] = m;
        }
        __syncthreads();
#pragma unroll
        for (int c = 0; c < 32; c++) {
            float ka0 = Wks[c * 65 + ty * 2];
            float ka1 = Wks[c * 65 + ty * 2 + 1];
            float va0 = Wvs[c * 65 + ty * 2];
            float va1 = Wvs[c * 65 + ty * 2 + 1];
            float4 bb = *(const float4*)&Is[c * 32 + tx * 4];
            ak[0][0] += ka0 * bb.x; ak[0][1] += ka0 * bb.y;
            ak[0][2] += ka0 * bb.z; ak[0][3] += ka0 * bb.w;
            ak[1][0] += ka1 * bb.x; ak[1][1] += ka1 * bb.y;
            ak[1][2] += ka1 * bb.z; ak[1][3] += ka1 * bb.w;
            av[0][0] += va0 * bb.x; av[0][1] += va0 * bb.y;
            av[0][2] += va0 * bb.z; av[0][3] += va0 * bb.w;
            av[1][0] += va1 * bb.x; av[1][1] += va1 * bb.y;
            av[1][2] += va1 * bb.z; av[1][3] += va1 * bb.w;
        }
        __syncthreads();
    }

    float s = 0.f, s2 = 0.f;
#pragma unroll
    for (int j = 0; j < 4; j++) {
        size_t row = ((size_t)(b * N + n0 + tx * 4 + j)) * 64 + ty * 2;
        float2 k2 = make_float2(ak[0][j], ak[1][j]);
        float2 v2 = make_float2(av[0][j], av[1][j]);
        *(float2*)(g_k + row) = k2;
        *(float2*)(g_v + row) = v2;
        s  += k2.x + k2.y;
        s2 += k2.x * k2.x + k2.y * k2.y;
    }
#pragma unroll
    for (int off = 16; off; off >>= 1) {
        s  += __shfl_down_sync(0xffffffffu, s,  off);
        s2 += __shfl_down_sync(0xffffffffu, s2, off);
    }
    if ((tid & 31) == 0) {
        int g = tid >> 5;
        atomicAdd(&g_kstats[(b * 8 + g) * 2 + 0], s);
        atomicAdd(&g_kstats[(b * 8 + g) * 2 + 1], s2);
    }
}

// -------- stats -> per-channel affine GN coefficients (1 block) -----------
__global__ void prep_ab(const float* __restrict__ gq_w, const float* __restrict__ gq_b,
                        const float* __restrict__ gk_w, const float* __restrict__ gk_b) {
    int t = threadIdx.x;
    if (t >= B * D) return;
    int b = t >> 6, d = t & 63, g = d >> 3;
    const float inv = 1.f / (float)(N * 8);
    {
        float su  = g_qstats[(b * 8 + g) * 2 + 0];
        float su2 = g_qstats[(b * 8 + g) * 2 + 1];
        float mu = su * inv;
        float rs = rsqrtf(su2 * inv - mu * mu + 1e-5f);
        float A = rs * gq_w[d];
        g_Aq[t] = A;
        g_Bq[t] = gq_b[d] - mu * A;
    }
    {
        float su  = g_kstats[(b * 8 + g) * 2 + 0];
        float su2 = g_kstats[(b * 8 + g) * 2 + 1];
        float mu = su * inv;
        float rs = rsqrtf(su2 * inv - mu * mu + 1e-5f);
        float A = rs * gk_w[d];
        g_Ak[t] = A;
        g_Bk[t] = gk_b[d] - mu * A;
    }
}

// ---------------- attention: warp/pixel, quarter-warp/position ------------
__global__ void attn_kernel() {
    __shared__ float sl[8][52];
    int wib  = threadIdx.x >> 5;
    int lane = threadIdx.x & 31;
    int warp = blockIdx.x * 8 + wib;
    int b = warp / N;
    int n = warp % N;
    int y = n / w_, x = n % w_;
    int grp = lane >> 3;       // window-position group (0..3)
    int sub = lane & 7;        // channel sub-lane
    int c0  = sub * 8;

    // load raw q for my 8 channels, apply q-GN, fold k-GN
    const float* qrow = g_q + (size_t)warp * 64 + c0;
    float4 q0 = *(const float4*)qrow;
    float4 q1 = *(const float4*)(qrow + 4);
    const float* Aqp = g_Aq + b * 64 + c0;
    const float* Bqp = g_Bq + b * 64 + c0;
    const float* Akp = g_Ak + b * 64 + c0;
    const float* Bkp = g_Bk + b * 64 + c0;
    float4 Aq0 = *(const float4*)Aqp,       Aq1 = *(const float4*)(Aqp + 4);
    float4 Bq0 = *(const float4*)Bqp,       Bq1 = *(const float4*)(Bqp + 4);
    float4 Ak0 = *(const float4*)Akp,       Ak1 = *(const float4*)(Akp + 4);
    float4 Bk0 = *(const float4*)Bkp,       Bk1 = *(const float4*)(Bkp + 4);
    float4 qn0, qn1;
    qn0.x = q0.x * Aq0.x + Bq0.x; qn0.y = q0.y * Aq0.y + Bq0.y;
    qn0.z = q0.z * Aq0.z + Bq0.z; qn0.w = q0.w * Aq0.w + Bq0.w;
    qn1.x = q1.x * Aq1.x + Bq1.x; qn1.y = q1.y * Aq1.y + Bq1.y;
    qn1.z = q1.z * Aq1.z + Bq1.z; qn1.w = q1.w * Aq1.w + Bq1.w;
    float qB = qn0.x * Bk0.x + qn0.y * Bk0.y + qn0.z * Bk0.z + qn0.w * Bk0.w
             + qn1.x * Bk1.x + qn1.y * Bk1.y + qn1.z * Bk1.z + qn1.w * Bk1.w;
#pragma unroll
    for (int off = 1; off < 8; off <<= 1)
        qB += __shfl_xor_sync(0xffffffffu, qB, off);
    float qB2 = qB * 0.125f;
    float4 qp0, qp1;
    qp0.x = qn0.x * Ak0.x * 0.125f; qp0.y = qn0.y * Ak0.y * 0.125f;
    qp0.z = qn0.z * Ak0.z * 0.125f; qp0.w = qn0.w * Ak0.w * 0.125f;
    qp1.x = qn1.x * Ak1.x * 0.125f; qp1.y = qn1.y * Ak1.y * 0.125f;
    qp1.z = qn1.z * Ak1.z * 0.125f; qp1.w = qn1.w * Ak1.w * 0.125f;

    const float LPAD = -27.631021115928547f;  // 2*ln(1e-6)

    // pass 1: logits (4 positions per iteration)
    for (int p0 = 0; p0 < P; p0 += 4) {
        int p = p0 + grp;
        float d8 = 0.f;
        int nn = 0;
        bool inb = false;
        if (p < P) {
            int yy = y + p / 7 - PADW;
            int xx = x + p % 7 - PADW;
            inb = ((unsigned)yy < (unsigned)h_) && ((unsigned)xx < (unsigned)w_);
            if (inb) {
                nn = b * N + yy * w_ + xx;
                const float* kr = g_k + (size_t)nn * 64 + c0;
                float4 k0 = *(const float4*)kr;
                float4 k1 = *(const float4*)(kr + 4);
                d8 = qp0.x * k0.x + qp0.y * k0.y + qp0.z * k0.z + qp0.w * k0.w
                   + qp1.x * k1.x + qp1.y * k1.y + qp1.z * k1.z + qp1.w * k1.w;
            }
        }
#pragma unroll
        for (int off = 1; off < 8; off <<= 1)
            d8 += __shfl_xor_sync(0xffffffffu, d8, off);
        float logit = inb ? (d8 + qB2 + g_locc[nn]) : LPAD;
        if (sub == 0 && p < P) sl[wib][p] = logit;
    }
    __syncwarp();

    // softmax over 49 logits
    float l0 = sl[wib][lane];
    float l1 = (lane < P - 32) ? sl[wib][lane + 32] : -1e30f;
    float m = fmaxf(l0, l1);
#pragma unroll
    for (int off = 16; off; off >>= 1)
        m = fmaxf(m, __shfl_xor_sync(0xffffffffu, m, off));
    float e0 = expf(l0 - m);
    float e1 = (lane < P - 32) ? expf(l1 - m) : 0.f;
    float s = e0 + e1;
#pragma unroll
    for (int off = 16; off; off >>= 1)
        s += __shfl_xor_sync(0xffffffffu, s, off);
    float gs = g_gate[warp] / s;     // occ gate commutes with Wo
    sl[wib][lane] = e0 * gs;
    if (lane < P - 32) sl[wib][lane + 32] = e1 * gs;
    __syncwarp();

    // pass 2: weighted v accumulation
    float4 a0 = make_float4(0.f, 0.f, 0.f, 0.f);
    float4 a1 = make_float4(0.f, 0.f, 0.f, 0.f);
    for (int p0 = 0; p0 < P; p0 += 4) {
        int p = p0 + grp;
        if (p < P) {
            int yy = y + p / 7 - PADW;
            int xx = x + p % 7 - PADW;
            if (((unsigned)yy < (unsigned)h_) && ((unsigned)xx < (unsigned)w_)) {
                int nn = b * N + yy * w_ + xx;
                float wgt = sl[wib][p];
                const float* vr = g_v + (size_t)nn * 64 + c0;
                float4 v0 = *(const float4*)vr;
                float4 v1 = *(const float4*)(vr + 4);
                a0.x += wgt * v0.x; a0.y += wgt * v0.y;
                a0.z += wgt * v0.z; a0.w += wgt * v0.w;
                a1.x += wgt * v1.x; a1.y += wgt * v1.y;
                a1.z += wgt * v1.z; a1.w += wgt * v1.w;
            }
        }
    }
    float r[8] = {a0.x, a0.y, a0.z, a0.w, a1.x, a1.y, a1.z, a1.w};
#pragma unroll
    for (int i = 0; i < 8; i++) {
        r[i] += __shfl_xor_sync(0xffffffffu, r[i], 8);
        r[i] += __shfl_xor_sync(0xffffffffu, r[i], 16);
    }
    if (grp == 0) {
        float* mr = g_msg + (size_t)warp * 64 + c0;
        *(float4*)mr       = make_float4(r[0], r[1], r[2], r[3]);
        *(float4*)(mr + 4) = make_float4(r[4], r[5], r[6], r[7]);
    }
}

// ---------------- Wo projection: msgo[b,co,n] = sum_d Wo[co,d]*msg[b,n,d] --
__global__ void wo_kernel(const float* __restrict__ Wo) {
    int b   = blockIdx.z;
    int co0 = blockIdx.y * 64;
    int n0  = blockIdx.x * 64;
    int tx  = threadIdx.x & 15;   // n
    int ty  = threadIdx.x >> 4;   // co

    __shared__ float Ws[64 * 65];
    __shared__ float Ms[64 * 65];
    for (int i = threadIdx.x; i < 64 * 64; i += 256) {
        int r = i >> 6, c = i & 63;
        Ws[r * 65 + c] = Wo[(co0 + r) * 64 + c];
        Ms[r * 65 + c] = g_msg[((size_t)(b * N + n0 + r)) * 64 + c];
    }
    __syncthreads();

    float acc[4][4] = {};
#pragma unroll
    for (int d = 0; d < 64; d++) {
        float a[4], bb[4];
#pragma unroll
        for (int i = 0; i < 4; i++) a[i] = Ws[(ty * 4 + i) * 65 + d];
#pragma unroll
        for (int j = 0; j < 4; j++) bb[j] = Ms[(tx * 4 + j) * 65 + d];
#pragma unroll
        for (int i = 0; i < 4; i++)
#pragma unroll
            for (int j = 0; j < 4; j++) acc[i][j] += a[i] * bb[j];
    }
#pragma unroll
    for (int i = 0; i < 4; i++) {
        float4 o4 = make_float4(acc[i][0], acc[i][1], acc[i][2], acc[i][3]);
        *(float4*)(g_msgo + ((size_t)(b * CI + co0 + ty * 4 + i)) * N + n0 + tx * 4) = o4;
    }
}

// ------- bilinear x4 upsample + residual: 1 thread = 4 output px ----------
__global__ void upsample_add(const float* __restrict__ img,
                             const float* __restrict__ alpha,
                             float* __restrict__ out) {
    int t = blockIdx.x * blockDim.x + threadIdx.x;
    if (t >= B * CI * H * (W / 4)) return;
    int k  = t % 96;
    int Y  = (t / 96) % H;
    int bc = t / (96 * H);

    int m = Y >> 2, i = Y & 3;
    int y0, y1;
    float wy;
    if (i < 2) { y0 = max(m - 1, 0); y1 = m; wy = (i == 0) ? 0.625f : 0.875f; }
    else       { y0 = m; y1 = min(m + 1, h_ - 1); wy = (i == 2) ? 0.125f : 0.375f; }

    const float* pl = g_msgo + (size_t)bc * N;
    int kl = max(k - 1, 0), kr = min(k + 1, w_ - 1);
    float l0 = pl[y0 * w_ + kl], c0 = pl[y0 * w_ + k], r0 = pl[y0 * w_ + kr];
    float l1 = pl[y1 * w_ + kl], c1 = pl[y1 * w_ + k], r1 = pl[y1 * w_ + kr];

    float a0 = 0.375f * l0 + 0.625f * c0;
    float a1 = 0.125f * l0 + 0.875f * c0;
    float a2 = 0.875f * c0 + 0.125f * r0;
    float a3 = 0.625f * c0 + 0.375f * r0;
    float b0 = 0.375f * l1 + 0.625f * c1;
    float b1 = 0.125f * l1 + 0.875f * c1;
    float b2 = 0.875f * c1 + 0.125f * r1;
    float b3 = 0.625f * c1 + 0.375f * r1;

    float wy1 = 1.f - wy;
    float A = alpha[0];
    float4 iv = *(const float4*)(img + (size_t)t * 4);
    float4 ov;
    ov.x = iv.x + A * (wy1 * a0 + wy * b0);
    ov.y = iv.y + A * (wy1 * a1 + wy * b1);
    ov.z = iv.z + A * (wy1 * a2 + wy * b2);
    ov.w = iv.w + A * (wy1 * a3 + wy * b3);
    *(float4*)(out + (size_t)t * 4) = ov;
}

// ---------------- launch ----------------
extern "C" void kernel_launch(void* const* d_in, const int* in_sizes, int n_in,
                              void* d_out, int out_size) {
    const float* img_bev  = (const float*)d_in[0];
    const float* rad_bev  = (const float*)d_in[1];
    const float* occ_prob = (const float*)d_in[2];
    const float* Wq    = (const float*)d_in[3];
    const float* Wk    = (const float*)d_in[4];
    const float* Wv    = (const float*)d_in[5];
    const float* Wo    = (const float*)d_in[6];
    const float* gq_w  = (const float*)d_in[7];
    const float* gq_b  = (const float*)d_in[8];
    const float* gk_w  = (const float*)d_in[9];
    const float* gk_b  = (const float*)d_in[10];
    const float* alpha = (const float*)d_in[11];
    float* out = (float*)d_out;

    pool_occ<<<(B * N + 255) / 256, 256>>>(occ_prob);

    dim3 pg(N / 32, B);
    proj_q <<<pg, 256>>>(img_bev, Wq);
    proj_kv<<<pg, 256>>>(rad_bev, Wk, Wv);

    prep_ab<<<1, 128>>>(gq_w, gq_b, gk_w, gk_b);

    attn_kernel<<<(B * N) / 8, 256>>>();

    dim3 wg(N / 64, CI / 64, B);
    wo_kernel<<<wg, 256>>>(Wo);

    upsample_add<<<(B * CI * H * (W / 4) + 255) / 256, 256>>>(img_bev, alpha, out);
}

// round 4
// speedup vs baseline: 1.7673x; 1.0036x over previous
#include <cuda_runtime.h>

// ---------------- problem constants ----------------
constexpr int B   = 2;
constexpr int CI  = 256;
constexpr int CR  = 128;
constexpr int H   = 384;
constexpr int W   = 384;
constexpr int h_  = 96;
constexpr int w_  = 96;
constexpr int N   = h_ * w_;       // 9216
constexpr int D   = 64;
constexpr int PADW= 3;
constexpr int P   = 49;
constexpr int GRP = 8;

// ---------------- scratch ----------------
__device__ float g_locc[B * N];            // 2*ln(clamp(occ,1e-6))
__device__ float g_gate[B * N];            // clamp(occ,0,1)
__device__ float g_q[B * N * D];           // [b, n, d]  (raw, pre-GN)
__device__ float g_k[B * N * D];           // raw, pre-GN
__device__ float g_v[B * N * D];
__device__ float g_msg[B * N * D];
__device__ float g_msgo[B * CI * N];       // [b, co, n]
__device__ float g_qstats[B * GRP * 2];    // (sum, sumsq)
__device__ float g_kstats[B * GRP * 2];

// ---------------- f32x2 packed-FMA helpers (2x fp32 rate, full precision) --
__device__ __forceinline__ unsigned long long ffma2(unsigned long long a,
                                                    unsigned long long b,
                                                    unsigned long long c) {
    unsigned long long d;
    asm("fma.rn.f32x2 %0, %1, %2, %3;" : "=l"(d) : "l"(a), "l"(b), "l"(c));
    return d;
}
__device__ __forceinline__ unsigned long long pack2(float x) {
    unsigned long long d;
    asm("mov.b64 %0, {%1, %2};" : "=l"(d)
        : "r"(__float_as_uint(x)), "r"(__float_as_uint(x)));
    return d;
}

// ---------------- occ pool + stats zeroing ----------------
__global__ void pool_occ(const float* __restrict__ occ) {
    int t = blockIdx.x * blockDim.x + threadIdx.x;
    if (blockIdx.x == 0) {
        if (threadIdx.x < 32) g_qstats[threadIdx.x] = 0.f;
        else if (threadIdx.x < 64) g_kstats[threadIdx.x - 32] = 0.f;
    }
    if (t >= B * N) return;
    int x = t % w_;
    int y = (t / w_) % h_;
    int b = t / N;
    const float* p = occ + ((size_t)b * H + y * 4) * W + x * 4;
    float m = -3.4e38f;
#pragma unroll
    for (int r = 0; r < 4; r++) {
        float4 v = *(const float4*)(p + r * W);
        m = fmaxf(m, fmaxf(fmaxf(v.x, v.y), fmaxf(v.z, v.w)));
    }
    g_locc[t] = 2.f * logf(fmaxf(m, 1e-6f));
    g_gate[t] = fminf(fmaxf(m, 0.f), 1.f);
}

// ---------------- fused avgpool + q projection + GN partial stats ----------
__global__ void proj_q(const float* __restrict__ img, const float* __restrict__ Wq) {
    __shared__ __align__(16) float Ws[32 * 65];
    __shared__ __align__(16) float Is[32 * 32];
    int b  = blockIdx.y;
    int n0 = blockIdx.x * 32;
    int y  = n0 / w_, x0 = n0 % w_;
    int tid = threadIdx.x;
    int tx = tid & 7;    // n quad
    int ty = tid >> 3;   // o pair (0..31)
    float acc[2][4] = {};

    for (int c0 = 0; c0 < CI; c0 += 32) {
        for (int i = tid; i < 2048; i += 256) {
            int c = i & 31, o = i >> 5;
            Ws[c * 65 + o] = Wq[o * CI + c0 + c];
        }
        for (int i = tid; i < 1024; i += 256) {
            int c = i >> 5, x = i & 31;
            const float* p = img + (((size_t)(b * CI + c0 + c) * H + y * 4) * W) + (x0 + x) * 4;
            float s = 0.f;
#pragma unroll
            for (int r = 0; r < 4; r++) {
                float4 v = *(const float4*)(p + r * W);
                s += v.x + v.y + v.z + v.w;
            }
            Is[c * 32 + x] = s * 0.0625f;
        }
        __syncthreads();
#pragma unroll
        for (int c = 0; c < 32; c++) {
            float a0 = Ws[c * 65 + ty * 2];
            float a1 = Ws[c * 65 + ty * 2 + 1];
            float4 bb = *(const float4*)&Is[c * 32 + tx * 4];
            acc[0][0] += a0 * bb.x; acc[0][1] += a0 * bb.y;
            acc[0][2] += a0 * bb.z; acc[0][3] += a0 * bb.w;
            acc[1][0] += a1 * bb.x; acc[1][1] += a1 * bb.y;
            acc[1][2] += a1 * bb.z; acc[1][3] += a1 * bb.w;
        }
        __syncthreads();
    }

    float s = 0.f, s2 = 0.f;
#pragma unroll
    for (int j = 0; j < 4; j++) {
        float2 o2 = make_float2(acc[0][j], acc[1][j]);
        *(float2*)(g_q + ((size_t)(b * N + n0 + tx * 4 + j)) * 64 + ty * 2) = o2;
        s  += o2.x + o2.y;
        s2 += o2.x * o2.x + o2.y * o2.y;
    }
#pragma unroll
    for (int off = 16; off; off >>= 1) {
        s  += __shfl_down_sync(0xffffffffu, s,  off);
        s2 += __shfl_down_sync(0xffffffffu, s2, off);
    }
    if ((tid & 31) == 0) {
        int g = tid >> 5;
        atomicAdd(&g_qstats[(b * 8 + g) * 2 + 0], s);
        atomicAdd(&g_qstats[(b * 8 + g) * 2 + 1], s2);
    }
}

// ---------------- fused maxpool + k,v projections + GN(k) partial stats ----
__global__ void proj_kv(const float* __restrict__ rad,
                        const float* __restrict__ Wk, const float* __restrict__ Wv) {
    __shared__ __align__(16) float Wks[32 * 65];
    __shared__ __align__(16) float Wvs[32 * 65];
    __shared__ __align__(16) float Is[32 * 32];
    int b  = blockIdx.y;
    int n0 = blockIdx.x * 32;
    int y  = n0 / w_, x0 = n0 % w_;
    int tid = threadIdx.x;
    int tx = tid & 7;
    int ty = tid >> 3;
    float ak[2][4] = {};
    float av[2][4] = {};

    for (int c0 = 0; c0 < CR; c0 += 32) {
        for (int i = tid; i < 2048; i += 256) {
            int c = i & 31, o = i >> 5;
            Wks[c * 65 + o] = Wk[o * CR + c0 + c];
            Wvs[c * 65 + o] = Wv[o * CR + c0 + c];
        }
        for (int i = tid; i < 1024; i += 256) {
            int c = i >> 5, x = i & 31;
            const float* p = rad + (((size_t)(b * CR + c0 + c) * H + y * 4) * W) + (x0 + x) * 4;
            float m = -3.4e38f;
#pragma unroll
            for (int r = 0; r < 4; r++) {
                float4 v = *(const float4*)(p + r * W);
                m = fmaxf(m, fmaxf(fmaxf(v.x, v.y), fmaxf(v.z, v.w)));
            }
            Is[c * 32 + x] = m;
        }
        __syncthreads();
#pragma unroll
        for (int c = 0; c < 32; c++) {
            float ka0 = Wks[c * 65 + ty * 2];
            float ka1 = Wks[c * 65 + ty * 2 + 1];
            float va0 = Wvs[c * 65 + ty * 2];
            float va1 = Wvs[c * 65 + ty * 2 + 1];
            float4 bb = *(const float4*)&Is[c * 32 + tx * 4];
            ak[0][0] += ka0 * bb.x; ak[0][1] += ka0 * bb.y;
            ak[0][2] += ka0 * bb.z; ak[0][3] += ka0 * bb.w;
            ak[1][0] += ka1 * bb.x; ak[1][1] += ka1 * bb.y;
            ak[1][2] += ka1 * bb.z; ak[1][3] += ka1 * bb.w;
            av[0][0] += va0 * bb.x; av[0][1] += va0 * bb.y;
            av[0][2] += va0 * bb.z; av[0][3] += va0 * bb.w;
            av[1][0] += va1 * bb.x; av[1][1] += va1 * bb.y;
            av[1][2] += va1 * bb.z; av[1][3] += va1 * bb.w;
        }
        __syncthreads();
    }

    float s = 0.f, s2 = 0.f;
#pragma unroll
    for (int j = 0; j < 4; j++) {
        size_t row = ((size_t)(b * N + n0 + tx * 4 + j)) * 64 + ty * 2;
        float2 k2 = make_float2(ak[0][j], ak[1][j]);
        float2 v2 = make_float2(av[0][j], av[1][j]);
        *(float2*)(g_k + row) = k2;
        *(float2*)(g_v + row) = v2;
        s  += k2.x + k2.y;
        s2 += k2.x * k2.x + k2.y * k2.y;
    }
#pragma unroll
    for (int off = 16; off; off >>= 1) {
        s  += __shfl_down_sync(0xffffffffu, s,  off);
        s2 += __shfl_down_sync(0xffffffffu, s2, off);
    }
    if ((tid & 31) == 0) {
        int g = tid >> 5;
        atomicAdd(&g_kstats[(b * 8 + g) * 2 + 0], s);
        atomicAdd(&g_kstats[(b * 8 + g) * 2 + 1], s2);
    }
}

// ---------------- attention: warp/pixel, quarter-warp/position ------------
// GN-affine coefficients computed per block (kills the prep_ab kernel).
__global__ void attn_kernel(const float* __restrict__ gq_w, const float* __restrict__ gq_b,
                            const float* __restrict__ gk_w, const float* __restrict__ gk_b) {
    __shared__ float sl[8][52];
    __shared__ __align__(16) float sQA[64], sQB[64], sAk[64], sBk[64];
    int wib  = threadIdx.x >> 5;
    int lane = threadIdx.x & 31;
    int warp = blockIdx.x * 8 + wib;
    int b = warp / N;           // uniform per block (1152 blocks per batch)
    int n = warp % N;
    int y = n / w_, x = n % w_;
    int grp = lane >> 3;
    int sub = lane & 7;
    int c0  = sub * 8;

    if (threadIdx.x < 64) {
        int d = threadIdx.x, g = d >> 3;
        const float inv = 1.f / (float)(N * 8);
        float su  = g_qstats[(b * 8 + g) * 2 + 0];
        float su2 = g_qstats[(b * 8 + g) * 2 + 1];
        float mu = su * inv;
        float rs = rsqrtf(su2 * inv - mu * mu + 1e-5f);
        float A = rs * gq_w[d];
        sQA[d] = A;
        sQB[d] = gq_b[d] - mu * A;
        su  = g_kstats[(b * 8 + g) * 2 + 0];
        su2 = g_kstats[(b * 8 + g) * 2 + 1];
        mu = su * inv;
        rs = rsqrtf(su2 * inv - mu * mu + 1e-5f);
        A = rs * gk_w[d];
        sAk[d] = A;
        sBk[d] = gk_b[d] - mu * A;
    }
    __syncthreads();

    const float* qrow = g_q + (size_t)warp * 64 + c0;
    float4 q0 = *(const float4*)qrow;
    float4 q1 = *(const float4*)(qrow + 4);
    float4 Aq0 = *(const float4*)&sQA[c0], Aq1 = *(const float4*)&sQA[c0 + 4];
    float4 Bq0 = *(const float4*)&sQB[c0], Bq1 = *(const float4*)&sQB[c0 + 4];
    float4 Ak0 = *(const float4*)&sAk[c0], Ak1 = *(const float4*)&sAk[c0 + 4];
    float4 Bk0 = *(const float4*)&sBk[c0], Bk1 = *(const float4*)&sBk[c0 + 4];
    float4 qn0, qn1;
    qn0.x = q0.x * Aq0.x + Bq0.x; qn0.y = q0.y * Aq0.y + Bq0.y;
    qn0.z = q0.z * Aq0.z + Bq0.z; qn0.w = q0.w * Aq0.w + Bq0.w;
    qn1.x = q1.x * Aq1.x + Bq1.x; qn1.y = q1.y * Aq1.y + Bq1.y;
    qn1.z = q1.z * Aq1.z + Bq1.z; qn1.w = q1.w * Aq1.w + Bq1.w;
    float qB = qn0.x * Bk0.x + qn0.y * Bk0.y + qn0.z * Bk0.z + qn0.w * Bk0.w
             + qn1.x * Bk1.x + qn1.y * Bk1.y + qn1.z * Bk1.z + qn1.w * Bk1.w;
#pragma unroll
    for (int off = 1; off < 8; off <<= 1)
        qB += __shfl_xor_sync(0xffffffffu, qB, off);
    float qB2 = qB * 0.125f;
    float4 qp0, qp1;
    qp0.x = qn0.x * Ak0.x * 0.125f; qp0.y = qn0.y * Ak0.y * 0.125f;
    qp0.z = qn0.z * Ak0.z * 0.125f; qp0.w = qn0.w * Ak0.w * 0.125f;
    qp1.x = qn1.x * Ak1.x * 0.125f; qp1.y = qn1.y * Ak1.y * 0.125f;
    qp1.z = qn1.z * Ak1.z * 0.125f; qp1.w = qn1.w * Ak1.w * 0.125f;

    const float LPAD = -27.631021115928547f;  // 2*ln(1e-6)

    for (int p0 = 0; p0 < P; p0 += 4) {
        int p = p0 + grp;
        float d8 = 0.f;
        int nn = 0;
        bool inb = false;
        if (p < P) {
            int yy = y + p / 7 - PADW;
            int xx = x + p % 7 - PADW;
            inb = ((unsigned)yy < (unsigned)h_) && ((unsigned)xx < (unsigned)w_);
            if (inb) {
                nn = b * N + yy * w_ + xx;
                const float* kr = g_k + (size_t)nn * 64 + c0;
                float4 k0 = *(const float4*)kr;
                float4 k1 = *(const float4*)(kr + 4);
                d8 = qp0.x * k0.x + qp0.y * k0.y + qp0.z * k0.z + qp0.w * k0.w
                   + qp1.x * k1.x + qp1.y * k1.y + qp1.z * k1.z + qp1.w * k1.w;
            }
        }
#pragma unroll
        for (int off = 1; off < 8; off <<= 1)
            d8 += __shfl_xor_sync(0xffffffffu, d8, off);
        float logit = inb ? (d8 + qB2 + g_locc[nn]) : LPAD;
        if (sub == 0 && p < P) sl[wib][p] = logit;
    }
    __syncwarp();

    float l0 = sl[wib][lane];
    float l1 = (lane < P - 32) ? sl[wib][lane + 32] : -1e30f;
    float m = fmaxf(l0, l1);
#pragma unroll
    for (int off = 16; off; off >>= 1)
        m = fmaxf(m, __shfl_xor_sync(0xffffffffu, m, off));
    float e0 = __expf(l0 - m);
    float e1 = (lane < P - 32) ? __expf(l1 - m) : 0.f;
    float s = e0 + e1;
#pragma unroll
    for (int off = 16; off; off >>= 1)
        s += __shfl_xor_sync(0xffffffffu, s, off);
    float gs = g_gate[warp] / s;     // occ gate commutes with Wo
    sl[wib][lane] = e0 * gs;
    if (lane < P - 32) sl[wib][lane + 32] = e1 * gs;
    __syncwarp();

    float4 a0 = make_float4(0.f, 0.f, 0.f, 0.f);
    float4 a1 = make_float4(0.f, 0.f, 0.f, 0.f);
    for (int p0 = 0; p0 < P; p0 += 4) {
        int p = p0 + grp;
        if (p < P) {
            int yy = y + p / 7 - PADW;
            int xx = x + p % 7 - PADW;
            if (((unsigned)yy < (unsigned)h_) && ((unsigned)xx < (unsigned)w_)) {
                int nn = b * N + yy * w_ + xx;
                float wgt = sl[wib][p];
                const float* vr = g_v + (size_t)nn * 64 + c0;
                float4 v0 = *(const float4*)vr;
                float4 v1 = *(const float4*)(vr + 4);
                a0.x += wgt * v0.x; a0.y += wgt * v0.y;
                a0.z += wgt * v0.z; a0.w += wgt * v0.w;
                a1.x += wgt * v1.x; a1.y += wgt * v1.y;
                a1.z += wgt * v1.z; a1.w += wgt * v1.w;
            }
        }
    }
    float r[8] = {a0.x, a0.y, a0.z, a0.w, a1.x, a1.y, a1.z, a1.w};
#pragma unroll
    for (int i = 0; i < 8; i++) {
        r[i] += __shfl_xor_sync(0xffffffffu, r[i], 8);
        r[i] += __shfl_xor_sync(0xffffffffu, r[i], 16);
    }
    if (grp == 0) {
        float* mr = g_msg + (size_t)warp * 64 + c0;
        *(float4*)mr       = make_float4(r[0], r[1], r[2], r[3]);
        *(float4*)(mr + 4) = make_float4(r[4], r[5], r[6], r[7]);
    }
}

// ---------------- Wo projection with packed f32x2 FMA ----------------
// tile: 128 co x 128 n, 256 threads, 8x8 per thread, smem d-major.
__global__ __launch_bounds__(256) void wo_kernel(const float* __restrict__ Wo) {
    __shared__ float Ws[32 * 132];   // [d][o]
    __shared__ float Ms[32 * 132];   // [d][n]
    int b   = blockIdx.z;
    int co0 = blockIdx.y * 128;
    int n0  = blockIdx.x * 128;
    int tid = threadIdx.x;
    int tx = tid & 15;   // n octet
    int ty = tid >> 4;   // co octet

    unsigned long long acc[8][4] = {};

    for (int kc = 0; kc < 2; kc++) {
        int d0 = kc * 32;
        for (int idx = tid; idx < 1024; idx += 256) {
            int r = idx >> 3, dq = idx & 7;
            float4 v = *(const float4*)(Wo + (size_t)(co0 + r) * 64 + d0 + dq * 4);
            Ws[(dq * 4 + 0) * 132 + r] = v.x;
            Ws[(dq * 4 + 1) * 132 + r] = v.y;
            Ws[(dq * 4 + 2) * 132 + r] = v.z;
            Ws[(dq * 4 + 3) * 132 + r] = v.w;
            float4 u = *(const float4*)(g_msg + ((size_t)(b * N + n0 + r)) * 64 + d0 + dq * 4);
            Ms[(dq * 4 + 0) * 132 + r] = u.x;
            Ms[(dq * 4 + 1) * 132 + r] = u.y;
            Ms[(dq * 4 + 2) * 132 + r] = u.z;
            Ms[(dq * 4 + 3) * 132 + r] = u.w;
        }
        __syncthreads();
#pragma unroll
        for (int d = 0; d < 32; d++) {
            unsigned long long b2[4];
#pragma unroll
            for (int jp = 0; jp < 4; jp++)
                b2[jp] = *(const unsigned long long*)&Ms[d * 132 + tx * 8 + jp * 2];
#pragma unroll
            for (int i = 0; i < 8; i++) {
                unsigned long long a2 = pack2(Ws[d * 132 + ty * 8 + i]);
#pragma unroll
                for (int jp = 0; jp < 4; jp++)
                    acc[i][jp] = ffma2(a2, b2[jp], acc[i][jp]);
            }
        }
        __syncthreads();
    }
#pragma unroll
    for (int i = 0; i < 8; i++) {
        float2 r0 = *(float2*)&acc[i][0];
        float2 r1 = *(float2*)&acc[i][1];
        float2 r2 = *(float2*)&acc[i][2];
        float2 r3 = *(float2*)&acc[i][3];
        float* dst = g_msgo + ((size_t)(b * CI + co0 + ty * 8 + i)) * N + n0 + tx * 8;
        *(float4*)dst       = make_float4(r0.x, r0.y, r1.x, r1.y);
        *(float4*)(dst + 4) = make_float4(r2.x, r2.y, r3.x, r3.y);
    }
}

// ------- bilinear x4 upsample + residual: 1 thread = 8 output px ----------
__global__ void upsample_add(const float* __restrict__ img,
                             const float* __restrict__ alpha,
                             float* __restrict__ out) {
    int t = blockIdx.x * blockDim.x + threadIdx.x;
    if (t >= B * CI * H * 48) return;
    int k2 = t % 48;
    int Y  = (t / 48) % H;
    int bc = t / (48 * H);

    int m = Y >> 2, i = Y & 3;
    int y0, y1;
    float wy;
    if (i < 2) { y0 = max(m - 1, 0); y1 = m; wy = (i == 0) ? 0.625f : 0.875f; }
    else       { y0 = m; y1 = min(m + 1, h_ - 1); wy = (i == 2) ? 0.125f : 0.375f; }

    const float* pl = g_msgo + (size_t)bc * N;
    int x0 = 2 * k2;
    int xm = max(x0 - 1, 0), x1 = x0 + 1, x2 = min(x0 + 2, w_ - 1);
    const float* r0p = pl + y0 * w_;
    const float* r1p = pl + y1 * w_;
    float wy1 = 1.f - wy;
    float pm = wy1 * r0p[xm] + wy * r1p[xm];
    float p0 = wy1 * r0p[x0] + wy * r1p[x0];
    float p1 = wy1 * r0p[x1] + wy * r1p[x1];
    float p2 = wy1 * r0p[x2] + wy * r1p[x2];

    float A = alpha[0];
    size_t base = (size_t)t * 8;
    float4 i0 = *(const float4*)(img + base);
    float4 i1 = *(const float4*)(img + base + 4);
    float4 o0, o1;
    o0.x = i0.x + A * (0.375f * pm + 0.625f * p0);
    o0.y = i0.y + A * (0.125f * pm + 0.875f * p0);
    o0.z = i0.z + A * (0.875f * p0 + 0.125f * p1);
    o0.w = i0.w + A * (0.625f * p0 + 0.375f * p1);
    o1.x = i1.x + A * (0.375f * p0 + 0.625f * p1);
    o1.y = i1.y + A * (0.125f * p0 + 0.875f * p1);
    o1.z = i1.z + A * (0.875f * p1 + 0.125f * p2);
    o1.w = i1.w + A * (0.625f * p1 + 0.375f * p2);
    *(float4*)(out + base)     = o0;
    *(float4*)(out + base + 4) = o1;
}

// ---------------- launch ----------------
extern "C" void kernel_launch(void* const* d_in, const int* in_sizes, int n_in,
                              void* d_out, int out_size) {
    const float* img_bev  = (const float*)d_in[0];
    const float* rad_bev  = (const float*)d_in[1];
    const float* occ_prob = (const float*)d_in[2];
    const float* Wq    = (const float*)d_in[3];
    const float* Wk    = (const float*)d_in[4];
    const float* Wv    = (const float*)d_in[5];
    const float* Wo    = (const float*)d_in[6];
    const float* gq_w  = (const float*)d_in[7];
    const float* gq_b  = (const float*)d_in[8];
    const float* gk_w  = (const float*)d_in[9];
    const float* gk_b  = (const float*)d_in[10];
    const float* alpha = (const float*)d_in[11];
    float* out = (float*)d_out;

    pool_occ<<<(B * N + 255) / 256, 256>>>(occ_prob);

    dim3 pg(N / 32, B);
    proj_q <<<pg, 256>>>(img_bev, Wq);
    proj_kv<<<pg, 256>>>(rad_bev, Wk, Wv);

    attn_kernel<<<(B * N) / 8, 256>>>(gq_w, gq_b, gk_w, gk_b);

    dim3 wg(N / 128, CI / 128, B);
    wo_kernel<<<wg, 256>>>(Wo);

    upsample_add<<<(B * CI * H * 48 + 255) / 256, 256>>>(img_bev, alpha, out);
}

// round 5
// speedup vs baseline: 1.8388x; 1.0404x over previous
#include <cuda_runtime.h>

// ---------------- problem constants ----------------
constexpr int B   = 2;
constexpr int CI  = 256;
constexpr int CR  = 128;
constexpr int H   = 384;
constexpr int W   = 384;
constexpr int h_  = 96;
constexpr int w_  = 96;
constexpr int N   = h_ * w_;       // 9216
constexpr int D   = 64;
constexpr int P   = 49;
constexpr int GRP = 8;

// attention tile geometry
constexpr int TX = 16;             // tile width (pixels)
constexpr int TY = 4;              // tile height (one warp per row)
constexpr int HC = TX + 6;         // 22 halo cols
constexpr int HR = TY + 6;         // 10 halo rows
constexpr int NCOL = HC * HR;      // 220
constexpr int CSTR = 33;           // float2 stride per col (32 pairs + pad)

// dynamic smem layout for attn
constexpr int KV_BYTES   = NCOL * CSTR * 8;        // 58080
constexpr int W_OFF      = KV_BYTES;               // 58080
constexpr int W_BYTES    = 64 * 49 * 4;            // 12544
constexpr int LOCC_OFF   = W_OFF + W_BYTES;        // 70624
constexpr int LOCC_BYTES = NCOL * 4;               // 880
constexpr int COEF_OFF   = LOCC_OFF + LOCC_BYTES;  // 71504
constexpr int SMEM_ATTN  = COEF_OFF + 4 * 64 * 4;  // 72528

// ---------------- scratch ----------------
__device__ float g_locc[B * N];            // 2*ln(clamp(occ,1e-6))
__device__ float g_gate[B * N];            // clamp(occ,0,1)
__device__ float g_q[B * N * D];           // [b, n, d]  (raw, pre-GN)
__device__ float g_k[B * N * D];           // raw, pre-GN
__device__ float g_v[B * N * D];
__device__ float g_msg[B * N * D];
__device__ float g_msgo[B * CI * N];       // [b, co, n]
__device__ float g_qstats[B * GRP * 2];    // (sum, sumsq)
__device__ float g_kstats[B * GRP * 2];

// ---------------- f32x2 packed-FMA helpers ----------------
__device__ __forceinline__ unsigned long long ffma2(unsigned long long a,
                                                    unsigned long long b,
                                                    unsigned long long c) {
    unsigned long long d;
    asm("fma.rn.f32x2 %0, %1, %2, %3;" : "=l"(d) : "l"(a), "l"(b), "l"(c));
    return d;
}
__device__ __forceinline__ unsigned long long pack2(float x) {
    unsigned long long d;
    asm("mov.b64 %0, {%1, %2};" : "=l"(d)
        : "r"(__float_as_uint(x)), "r"(__float_as_uint(x)));
    return d;
}
__device__ __forceinline__ float2 ffma2v(float2 a, float2 b, float2 c) {
    float2 d;
    asm("fma.rn.f32x2 %0, %1, %2, %3;"
        : "=l"(reinterpret_cast<unsigned long long&>(d))
        : "l"(reinterpret_cast<unsigned long long&>(a)),
          "l"(reinterpret_cast<unsigned long long&>(b)),
          "l"(reinterpret_cast<unsigned long long&>(c)));
    return d;
}

// ---------------- occ pool + stats zeroing ----------------
__global__ void pool_occ(const float* __restrict__ occ) {
    int t = blockIdx.x * blockDim.x + threadIdx.x;
    if (blockIdx.x == 0) {
        if (threadIdx.x < 32) g_qstats[threadIdx.x] = 0.f;
        else if (threadIdx.x < 64) g_kstats[threadIdx.x - 32] = 0.f;
    }
    if (t >= B * N) return;
    int x = t % w_;
    int y = (t / w_) % h_;
    int b = t / N;
    const float* p = occ + ((size_t)b * H + y * 4) * W + x * 4;
    float m = -3.4e38f;
#pragma unroll
    for (int r = 0; r < 4; r++) {
        float4 v = *(const float4*)(p + r * W);
        m = fmaxf(m, fmaxf(fmaxf(v.x, v.y), fmaxf(v.z, v.w)));
    }
    g_locc[t] = 2.f * logf(fmaxf(m, 1e-6f));
    g_gate[t] = fminf(fmaxf(m, 0.f), 1.f);
}

// ---------------- fused avgpool + q projection + GN partial stats ----------
__global__ void proj_q(const float* __restrict__ img, const float* __restrict__ Wq) {
    __shared__ __align__(16) float Ws[32 * 65];
    __shared__ __align__(16) float Is[32 * 32];
    int b  = blockIdx.y;
    int n0 = blockIdx.x * 32;
    int y  = n0 / w_, x0 = n0 % w_;
    int tid = threadIdx.x;
    int tx = tid & 7;    // n quad
    int ty = tid >> 3;   // o pair (0..31)
    float acc[2][4] = {};

    for (int c0 = 0; c0 < CI; c0 += 32) {
        for (int i = tid; i < 2048; i += 256) {
            int c = i & 31, o = i >> 5;
            Ws[c * 65 + o] = Wq[o * CI + c0 + c];
        }
        for (int i = tid; i < 1024; i += 256) {
            int c = i >> 5, x = i & 31;
            const float* p = img + (((size_t)(b * CI + c0 + c) * H + y * 4) * W) + (x0 + x) * 4;
            float s = 0.f;
#pragma unroll
            for (int r = 0; r < 4; r++) {
                float4 v = *(const float4*)(p + r * W);
                s += v.x + v.y + v.z + v.w;
            }
            Is[c * 32 + x] = s * 0.0625f;
        }
        __syncthreads();
#pragma unroll
        for (int c = 0; c < 32; c++) {
            float a0 = Ws[c * 65 + ty * 2];
            float a1 = Ws[c * 65 + ty * 2 + 1];
            float4 bb = *(const float4*)&Is[c * 32 + tx * 4];
            acc[0][0] += a0 * bb.x; acc[0][1] += a0 * bb.y;
            acc[0][2] += a0 * bb.z; acc[0][3] += a0 * bb.w;
            acc[1][0] += a1 * bb.x; acc[1][1] += a1 * bb.y;
            acc[1][2] += a1 * bb.z; acc[1][3] += a1 * bb.w;
        }
        __syncthreads();
    }

    float s = 0.f, s2 = 0.f;
#pragma unroll
    for (int j = 0; j < 4; j++) {
        float2 o2 = make_float2(acc[0][j], acc[1][j]);
        *(float2*)(g_q + ((size_t)(b * N + n0 + tx * 4 + j)) * 64 + ty * 2) = o2;
        s  += o2.x + o2.y;
        s2 += o2.x * o2.x + o2.y * o2.y;
    }
#pragma unroll
    for (int off = 16; off; off >>= 1) {
        s  += __shfl_down_sync(0xffffffffu, s,  off);
        s2 += __shfl_down_sync(0xffffffffu, s2, off);
    }
    if ((tid & 31) == 0) {
        int g = tid >> 5;
        atomicAdd(&g_qstats[(b * 8 + g) * 2 + 0], s);
        atomicAdd(&g_qstats[(b * 8 + g) * 2 + 1], s2);
    }
}

// ---------------- fused maxpool + k,v projections + GN(k) partial stats ----
__global__ void proj_kv(const float* __restrict__ rad,
                        const float* __restrict__ Wk, const float* __restrict__ Wv) {
    __shared__ __align__(16) float Wks[32 * 65];
    __shared__ __align__(16) float Wvs[32 * 65];
    __shared__ __align__(16) float Is[32 * 32];
    int b  = blockIdx.y;
    int n0 = blockIdx.x * 32;
    int y  = n0 / w_, x0 = n0 % w_;
    int tid = threadIdx.x;
    int tx = tid & 7;
    int ty = tid >> 3;
    float ak[2][4] = {};
    float av[2][4] = {};

    for (int c0 = 0; c0 < CR; c0 += 32) {
        for (int i = tid; i < 2048; i += 256) {
            int c = i & 31, o = i >> 5;
            Wks[c * 65 + o] = Wk[o * CR + c0 + c];
            Wvs[c * 65 + o] = Wv[o * CR + c0 + c];
        }
        for (int i = tid; i < 1024; i += 256) {
            int c = i >> 5, x = i & 31;
            const float* p = rad + (((size_t)(b * CR + c0 + c) * H + y * 4) * W) + (x0 + x) * 4;
            float m = -3.4e38f;
#pragma unroll
            for (int r = 0; r < 4; r++) {
                float4 v = *(const float4*)(p + r * W);
                m = fmaxf(m, fmaxf(fmaxf(v.x, v.y), fmaxf(v.z, v.w)));
            }
            Is[c * 32 + x] = m;
        }
        __syncthreads();
#pragma unroll
        for (int c = 0; c < 32; c++) {
            float ka0 = Wks[c * 65 + ty * 2];
            float ka1 = Wks[c * 65 + ty * 2 + 1];
            float va0 = Wvs[c * 65 + ty * 2];
            float va1 = Wvs[c * 65 + ty * 2 + 1];
            float4 bb = *(const float4*)&Is[c * 32 + tx * 4];
            ak[0][0] += ka0 * bb.x; ak[0][1] += ka0 * bb.y;
            ak[0][2] += ka0 * bb.z; ak[0][3] += ka0 * bb.w;
            ak[1][0] += ka1 * bb.x; ak[1][1] += ka1 * bb.y;
            ak[1][2] += ka1 * bb.z; ak[1][3] += ka1 * bb.w;
            av[0][0] += va0 * bb.x; av[0][1] += va0 * bb.y;
            av[0][2] += va0 * bb.z; av[0][3] += va0 * bb.w;
            av[1][0] += va1 * bb.x; av[1][1] += va1 * bb.y;
            av[1][2] += va1 * bb.z; av[1][3] += va1 * bb.w;
        }
        __syncthreads();
    }

    float s = 0.f, s2 = 0.f;
#pragma unroll
    for (int j = 0; j < 4; j++) {
        size_t row = ((size_t)(b * N + n0 + tx * 4 + j)) * 64 + ty * 2;
        float2 k2 = make_float2(ak[0][j], ak[1][j]);
        float2 v2 = make_float2(av[0][j], av[1][j]);
        *(float2*)(g_k + row) = k2;
        *(float2*)(g_v + row) = v2;
        s  += k2.x + k2.y;
        s2 += k2.x * k2.x + k2.y * k2.y;
    }
#pragma unroll
    for (int off = 16; off; off >>= 1) {
        s  += __shfl_down_sync(0xffffffffu, s,  off);
        s2 += __shfl_down_sync(0xffffffffu, s2, off);
    }
    if ((tid & 31) == 0) {
        int g = tid >> 5;
        atomicAdd(&g_kstats[(b * 8 + g) * 2 + 0], s);
        atomicAdd(&g_kstats[(b * 8 + g) * 2 + 1], s2);
    }
}

// ---------------- attention: tiled, lane-per-pixel ----------------
// block = 128 threads (4 warps), tile 16x4 pixels. lane = (pix, channel-half).
// k/v halo staged in smem once per tile; weights in smem; GN folded into q.
__global__ __launch_bounds__(128)
void attn_kernel(const float* __restrict__ gq_w, const float* __restrict__ gq_b,
                 const float* __restrict__ gk_w, const float* __restrict__ gk_b) {
    extern __shared__ char sm_[];
    float2* kv_s   = (float2*)sm_;                  // [col][chpair], stride 33
    float*  w_s    = (float*)(sm_ + W_OFF);         // [64 px][49]
    float*  locc_s = (float*)(sm_ + LOCC_OFF);      // [col]
    float*  sQA    = (float*)(sm_ + COEF_OFF);
    float*  sQB    = sQA + 64;
    float*  sAk    = sQA + 128;
    float*  sBk    = sQA + 192;

    int x0 = blockIdx.x * TX, y0 = blockIdx.y * TY, b = blockIdx.z;
    int tid  = threadIdx.x;
    int wrp  = tid >> 5;          // tile row
    int lane = tid & 31;
    int pix  = lane & 15;         // x within tile
    int half = lane >> 4;         // channel half (0: ch 0-31, 1: ch 32-63)

    if (tid < 64) {
        int d = tid, g = d >> 3;
        const float inv = 1.f / (float)(N * 8);
        float su  = g_qstats[(b * 8 + g) * 2 + 0];
        float su2 = g_qstats[(b * 8 + g) * 2 + 1];
        float mu = su * inv;
        float rs = rsqrtf(su2 * inv - mu * mu + 1e-5f);
        float A = rs * gq_w[d];
        sQA[d] = A;
        sQB[d] = gq_b[d] - mu * A;
        su  = g_kstats[(b * 8 + g) * 2 + 0];
        su2 = g_kstats[(b * 8 + g) * 2 + 1];
        mu = su * inv;
        rs = rsqrtf(su2 * inv - mu * mu + 1e-5f);
        A = rs * gk_w[d];
        sAk[d] = A;
        sBk[d] = gk_b[d] - mu * A;
    }

    // ---- stage k halo (+locc), zero-filled outside the image ----
    for (int i = tid; i < NCOL * 16; i += 128) {
        int col = i >> 4, quad = i & 15;
        int r = col / HC, cc = col - r * HC;
        int yy = y0 - 3 + r, xx = x0 - 3 + cc;
        bool ok = ((unsigned)yy < (unsigned)h_) && ((unsigned)xx < (unsigned)w_);
        int nn = b * N + yy * w_ + xx;
        float4 v = make_float4(0.f, 0.f, 0.f, 0.f);
        if (ok) v = *(const float4*)(g_k + (size_t)nn * 64 + quad * 4);
        kv_s[col * CSTR + quad * 2]     = make_float2(v.x, v.y);
        kv_s[col * CSTR + quad * 2 + 1] = make_float2(v.z, v.w);
        if (quad == 0) locc_s[col] = ok ? g_locc[nn] : 0.f;
    }
    __syncthreads();

    int nq = b * N + (y0 + wrp) * w_ + x0 + pix;

    // ---- q: load 32 channels, fold q-GN and k-GN (A,B) ----
    float2 qp[16];
    float qB = 0.f;
    {
        const float* qr = g_q + (size_t)nq * 64 + half * 32;
#pragma unroll
        for (int c4 = 0; c4 < 32; c4 += 4) {
            float4 q4 = *(const float4*)(qr + c4);
            int d = half * 32 + c4;
            float n0 = q4.x * sQA[d + 0] + sQB[d + 0];
            float n1 = q4.y * sQA[d + 1] + sQB[d + 1];
            float n2 = q4.z * sQA[d + 2] + sQB[d + 2];
            float n3 = q4.w * sQA[d + 3] + sQB[d + 3];
            qB += n0 * sBk[d + 0] + n1 * sBk[d + 1]
                + n2 * sBk[d + 2] + n3 * sBk[d + 3];
            qp[c4 / 2]     = make_float2(n0 * sAk[d + 0] * 0.125f, n1 * sAk[d + 1] * 0.125f);
            qp[c4 / 2 + 1] = make_float2(n2 * sAk[d + 2] * 0.125f, n3 * sAk[d + 3] * 0.125f);
        }
    }
    qB += __shfl_xor_sync(0xffffffffu, qB, 16);
    float qB2 = qB * 0.125f;

    const float LPAD = -27.631021115928547f;  // 2*ln(1e-6)
    float m = -1e30f;
    float* wr = &w_s[(wrp * 16 + pix) * 49];

    // ---- pass 1: logits ----
    int p = 0;
    for (int dy = 0; dy < 7; dy++) {
        int yy = y0 + wrp + dy - 3;
        bool yok = (unsigned)yy < (unsigned)h_;
        int colr = (wrp + dy) * HC + pix;
#pragma unroll
        for (int dx = 0; dx < 7; dx++, p++) {
            int col = colr + dx;
            const float2* kp = &kv_s[col * CSTR + half * 16];
            float2 a2 = make_float2(0.f, 0.f);
            float2 b2 = make_float2(0.f, 0.f);
#pragma unroll
            for (int c = 0; c < 16; c += 2) {
                a2 = ffma2v(qp[c],     kp[c],     a2);
                b2 = ffma2v(qp[c + 1], kp[c + 1], b2);
            }
            float dot = a2.x + a2.y + b2.x + b2.y;
            dot += __shfl_xor_sync(0xffffffffu, dot, 16);
            int xx = x0 + pix + dx - 3;
            bool inb = yok && ((unsigned)xx < (unsigned)w_);
            float logit = inb ? (dot + qB2 + locc_s[col]) : LPAD;
            m = fmaxf(m, logit);
            if (half == 0) wr[p] = logit;
        }
    }
    __syncwarp();

    // ---- softmax (halves split the 49 positions) ----
    float s = 0.f;
    {
        int pa = half ? 25 : 0, pb = half ? 49 : 25;
        for (int q = pa; q < pb; q++) {
            float e = __expf(wr[q] - m);
            wr[q] = e;
            s += e;
        }
    }
    s += __shfl_xor_sync(0xffffffffu, s, 16);
    float gs = g_gate[nq] / s;   // occ gate commutes with Wo

    // ---- stage v halo into the same buffer ----
    __syncthreads();
    for (int i = tid; i < NCOL * 16; i += 128) {
        int col = i >> 4, quad = i & 15;
        int r = col / HC, cc = col - r * HC;
        int yy = y0 - 3 + r, xx = x0 - 3 + cc;
        bool ok = ((unsigned)yy < (unsigned)h_) && ((unsigned)xx < (unsigned)w_);
        float4 v = make_float4(0.f, 0.f, 0.f, 0.f);
        if (ok) v = *(const float4*)(g_v + ((size_t)(b * N + yy * w_ + xx)) * 64 + quad * 4);
        kv_s[col * CSTR + quad * 2]     = make_float2(v.x, v.y);
        kv_s[col * CSTR + quad * 2 + 1] = make_float2(v.z, v.w);
    }
    __syncthreads();

    // ---- pass 2: weighted v accumulation (OOB v = 0, no mask needed) ----
    float2 acc[16];
#pragma unroll
    for (int c = 0; c < 16; c++) acc[c] = make_float2(0.f, 0.f);
    p = 0;
    for (int dy = 0; dy < 7; dy++) {
        int colr = (wrp + dy) * HC + pix;
#pragma unroll
        for (int dx = 0; dx < 7; dx++, p++) {
            float wgt = wr[p];
            float2 w2 = make_float2(wgt, wgt);
            const float2* vp = &kv_s[(colr + dx) * CSTR + half * 16];
#pragma unroll
            for (int c = 0; c < 16; c++) acc[c] = ffma2v(w2, vp[c], acc[c]);
        }
    }
    float* mp = g_msg + (size_t)nq * 64 + half * 32;
#pragma unroll
    for (int c = 0; c < 16; c += 2) {
        *(float4*)(mp + c * 2) = make_float4(acc[c].x * gs, acc[c].y * gs,
                                             acc[c + 1].x * gs, acc[c + 1].y * gs);
    }
}

// ---------------- Wo projection with packed f32x2 FMA ----------------
__global__ __launch_bounds__(256) void wo_kernel(const float* __restrict__ Wo) {
    __shared__ float Ws[32 * 132];   // [d][o]
    __shared__ float Ms[32 * 132];   // [d][n]
    int b   = blockIdx.z;
    int co0 = blockIdx.y * 128;
    int n0  = blockIdx.x * 128;
    int tid = threadIdx.x;
    int tx = tid & 15;   // n octet
    int ty = tid >> 4;   // co octet

    unsigned long long acc[8][4] = {};

    for (int kc = 0; kc < 2; kc++) {
        int d0 = kc * 32;
        for (int idx = tid; idx < 1024; idx += 256) {
            int r = idx >> 3, dq = idx & 7;
            float4 v = *(const float4*)(Wo + (size_t)(co0 + r) * 64 + d0 + dq * 4);
            Ws[(dq * 4 + 0) * 132 + r] = v.x;
            Ws[(dq * 4 + 1) * 132 + r] = v.y;
            Ws[(dq * 4 + 2) * 132 + r] = v.z;
            Ws[(dq * 4 + 3) * 132 + r] = v.w;
            float4 u = *(const float4*)(g_msg + ((size_t)(b * N + n0 + r)) * 64 + d0 + dq * 4);
            Ms[(dq * 4 + 0) * 132 + r] = u.x;
            Ms[(dq * 4 + 1) * 132 + r] = u.y;
            Ms[(dq * 4 + 2) * 132 + r] = u.z;
            Ms[(dq * 4 + 3) * 132 + r] = u.w;
        }
        __syncthreads();
#pragma unroll
        for (int d = 0; d < 32; d++) {
            unsigned long long b2[4];
#pragma unroll
            for (int jp = 0; jp < 4; jp++)
                b2[jp] = *(const unsigned long long*)&Ms[d * 132 + tx * 8 + jp * 2];
#pragma unroll
            for (int i = 0; i < 8; i++) {
                unsigned long long a2 = pack2(Ws[d * 132 + ty * 8 + i]);
#pragma unroll
                for (int jp = 0; jp < 4; jp++)
                    acc[i][jp] = ffma2(a2, b2[jp], acc[i][jp]);
            }
        }
        __syncthreads();
    }
#pragma unroll
    for (int i = 0; i < 8; i++) {
        float2 r0 = *(float2*)&acc[i][0];
        float2 r1 = *(float2*)&acc[i][1];
        float2 r2 = *(float2*)&acc[i][2];
        float2 r3 = *(float2*)&acc[i][3];
        float* dst = g_msgo + ((size_t)(b * CI + co0 + ty * 8 + i)) * N + n0 + tx * 8;
        *(float4*)dst       = make_float4(r0.x, r0.y, r1.x, r1.y);
        *(float4*)(dst + 4) = make_float4(r2.x, r2.y, r3.x, r3.y);
    }
}

// ------- bilinear x4 upsample + residual: 1 thread = 8 output px ----------
__global__ void upsample_add(const float* __restrict__ img,
                             const float* __restrict__ alpha,
                             float* __restrict__ out) {
    int t = blockIdx.x * blockDim.x + threadIdx.x;
    if (t >= B * CI * H * 48) return;
    int k2 = t % 48;
    int Y  = (t / 48) % H;
    int bc = t / (48 * H);

    int m = Y >> 2, i = Y & 3;
    int y0, y1;
    float wy;
    if (i < 2) { y0 = max(m - 1, 0); y1 = m; wy = (i == 0) ? 0.625f : 0.875f; }
    else       { y0 = m; y1 = min(m + 1, h_ - 1); wy = (i == 2) ? 0.125f : 0.375f; }

    const float* pl = g_msgo + (size_t)bc * N;
    int x0 = 2 * k2;
    int xm = max(x0 - 1, 0), x1 = x0 + 1, x2 = min(x0 + 2, w_ - 1);
    const float* r0p = pl + y0 * w_;
    const float* r1p = pl + y1 * w_;
    float wy1 = 1.f - wy;
    float pm = wy1 * r0p[xm] + wy * r1p[xm];
    float p0 = wy1 * r0p[x0] + wy * r1p[x0];
    float p1 = wy1 * r0p[x1] + wy * r1p[x1];
    float p2 = wy1 * r0p[x2] + wy * r1p[x2];

    float A = alpha[0];
    size_t base = (size_t)t * 8;
    float4 i0 = *(const float4*)(img + base);
    float4 i1 = *(const float4*)(img + base + 4);
    float4 o0, o1;
    o0.x = i0.x + A * (0.375f * pm + 0.625f * p0);
    o0.y = i0.y + A * (0.125f * pm + 0.875f * p0);
    o0.z = i0.z + A * (0.875f * p0 + 0.125f * p1);
    o0.w = i0.w + A * (0.625f * p0 + 0.375f * p1);
    o1.x = i1.x + A * (0.375f * p0 + 0.625f * p1);
    o1.y = i1.y + A * (0.125f * p0 + 0.875f * p1);
    o1.z = i1.z + A * (0.875f * p1 + 0.125f * p2);
    o1.w = i1.w + A * (0.625f * p1 + 0.375f * p2);
    *(float4*)(out + base)     = o0;
    *(float4*)(out + base + 4) = o1;
}

// ---------------- launch ----------------
extern "C" void kernel_launch(void* const* d_in, const int* in_sizes, int n_in,
                              void* d_out, int out_size) {
    const float* img_bev  = (const float*)d_in[0];
    const float* rad_bev  = (const float*)d_in[1];
    const float* occ_prob = (const float*)d_in[2];
    const float* Wq    = (const float*)d_in[3];
    const float* Wk    = (const float*)d_in[4];
    const float* Wv    = (const float*)d_in[5];
    const float* Wo    = (const float*)d_in[6];
    const float* gq_w  = (const float*)d_in[7];
    const float* gq_b  = (const float*)d_in[8];
    const float* gk_w  = (const float*)d_in[9];
    const float* gk_b  = (const float*)d_in[10];
    const float* alpha = (const float*)d_in[11];
    float* out = (float*)d_out;

    cudaFuncSetAttribute(attn_kernel,
                         cudaFuncAttributeMaxDynamicSharedMemorySize, SMEM_ATTN);

    pool_occ<<<(B * N + 255) / 256, 256>>>(occ_prob);

    dim3 pg(N / 32, B);
    proj_q <<<pg, 256>>>(img_bev, Wq);
    proj_kv<<<pg, 256>>>(rad_bev, Wk, Wv);

    dim3 ag(w_ / TX, h_ / TY, B);
    attn_kernel<<<ag, 128, SMEM_ATTN>>>(gq_w, gq_b, gk_w, gk_b);

    dim3 wg(N / 128, CI / 128, B);
    wo_kernel<<<wg, 256>>>(Wo);

    upsample_add<<<(B * CI * H * 48 + 255) / 256, 256>>>(img_bev, alpha, out);
}

// round 6
// speedup vs baseline: 1.8653x; 1.0144x over previous
#include <cuda_runtime.h>

// ---------------- problem constants ----------------
constexpr int B   = 2;
constexpr int CI  = 256;
constexpr int CR  = 128;
constexpr int H   = 384;
constexpr int W   = 384;
constexpr int h_  = 96;
constexpr int w_  = 96;
constexpr int N   = h_ * w_;       // 9216
constexpr int D   = 64;
constexpr int P   = 49;
constexpr int GRP = 8;

// attention tile geometry: 8x4 pixels, lane = (pix, channel-quarter)
constexpr int TX = 8;
constexpr int TY = 4;
constexpr int HC = TX + 6;         // 14
constexpr int HR = TY + 6;         // 10
constexpr int NCOL = HC * HR;      // 140
constexpr int CSTR = 33;           // float2 stride per col

// ---------------- scratch ----------------
__device__ float g_locc[B * N];            // 2*ln(clamp(occ,1e-6))
__device__ float g_gate[B * N];            // clamp(occ,0,1)
__device__ float g_q[B * N * D];           // [b, n, d]  (raw, pre-GN)
__device__ float g_k[B * N * D];           // raw, pre-GN
__device__ float g_v[B * N * D];
__device__ float g_msg[B * N * D];
__device__ float g_msgo[B * CI * N];       // [b, co, n]
__device__ float g_qstats[B * GRP * 2];    // (sum, sumsq)
__device__ float g_kstats[B * GRP * 2];

// ---------------- f32x2 packed-FMA helpers ----------------
__device__ __forceinline__ unsigned long long ffma2(unsigned long long a,
                                                    unsigned long long b,
                                                    unsigned long long c) {
    unsigned long long d;
    asm("fma.rn.f32x2 %0, %1, %2, %3;" : "=l"(d) : "l"(a), "l"(b), "l"(c));
    return d;
}
__device__ __forceinline__ unsigned long long pack2(float x) {
    unsigned long long d;
    asm("mov.b64 %0, {%1, %2};" : "=l"(d)
        : "r"(__float_as_uint(x)), "r"(__float_as_uint(x)));
    return d;
}
__device__ __forceinline__ float2 ffma2v(float2 a, float2 b, float2 c) {
    float2 d;
    asm("fma.rn.f32x2 %0, %1, %2, %3;"
        : "=l"(reinterpret_cast<unsigned long long&>(d))
        : "l"(reinterpret_cast<unsigned long long&>(a)),
          "l"(reinterpret_cast<unsigned long long&>(b)),
          "l"(reinterpret_cast<unsigned long long&>(c)));
    return d;
}

// ---------------- occ pool + stats zeroing ----------------
__global__ void pool_occ(const float* __restrict__ occ) {
    int t = blockIdx.x * blockDim.x + threadIdx.x;
    if (blockIdx.x == 0) {
        if (threadIdx.x < 32) g_qstats[threadIdx.x] = 0.f;
        else if (threadIdx.x < 64) g_kstats[threadIdx.x - 32] = 0.f;
    }
    if (t >= B * N) return;
    int x = t % w_;
    int y = (t / w_) % h_;
    int b = t / N;
    const float* p = occ + ((size_t)b * H + y * 4) * W + x * 4;
    float m = -3.4e38f;
#pragma unroll
    for (int r = 0; r < 4; r++) {
        float4 v = *(const float4*)(p + r * W);
        m = fmaxf(m, fmaxf(fmaxf(v.x, v.y), fmaxf(v.z, v.w)));
    }
    g_locc[t] = 2.f * logf(fmaxf(m, 1e-6f));
    g_gate[t] = fminf(fmaxf(m, 0.f), 1.f);
}

// ---------------- fused avgpool + q projection + GN partial stats ----------
__global__ void proj_q(const float* __restrict__ img, const float* __restrict__ Wq) {
    __shared__ __align__(16) float Ws[32 * 65];
    __shared__ __align__(16) float Is[32 * 32];
    int b  = blockIdx.y;
    int n0 = blockIdx.x * 32;
    int y  = n0 / w_, x0 = n0 % w_;
    int tid = threadIdx.x;
    int tx = tid & 7;    // n quad
    int ty = tid >> 3;   // o pair (0..31)
    float acc[2][4] = {};

    for (int c0 = 0; c0 < CI; c0 += 32) {
        for (int i = tid; i < 2048; i += 256) {
            int c = i & 31, o = i >> 5;
            Ws[c * 65 + o] = Wq[o * CI + c0 + c];
        }
        for (int i = tid; i < 1024; i += 256) {
            int c = i >> 5, x = i & 31;
            const float* p = img + (((size_t)(b * CI + c0 + c) * H + y * 4) * W) + (x0 + x) * 4;
            float s = 0.f;
#pragma unroll
            for (int r = 0; r < 4; r++) {
                float4 v = *(const float4*)(p + r * W);
                s += v.x + v.y + v.z + v.w;
            }
            Is[c * 32 + x] = s * 0.0625f;
        }
        __syncthreads();
#pragma unroll
        for (int c = 0; c < 32; c++) {
            float a0 = Ws[c * 65 + ty * 2];
            float a1 = Ws[c * 65 + ty * 2 + 1];
            float4 bb = *(const float4*)&Is[c * 32 + tx * 4];
            acc[0][0] += a0 * bb.x; acc[0][1] += a0 * bb.y;
            acc[0][2] += a0 * bb.z; acc[0][3] += a0 * bb.w;
            acc[1][0] += a1 * bb.x; acc[1][1] += a1 * bb.y;
            acc[1][2] += a1 * bb.z; acc[1][3] += a1 * bb.w;
        }
        __syncthreads();
    }

    float s = 0.f, s2 = 0.f;
#pragma unroll
    for (int j = 0; j < 4; j++) {
        float2 o2 = make_float2(acc[0][j], acc[1][j]);
        *(float2*)(g_q + ((size_t)(b * N + n0 + tx * 4 + j)) * 64 + ty * 2) = o2;
        s  += o2.x + o2.y;
        s2 += o2.x * o2.x + o2.y * o2.y;
    }
#pragma unroll
    for (int off = 16; off; off >>= 1) {
        s  += __shfl_down_sync(0xffffffffu, s,  off);
        s2 += __shfl_down_sync(0xffffffffu, s2, off);
    }
    if ((tid & 31) == 0) {
        int g = tid >> 5;
        atomicAdd(&g_qstats[(b * 8 + g) * 2 + 0], s);
        atomicAdd(&g_qstats[(b * 8 + g) * 2 + 1], s2);
    }
}

// ---------------- fused maxpool + k,v projections + GN(k) partial stats ----
__global__ void proj_kv(const float* __restrict__ rad,
                        const float* __restrict__ Wk, const float* __restrict__ Wv) {
    __shared__ __align__(16) float Wks[32 * 65];
    __shared__ __align__(16) float Wvs[32 * 65];
    __shared__ __align__(16) float Is[32 * 32];
    int b  = blockIdx.y;
    int n0 = blockIdx.x * 32;
    int y  = n0 / w_, x0 = n0 % w_;
    int tid = threadIdx.x;
    int tx = tid & 7;
    int ty = tid >> 3;
    float ak[2][4] = {};
    float av[2][4] = {};

    for (int c0 = 0; c0 < CR; c0 += 32) {
        for (int i = tid; i < 2048; i += 256) {
            int c = i & 31, o = i >> 5;
            Wks[c * 65 + o] = Wk[o * CR + c0 + c];
            Wvs[c * 65 + o] = Wv[o * CR + c0 + c];
        }
        for (int i = tid; i < 1024; i += 256) {
            int c = i >> 5, x = i & 31;
            const float* p = rad + (((size_t)(b * CR + c0 + c) * H + y * 4) * W) + (x0 + x) * 4;
            float m = -3.4e38f;
#pragma unroll
            for (int r = 0; r < 4; r++) {
                float4 v = *(const float4*)(p + r * W);
                m = fmaxf(m, fmaxf(fmaxf(v.x, v.y), fmaxf(v.z, v.w)));
            }
            Is[c * 32 + x] = m;
        }
        __syncthreads();
#pragma unroll
        for (int c = 0; c < 32; c++) {
            float ka0 = Wks[c * 65 + ty * 2];
            float ka1 = Wks[c * 65 + ty * 2 + 1];
            float va0 = Wvs[c * 65 + ty * 2];
            float va1 = Wvs[c * 65 + ty * 2 + 1];
            float4 bb = *(const float4*)&Is[c * 32 + tx * 4];
            ak[0][0] += ka0 * bb.x; ak[0][1] += ka0 * bb.y;
            ak[0][2] += ka0 * bb.z; ak[0][3] += ka0 * bb.w;
            ak[1][0] += ka1 * bb.x; ak[1][1] += ka1 * bb.y;
            ak[1][2] += ka1 * bb.z; ak[1][3] += ka1 * bb.w;
            av[0][0] += va0 * bb.x; av[0][1] += va0 * bb.y;
            av[0][2] += va0 * bb.z; av[0][3] += va0 * bb.w;
            av[1][0] += va1 * bb.x; av[1][1] += va1 * bb.y;
            av[1][2] += va1 * bb.z; av[1][3] += va1 * bb.w;
        }
        __syncthreads();
    }

    float s = 0.f, s2 = 0.f;
#pragma unroll
    for (int j = 0; j < 4; j++) {
        size_t row = ((size_t)(b * N + n0 + tx * 4 + j)) * 64 + ty * 2;
        float2 k2 = make_float2(ak[0][j], ak[1][j]);
        float2 v2 = make_float2(av[0][j], av[1][j]);
        *(float2*)(g_k + row) = k2;
        *(float2*)(g_v + row) = v2;
        s  += k2.x + k2.y;
        s2 += k2.x * k2.x + k2.y * k2.y;
    }
#pragma unroll
    for (int off = 16; off; off >>= 1) {
        s  += __shfl_down_sync(0xffffffffu, s,  off);
        s2 += __shfl_down_sync(0xffffffffu, s2, off);
    }
    if ((tid & 31) == 0) {
        int g = tid >> 5;
        atomicAdd(&g_kstats[(b * 8 + g) * 2 + 0], s);
        atomicAdd(&g_kstats[(b * 8 + g) * 2 + 1], s2);
    }
}

// ---------------- attention: tiled, quarter-lane-per-pixel ----------------
// block = 128 threads (4 warps), tile 8x4 px. warp row: lane=(pix 0..7, qtr 0..3).
// Each thread owns 16 channels. Pass2 is shuffle-free.
__global__ __launch_bounds__(128)
void attn_kernel(const float* __restrict__ gq_w, const float* __restrict__ gq_b,
                 const float* __restrict__ gk_w, const float* __restrict__ gk_b) {
    __shared__ float2 kv_s[NCOL * CSTR];      // 36960 B
    __shared__ float  w_s[32 * 49];           //  6272 B
    __shared__ float  locc_s[NCOL];
    __shared__ float  sQA[64], sQB[64], sAk[64], sBk[64];

    int x0 = blockIdx.x * TX, y0 = blockIdx.y * TY, b = blockIdx.z;
    int tid  = threadIdx.x;
    int wrp  = tid >> 5;          // tile row
    int lane = tid & 31;
    int pix  = lane & 7;          // x within tile
    int qtr  = lane >> 3;         // channel quarter (16 ch)
    int c0   = qtr * 16;

    if (tid < 64) {
        int d = tid, g = d >> 3;
        const float inv = 1.f / (float)(N * 8);
        float su  = g_qstats[(b * 8 + g) * 2 + 0];
        float su2 = g_qstats[(b * 8 + g) * 2 + 1];
        float mu = su * inv;
        float rs = rsqrtf(su2 * inv - mu * mu + 1e-5f);
        float A = rs * gq_w[d];
        sQA[d] = A;
        sQB[d] = gq_b[d] - mu * A;
        su  = g_kstats[(b * 8 + g) * 2 + 0];
        su2 = g_kstats[(b * 8 + g) * 2 + 1];
        mu = su * inv;
        rs = rsqrtf(su2 * inv - mu * mu + 1e-5f);
        A = rs * gk_w[d];
        sAk[d] = A;
        sBk[d] = gk_b[d] - mu * A;
    }

    // ---- stage k halo (+locc), zero-filled outside the image ----
    for (int i = tid; i < NCOL * 16; i += 128) {
        int col = i >> 4, quad = i & 15;
        int r = col / HC, cc = col - r * HC;
        int yy = y0 - 3 + r, xx = x0 - 3 + cc;
        bool ok = ((unsigned)yy < (unsigned)h_) && ((unsigned)xx < (unsigned)w_);
        int nn = b * N + yy * w_ + xx;
        float4 v = make_float4(0.f, 0.f, 0.f, 0.f);
        if (ok) v = *(const float4*)(g_k + (size_t)nn * 64 + quad * 4);
        kv_s[col * CSTR + quad * 2]     = make_float2(v.x, v.y);
        kv_s[col * CSTR + quad * 2 + 1] = make_float2(v.z, v.w);
        if (quad == 0) locc_s[col] = ok ? g_locc[nn] : 0.f;
    }
    __syncthreads();

    int nq = b * N + (y0 + wrp) * w_ + x0 + pix;

    // ---- q: load 16 channels, fold q-GN and k-GN (A,B) ----
    float2 qp[8];
    float qB = 0.f;
    {
        const float* qr = g_q + (size_t)nq * 64 + c0;
#pragma unroll
        for (int c4 = 0; c4 < 16; c4 += 4) {
            float4 q4 = *(const float4*)(qr + c4);
            int d = c0 + c4;
            float n0 = q4.x * sQA[d + 0] + sQB[d + 0];
            float n1 = q4.y * sQA[d + 1] + sQB[d + 1];
            float n2 = q4.z * sQA[d + 2] + sQB[d + 2];
            float n3 = q4.w * sQA[d + 3] + sQB[d + 3];
            qB += n0 * sBk[d + 0] + n1 * sBk[d + 1]
                + n2 * sBk[d + 2] + n3 * sBk[d + 3];
            qp[c4 / 2]     = make_float2(n0 * sAk[d + 0] * 0.125f, n1 * sAk[d + 1] * 0.125f);
            qp[c4 / 2 + 1] = make_float2(n2 * sAk[d + 2] * 0.125f, n3 * sAk[d + 3] * 0.125f);
        }
    }
    qB += __shfl_xor_sync(0xffffffffu, qB, 8);
    qB += __shfl_xor_sync(0xffffffffu, qB, 16);
    float qB2 = qB * 0.125f;

    const float LPAD = -27.631021115928547f;  // 2*ln(1e-6)
    float m = -1e30f;
    float* wr = &w_s[(wrp * 8 + pix) * 49];

    // ---- pass 1: logits ----
    int p = 0;
    for (int dy = 0; dy < 7; dy++) {
        int yy = y0 + wrp + dy - 3;
        bool yok = (unsigned)yy < (unsigned)h_;
        int colr = (wrp + dy) * HC + pix;
#pragma unroll
        for (int dx = 0; dx < 7; dx++, p++) {
            int col = colr + dx;
            const float2* kp = &kv_s[col * CSTR + qtr * 8];
            float2 a2 = make_float2(0.f, 0.f);
            float2 b2 = make_float2(0.f, 0.f);
#pragma unroll
            for (int c = 0; c < 8; c += 2) {
                a2 = ffma2v(qp[c],     kp[c],     a2);
                b2 = ffma2v(qp[c + 1], kp[c + 1], b2);
            }
            float dot = a2.x + a2.y + b2.x + b2.y;
            dot += __shfl_xor_sync(0xffffffffu, dot, 8);
            dot += __shfl_xor_sync(0xffffffffu, dot, 16);
            int xx = x0 + pix + dx - 3;
            bool inb = yok && ((unsigned)xx < (unsigned)w_);
            float logit = inb ? (dot + qB2 + locc_s[col]) : LPAD;
            m = fmaxf(m, logit);
            if (qtr == 0) wr[p] = logit;
        }
    }
    __syncwarp();

    // ---- softmax (quarters split the 49 positions: 12/12/12/13) ----
    float s = 0.f;
    {
        int pa = qtr * 12, pb = (qtr == 3) ? 49 : pa + 12;
        for (int q = pa; q < pb; q++) {
            float e = __expf(wr[q] - m);
            wr[q] = e;
            s += e;
        }
    }
    s += __shfl_xor_sync(0xffffffffu, s, 8);
    s += __shfl_xor_sync(0xffffffffu, s, 16);
    float gs = g_gate[nq] / s;   // occ gate commutes with Wo

    // ---- stage v halo into the same buffer ----
    __syncthreads();
    for (int i = tid; i < NCOL * 16; i += 128) {
        int col = i >> 4, quad = i & 15;
        int r = col / HC, cc = col - r * HC;
        int yy = y0 - 3 + r, xx = x0 - 3 + cc;
        bool ok = ((unsigned)yy < (unsigned)h_) && ((unsigned)xx < (unsigned)w_);
        float4 v = make_float4(0.f, 0.f, 0.f, 0.f);
        if (ok) v = *(const float4*)(g_v + ((size_t)(b * N + yy * w_ + xx)) * 64 + quad * 4);
        kv_s[col * CSTR + quad * 2]     = make_float2(v.x, v.y);
        kv_s[col * CSTR + quad * 2 + 1] = make_float2(v.z, v.w);
    }
    __syncthreads();

    // ---- pass 2: weighted v accumulation (OOB v = 0, no mask; no shuffles) --
    float2 acc[8];
#pragma unroll
    for (int c = 0; c < 8; c++) acc[c] = make_float2(0.f, 0.f);
    p = 0;
    for (int dy = 0; dy < 7; dy++) {
        int colr = (wrp + dy) * HC + pix;
#pragma unroll
        for (int dx = 0; dx < 7; dx++, p++) {
            float wgt = wr[p];
            float2 w2 = make_float2(wgt, wgt);
            const float2* vp = &kv_s[(colr + dx) * CSTR + qtr * 8];
#pragma unroll
            for (int c = 0; c < 8; c++) acc[c] = ffma2v(w2, vp[c], acc[c]);
        }
    }
    float* mp = g_msg + (size_t)nq * 64 + c0;
#pragma unroll
    for (int c = 0; c < 8; c += 2) {
        *(float4*)(mp + c * 2) = make_float4(acc[c].x * gs, acc[c].y * gs,
                                             acc[c + 1].x * gs, acc[c + 1].y * gs);
    }
}

// ---------------- Wo projection with packed f32x2 FMA ----------------
__global__ __launch_bounds__(256) void wo_kernel(const float* __restrict__ Wo) {
    __shared__ float Ws[32 * 132];   // [d][o]
    __shared__ float Ms[32 * 132];   // [d][n]
    int b   = blockIdx.z;
    int co0 = blockIdx.y * 128;
    int n0  = blockIdx.x * 128;
    int tid = threadIdx.x;
    int tx = tid & 15;   // n octet
    int ty = tid >> 4;   // co octet

    unsigned long long acc[8][4] = {};

    for (int kc = 0; kc < 2; kc++) {
        int d0 = kc * 32;
        for (int idx = tid; idx < 1024; idx += 256) {
            int r = idx >> 3, dq = idx & 7;
            float4 v = *(const float4*)(Wo + (size_t)(co0 + r) * 64 + d0 + dq * 4);
            Ws[(dq * 4 + 0) * 132 + r] = v.x;
            Ws[(dq * 4 + 1) * 132 + r] = v.y;
            Ws[(dq * 4 + 2) * 132 + r] = v.z;
            Ws[(dq * 4 + 3) * 132 + r] = v.w;
            float4 u = *(const float4*)(g_msg + ((size_t)(b * N + n0 + r)) * 64 + d0 + dq * 4);
            Ms[(dq * 4 + 0) * 132 + r] = u.x;
            Ms[(dq * 4 + 1) * 132 + r] = u.y;
            Ms[(dq * 4 + 2) * 132 + r] = u.z;
            Ms[(dq * 4 + 3) * 132 + r] = u.w;
        }
        __syncthreads();
#pragma unroll
        for (int d = 0; d < 32; d++) {
            unsigned long long b2[4];
#pragma unroll
            for (int jp = 0; jp < 4; jp++)
                b2[jp] = *(const unsigned long long*)&Ms[d * 132 + tx * 8 + jp * 2];
#pragma unroll
            for (int i = 0; i < 8; i++) {
                unsigned long long a2 = pack2(Ws[d * 132 + ty * 8 + i]);
#pragma unroll
                for (int jp = 0; jp < 4; jp++)
                    acc[i][jp] = ffma2(a2, b2[jp], acc[i][jp]);
            }
        }
        __syncthreads();
    }
#pragma unroll
    for (int i = 0; i < 8; i++) {
        float2 r0 = *(float2*)&acc[i][0];
        float2 r1 = *(float2*)&acc[i][1];
        float2 r2 = *(float2*)&acc[i][2];
        float2 r3 = *(float2*)&acc[i][3];
        float* dst = g_msgo + ((size_t)(b * CI + co0 + ty * 8 + i)) * N + n0 + tx * 8;
        *(float4*)dst       = make_float4(r0.x, r0.y, r1.x, r1.y);
        *(float4*)(dst + 4) = make_float4(r2.x, r2.y, r3.x, r3.y);
    }
}

// ------- bilinear x4 upsample + residual: 1 thread = 8 output px ----------
__global__ void upsample_add(const float* __restrict__ img,
                             const float* __restrict__ alpha,
                             float* __restrict__ out) {
    int t = blockIdx.x * blockDim.x + threadIdx.x;
    if (t >= B * CI * H * 48) return;
    int k2 = t % 48;
    int Y  = (t / 48) % H;
    int bc = t / (48 * H);

    int m = Y >> 2, i = Y & 3;
    int y0, y1;
    float wy;
    if (i < 2) { y0 = max(m - 1, 0); y1 = m; wy = (i == 0) ? 0.625f : 0.875f; }
    else       { y0 = m; y1 = min(m + 1, h_ - 1); wy = (i == 2) ? 0.125f : 0.375f; }

    const float* pl = g_msgo + (size_t)bc * N;
    int x0 = 2 * k2;
    int xm = max(x0 - 1, 0), x1 = x0 + 1, x2 = min(x0 + 2, w_ - 1);
    const float* r0p = pl + y0 * w_;
    const float* r1p = pl + y1 * w_;
    float wy1 = 1.f - wy;
    float pm = wy1 * r0p[xm] + wy * r1p[xm];
    float p0 = wy1 * r0p[x0] + wy * r1p[x0];
    float p1 = wy1 * r0p[x1] + wy * r1p[x1];
    float p2 = wy1 * r0p[x2] + wy * r1p[x2];

    float A = alpha[0];
    size_t base = (size_t)t * 8;
    float4 i0 = *(const float4*)(img + base);
    float4 i1 = *(const float4*)(img + base + 4);
    float4 o0, o1;
    o0.x = i0.x + A * (0.375f * pm + 0.625f * p0);
    o0.y = i0.y + A * (0.125f * pm + 0.875f * p0);
    o0.z = i0.z + A * (0.875f * p0 + 0.125f * p1);
    o0.w = i0.w + A * (0.625f * p0 + 0.375f * p1);
    o1.x = i1.x + A * (0.375f * p0 + 0.625f * p1);
    o1.y = i1.y + A * (0.125f * p0 + 0.875f * p1);
    o1.z = i1.z + A * (0.875f * p1 + 0.125f * p2);
    o1.w = i1.w + A * (0.625f * p1 + 0.375f * p2);
    *(float4*)(out + base)     = o0;
    *(float4*)(out + base + 4) = o1;
}

// ---------------- launch ----------------
extern "C" void kernel_launch(void* const* d_in, const int* in_sizes, int n_in,
                              void* d_out, int out_size) {
    const float* img_bev  = (const float*)d_in[0];
    const float* rad_bev  = (const float*)d_in[1];
    const float* occ_prob = (const float*)d_in[2];
    const float* Wq    = (const float*)d_in[3];
    const float* Wk    = (const float*)d_in[4];
    const float* Wv    = (const float*)d_in[5];
    const float* Wo    = (const float*)d_in[6];
    const float* gq_w  = (const float*)d_in[7];
    const float* gq_b  = (const float*)d_in[8];
    const float* gk_w  = (const float*)d_in[9];
    const float* gk_b  = (const float*)d_in[10];
    const float* alpha = (const float*)d_in[11];
    float* out = (float*)d_out;

    pool_occ<<<(B * N + 255) / 256, 256>>>(occ_prob);

    dim3 pg(N / 32, B);
    proj_q <<<pg, 256>>>(img_bev, Wq);
    proj_kv<<<pg, 256>>>(rad_bev, Wk, Wv);

    dim3 ag(w_ / TX, h_ / TY, B);
    attn_kernel<<<ag, 128>>>(gq_w, gq_b, gk_w, gk_b);

    dim3 wg(N / 128, CI / 128, B);
    wo_kernel<<<wg, 256>>>(Wo);

    upsample_add<<<(B * CI * H * 48 + 255) / 256, 256>>>(img_bev, alpha, out);
}

// round 7
// speedup vs baseline: 1.8669x; 1.0008x over previous
#include <cuda_runtime.h>

// ---------------- problem constants ----------------
constexpr int B   = 2;
constexpr int CI  = 256;
constexpr int CR  = 128;
constexpr int H   = 384;
constexpr int W   = 384;
constexpr int h_  = 96;
constexpr int w_  = 96;
constexpr int N   = h_ * w_;       // 9216
constexpr int D   = 64;
constexpr int P   = 49;
constexpr int GRP = 8;

// attention tile geometry: 8x4 pixels, lane = (pix, channel-quarter)
constexpr int TX = 8;
constexpr int TY = 4;
constexpr int HC = TX + 6;         // 14
constexpr int HR = TY + 6;         // 10
constexpr int NCOL = HC * HR;      // 140
constexpr int CSTR = 33;           // float2 stride per col

// ---------------- scratch ----------------
__device__ float g_locc[B * N];            // 2*ln(clamp(occ,1e-6))
__device__ float g_gate[B * N];            // clamp(occ,0,1)
__device__ float g_q[B * N * D];           // [b, n, d]  (raw, pre-GN)
__device__ float g_k[B * N * D];           // raw, pre-GN
__device__ float g_v[B * N * D];
__device__ float g_msg[B * N * D];
__device__ float g_msgo[B * CI * N];       // [b, co, n]
__device__ float g_qstats[B * GRP * 2];    // (sum, sumsq)
__device__ float g_kstats[B * GRP * 2];

// ---------------- f32x2 packed-FMA helpers ----------------
__device__ __forceinline__ unsigned long long ffma2(unsigned long long a,
                                                    unsigned long long b,
                                                    unsigned long long c) {
    unsigned long long d;
    asm("fma.rn.f32x2 %0, %1, %2, %3;" : "=l"(d) : "l"(a), "l"(b), "l"(c));
    return d;
}
__device__ __forceinline__ unsigned long long pack2(float x) {
    unsigned long long d;
    asm("mov.b64 %0, {%1, %2};" : "=l"(d)
        : "r"(__float_as_uint(x)), "r"(__float_as_uint(x)));
    return d;
}
__device__ __forceinline__ float2 ffma2v(float2 a, float2 b, float2 c) {
    float2 d;
    asm("fma.rn.f32x2 %0, %1, %2, %3;"
        : "=l"(reinterpret_cast<unsigned long long&>(d))
        : "l"(reinterpret_cast<unsigned long long&>(a)),
          "l"(reinterpret_cast<unsigned long long&>(b)),
          "l"(reinterpret_cast<unsigned long long&>(c)));
    return d;
}

// ---------------- occ pool + stats zeroing ----------------
__global__ void pool_occ(const float* __restrict__ occ) {
    int t = blockIdx.x * blockDim.x + threadIdx.x;
    if (blockIdx.x == 0) {
        if (threadIdx.x < 32) g_qstats[threadIdx.x] = 0.f;
        else if (threadIdx.x < 64) g_kstats[threadIdx.x - 32] = 0.f;
    }
    if (t >= B * N) return;
    int x = t % w_;
    int y = (t / w_) % h_;
    int b = t / N;
    const float* p = occ + ((size_t)b * H + y * 4) * W + x * 4;
    float m = -3.4e38f;
#pragma unroll
    for (int r = 0; r < 4; r++) {
        float4 v = *(const float4*)(p + r * W);
        m = fmaxf(m, fmaxf(fmaxf(v.x, v.y), fmaxf(v.z, v.w)));
    }
    g_locc[t] = 2.f * logf(fmaxf(m, 1e-6f));
    g_gate[t] = fminf(fmaxf(m, 0.f), 1.f);
}

// ---------------- fused avgpool + q projection + GN partial stats ----------
__global__ void proj_q(const float* __restrict__ img, const float* __restrict__ Wq) {
    __shared__ __align__(16) float Ws[32 * 65];
    __shared__ __align__(16) float Is[32 * 32];
    int b  = blockIdx.y;
    int n0 = blockIdx.x * 32;
    int y  = n0 / w_, x0 = n0 % w_;
    int tid = threadIdx.x;
    int tx = tid & 7;    // n quad
    int ty = tid >> 3;   // o pair (0..31)
    float acc[2][4] = {};

    for (int c0 = 0; c0 < CI; c0 += 32) {
        for (int i = tid; i < 2048; i += 256) {
            int c = i & 31, o = i >> 5;
            Ws[c * 65 + o] = Wq[o * CI + c0 + c];
        }
        for (int i = tid; i < 1024; i += 256) {
            int c = i >> 5, x = i & 31;
            const float* p = img + (((size_t)(b * CI + c0 + c) * H + y * 4) * W) + (x0 + x) * 4;
            float s = 0.f;
#pragma unroll
            for (int r = 0; r < 4; r++) {
                float4 v = *(const float4*)(p + r * W);
                s += v.x + v.y + v.z + v.w;
            }
            Is[c * 32 + x] = s * 0.0625f;
        }
        __syncthreads();
#pragma unroll
        for (int c = 0; c < 32; c++) {
            float a0 = Ws[c * 65 + ty * 2];
            float a1 = Ws[c * 65 + ty * 2 + 1];
            float4 bb = *(const float4*)&Is[c * 32 + tx * 4];
            acc[0][0] += a0 * bb.x; acc[0][1] += a0 * bb.y;
            acc[0][2] += a0 * bb.z; acc[0][3] += a0 * bb.w;
            acc[1][0] += a1 * bb.x; acc[1][1] += a1 * bb.y;
            acc[1][2] += a1 * bb.z; acc[1][3] += a1 * bb.w;
        }
        __syncthreads();
    }

    float s = 0.f, s2 = 0.f;
#pragma unroll
    for (int j = 0; j < 4; j++) {
        float2 o2 = make_float2(acc[0][j], acc[1][j]);
        *(float2*)(g_q + ((size_t)(b * N + n0 + tx * 4 + j)) * 64 + ty * 2) = o2;
        s  += o2.x + o2.y;
        s2 += o2.x * o2.x + o2.y * o2.y;
    }
#pragma unroll
    for (int off = 16; off; off >>= 1) {
        s  += __shfl_down_sync(0xffffffffu, s,  off);
        s2 += __shfl_down_sync(0xffffffffu, s2, off);
    }
    if ((tid & 31) == 0) {
        int g = tid >> 5;
        atomicAdd(&g_qstats[(b * 8 + g) * 2 + 0], s);
        atomicAdd(&g_qstats[(b * 8 + g) * 2 + 1], s2);
    }
}

// ---------------- fused maxpool + k,v projections + GN(k) partial stats ----
__global__ void proj_kv(const float* __restrict__ rad,
                        const float* __restrict__ Wk, const float* __restrict__ Wv) {
    __shared__ __align__(16) float Wks[32 * 65];
    __shared__ __align__(16) float Wvs[32 * 65];
    __shared__ __align__(16) float Is[32 * 32];
    int b  = blockIdx.y;
    int n0 = blockIdx.x * 32;
    int y  = n0 / w_, x0 = n0 % w_;
    int tid = threadIdx.x;
    int tx = tid & 7;
    int ty = tid >> 3;
    float ak[2][4] = {};
    float av[2][4] = {};

    for (int c0 = 0; c0 < CR; c0 += 32) {
        for (int i = tid; i < 2048; i += 256) {
            int c = i & 31, o = i >> 5;
            Wks[c * 65 + o] = Wk[o * CR + c0 + c];
            Wvs[c * 65 + o] = Wv[o * CR + c0 + c];
        }
        for (int i = tid; i < 1024; i += 256) {
            int c = i >> 5, x = i & 31;
            const float* p = rad + (((size_t)(b * CR + c0 + c) * H + y * 4) * W) + (x0 + x) * 4;
            float m = -3.4e38f;
#pragma unroll
            for (int r = 0; r < 4; r++) {
                float4 v = *(const float4*)(p + r * W);
                m = fmaxf(m, fmaxf(fmaxf(v.x, v.y), fmaxf(v.z, v.w)));
            }
            Is[c * 32 + x] = m;
        }
        __syncthreads();
#pragma unroll
        for (int c = 0; c < 32; c++) {
            float ka0 = Wks[c * 65 + ty * 2];
            float ka1 = Wks[c * 65 + ty * 2 + 1];
            float va0 = Wvs[c * 65 + ty * 2];
            float va1 = Wvs[c * 65 + ty * 2 + 1];
            float4 bb = *(const float4*)&Is[c * 32 + tx * 4];
            ak[0][0] += ka0 * bb.x; ak[0][1] += ka0 * bb.y;
            ak[0][2] += ka0 * bb.z; ak[0][3] += ka0 * bb.w;
            ak[1][0] += ka1 * bb.x; ak[1][1] += ka1 * bb.y;
            ak[1][2] += ka1 * bb.z; ak[1][3] += ka1 * bb.w;
            av[0][0] += va0 * bb.x; av[0][1] += va0 * bb.y;
            av[0][2] += va0 * bb.z; av[0][3] += va0 * bb.w;
            av[1][0] += va1 * bb.x; av[1][1] += va1 * bb.y;
            av[1][2] += va1 * bb.z; av[1][3] += va1 * bb.w;
        }
        __syncthreads();
    }

    float s = 0.f, s2 = 0.f;
#pragma unroll
    for (int j = 0; j < 4; j++) {
        size_t row = ((size_t)(b * N + n0 + tx * 4 + j)) * 64 + ty * 2;
        float2 k2 = make_float2(ak[0][j], ak[1][j]);
        float2 v2 = make_float2(av[0][j], av[1][j]);
        *(float2*)(g_k + row) = k2;
        *(float2*)(g_v + row) = v2;
        s  += k2.x + k2.y;
        s2 += k2.x * k2.x + k2.y * k2.y;
    }
#pragma unroll
    for (int off = 16; off; off >>= 1) {
        s  += __shfl_down_sync(0xffffffffu, s,  off);
        s2 += __shfl_down_sync(0xffffffffu, s2, off);
    }
    if ((tid & 31) == 0) {
        int g = tid >> 5;
        atomicAdd(&g_kstats[(b * 8 + g) * 2 + 0], s);
        atomicAdd(&g_kstats[(b * 8 + g) * 2 + 1], s2);
    }
}

// ---------------- attention: tiled, quarter-lane, butterfly logits --------
// block = 128 threads (4 warps), tile 8x4 px. lane = (pix 0..7, qtr 0..3).
// Pass 1 processes 4 window positions per step with a 3-shuffle transpose
// reduce; each thread then owns ~13 full logits in registers.
__global__ __launch_bounds__(128)
void attn_kernel(const float* __restrict__ gq_w, const float* __restrict__ gq_b,
                 const float* __restrict__ gk_w, const float* __restrict__ gk_b) {
    __shared__ float2 kv_s[NCOL * CSTR];      // 36960 B
    __shared__ float  w_s[32 * 49];           //  6272 B
    __shared__ float  locc_s[NCOL];
    __shared__ float  sQA[64], sQB[64], sAk[64], sBk[64];

    int x0 = blockIdx.x * TX, y0 = blockIdx.y * TY, b = blockIdx.z;
    int tid  = threadIdx.x;
    int wrp  = tid >> 5;          // tile row
    int lane = tid & 31;
    int pix  = lane & 7;          // x within tile
    int qtr  = lane >> 3;         // channel quarter (16 ch)
    int c0   = qtr * 16;

    if (tid < 64) {
        int d = tid, g = d >> 3;
        const float inv = 1.f / (float)(N * 8);
        float su  = g_qstats[(b * 8 + g) * 2 + 0];
        float su2 = g_qstats[(b * 8 + g) * 2 + 1];
        float mu = su * inv;
        float rs = rsqrtf(su2 * inv - mu * mu + 1e-5f);
        float A = rs * gq_w[d];
        sQA[d] = A;
        sQB[d] = gq_b[d] - mu * A;
        su  = g_kstats[(b * 8 + g) * 2 + 0];
        su2 = g_kstats[(b * 8 + g) * 2 + 1];
        mu = su * inv;
        rs = rsqrtf(su2 * inv - mu * mu + 1e-5f);
        A = rs * gk_w[d];
        sAk[d] = A;
        sBk[d] = gk_b[d] - mu * A;
    }

    // ---- stage k halo (+locc), zero-filled outside the image ----
    for (int i = tid; i < NCOL * 16; i += 128) {
        int col = i >> 4, quad = i & 15;
        int r = col / HC, cc = col - r * HC;
        int yy = y0 - 3 + r, xx = x0 - 3 + cc;
        bool ok = ((unsigned)yy < (unsigned)h_) && ((unsigned)xx < (unsigned)w_);
        int nn = b * N + yy * w_ + xx;
        float4 v = make_float4(0.f, 0.f, 0.f, 0.f);
        if (ok) v = *(const float4*)(g_k + (size_t)nn * 64 + quad * 4);
        kv_s[col * CSTR + quad * 2]     = make_float2(v.x, v.y);
        kv_s[col * CSTR + quad * 2 + 1] = make_float2(v.z, v.w);
        if (quad == 0) locc_s[col] = ok ? g_locc[nn] : 0.f;
    }
    __syncthreads();

    int nq = b * N + (y0 + wrp) * w_ + x0 + pix;

    // ---- q: load 16 channels, fold q-GN and k-GN (A,B) ----
    float2 qp[8];
    float qB = 0.f;
    {
        const float* qr = g_q + (size_t)nq * 64 + c0;
#pragma unroll
        for (int c4 = 0; c4 < 16; c4 += 4) {
            float4 q4 = *(const float4*)(qr + c4);
            int d = c0 + c4;
            float n0 = q4.x * sQA[d + 0] + sQB[d + 0];
            float n1 = q4.y * sQA[d + 1] + sQB[d + 1];
            float n2 = q4.z * sQA[d + 2] + sQB[d + 2];
            float n3 = q4.w * sQA[d + 3] + sQB[d + 3];
            qB += n0 * sBk[d + 0] + n1 * sBk[d + 1]
                + n2 * sBk[d + 2] + n3 * sBk[d + 3];
            qp[c4 / 2]     = make_float2(n0 * sAk[d + 0] * 0.125f, n1 * sAk[d + 1] * 0.125f);
            qp[c4 / 2 + 1] = make_float2(n2 * sAk[d + 2] * 0.125f, n3 * sAk[d + 3] * 0.125f);
        }
    }
    qB += __shfl_xor_sync(0xffffffffu, qB, 8);
    qB += __shfl_xor_sync(0xffffffffu, qB, 16);
    float qB2 = qB * 0.125f;

    const float LPAD = -27.631021115928547f;  // 2*ln(1e-6)
    // position this thread owns within each group of 4: perm = [0,2,1,3]
    int pbase = ((qtr & 1) << 1) + (qtr >> 1);
    bool q_lo = (qtr & 1) == 0;
    bool q_hi = (qtr & 2) == 0;

    float lg[13];
    float m_own = -1e30f;

    // ---- pass 1: logits, 4 positions per step, 3-shuffle butterfly ----
    for (int g = 0; g < 13; g++) {
        int p0 = g * 4;
        float d4[4];
#pragma unroll
        for (int j = 0; j < 4; j++) {
            int p = min(p0 + j, 48);
            int dy = p / 7, dx = p - dy * 7;
            const float2* kp = &kv_s[((wrp + dy) * HC + pix + dx) * CSTR + qtr * 8];
            float2 a2 = make_float2(0.f, 0.f);
#pragma unroll
            for (int c = 0; c < 8; c++) a2 = ffma2v(qp[c], kp[c], a2);
            d4[j] = a2.x + a2.y;
        }
        // butterfly transpose-reduce: 3 shuffles for 4 full sums
        float x = __shfl_xor_sync(0xffffffffu, q_lo ? d4[2] : d4[0], 8);
        float y = __shfl_xor_sync(0xffffffffu, q_lo ? d4[3] : d4[1], 8);
        float s0 = (q_lo ? d4[0] : d4[2]) + x;
        float s1 = (q_lo ? d4[1] : d4[3]) + y;
        float z = __shfl_xor_sync(0xffffffffu, q_hi ? s1 : s0, 16);
        float dot = (q_hi ? s0 : s1) + z;

        int p_own = p0 + pbase;
        if (p_own <= 48) {
            int dy = p_own / 7, dx = p_own - dy * 7;
            int yy = y0 + wrp + dy - 3;
            int xx = x0 + pix + dx - 3;
            bool inb = ((unsigned)yy < (unsigned)h_) && ((unsigned)xx < (unsigned)w_);
            int col = (wrp + dy) * HC + pix + dx;
            float logit = inb ? (dot + qB2 + locc_s[col]) : LPAD;
            lg[g] = logit;
            m_own = fmaxf(m_own, logit);
        }
    }

    // ---- softmax: 2-shuffle max, exp own logits, 2-shuffle sum ----
    m_own = fmaxf(m_own, __shfl_xor_sync(0xffffffffu, m_own, 8));
    m_own = fmaxf(m_own, __shfl_xor_sync(0xffffffffu, m_own, 16));
    float* wr = &w_s[(wrp * 8 + pix) * 49];
    float ssum = 0.f;
#pragma unroll
    for (int g = 0; g < 13; g++) {
        int p_own = g * 4 + pbase;
        if (p_own <= 48) {
            float e = __expf(lg[g] - m_own);
            ssum += e;
            wr[p_own] = e;
        }
    }
    ssum += __shfl_xor_sync(0xffffffffu, ssum, 8);
    ssum += __shfl_xor_sync(0xffffffffu, ssum, 16);
    float gs = g_gate[nq] / ssum;   // occ gate commutes with Wo

    // ---- stage v halo into the same buffer ----
    __syncthreads();
    for (int i = tid; i < NCOL * 16; i += 128) {
        int col = i >> 4, quad = i & 15;
        int r = col / HC, cc = col - r * HC;
        int yy = y0 - 3 + r, xx = x0 - 3 + cc;
        bool ok = ((unsigned)yy < (unsigned)h_) && ((unsigned)xx < (unsigned)w_);
        float4 v = make_float4(0.f, 0.f, 0.f, 0.f);
        if (ok) v = *(const float4*)(g_v + ((size_t)(b * N + yy * w_ + xx)) * 64 + quad * 4);
        kv_s[col * CSTR + quad * 2]     = make_float2(v.x, v.y);
        kv_s[col * CSTR + quad * 2 + 1] = make_float2(v.z, v.w);
    }
    __syncthreads();

    // ---- pass 2: weighted v accumulation (OOB v = 0, no mask; no shuffles) --
    float2 acc[8];
#pragma unroll
    for (int c = 0; c < 8; c++) acc[c] = make_float2(0.f, 0.f);
    int p = 0;
    for (int dy = 0; dy < 7; dy++) {
        int colr = (wrp + dy) * HC + pix;
#pragma unroll
        for (int dx = 0; dx < 7; dx++, p++) {
            float wgt = wr[p];
            float2 w2 = make_float2(wgt, wgt);
            const float2* vp = &kv_s[(colr + dx) * CSTR + qtr * 8];
#pragma unroll
            for (int c = 0; c < 8; c++) acc[c] = ffma2v(w2, vp[c], acc[c]);
        }
    }
    float* mp = g_msg + (size_t)nq * 64 + c0;
#pragma unroll
    for (int c = 0; c < 8; c += 2) {
        *(float4*)(mp + c * 2) = make_float4(acc[c].x * gs, acc[c].y * gs,
                                             acc[c + 1].x * gs, acc[c + 1].y * gs);
    }
}

// ---------------- Wo projection with packed f32x2 FMA ----------------
__global__ __launch_bounds__(256) void wo_kernel(const float* __restrict__ Wo) {
    __shared__ float Ws[32 * 132];   // [d][o]
    __shared__ float Ms[32 * 132];   // [d][n]
    int b   = blockIdx.z;
    int co0 = blockIdx.y * 128;
    int n0  = blockIdx.x * 128;
    int tid = threadIdx.x;
    int tx = tid & 15;   // n octet
    int ty = tid >> 4;   // co octet

    unsigned long long acc[8][4] = {};

    for (int kc = 0; kc < 2; kc++) {
        int d0 = kc * 32;
        for (int idx = tid; idx < 1024; idx += 256) {
            int r = idx >> 3, dq = idx & 7;
            float4 v = *(const float4*)(Wo + (size_t)(co0 + r) * 64 + d0 + dq * 4);
            Ws[(dq * 4 + 0) * 132 + r] = v.x;
            Ws[(dq * 4 + 1) * 132 + r] = v.y;
            Ws[(dq * 4 + 2) * 132 + r] = v.z;
            Ws[(dq * 4 + 3) * 132 + r] = v.w;
            float4 u = *(const float4*)(g_msg + ((size_t)(b * N + n0 + r)) * 64 + d0 + dq * 4);
            Ms[(dq * 4 + 0) * 132 + r] = u.x;
            Ms[(dq * 4 + 1) * 132 + r] = u.y;
            Ms[(dq * 4 + 2) * 132 + r] = u.z;
            Ms[(dq * 4 + 3) * 132 + r] = u.w;
        }
        __syncthreads();
#pragma unroll
        for (int d = 0; d < 32; d++) {
            unsigned long long b2[4];
#pragma unroll
            for (int jp = 0; jp < 4; jp++)
                b2[jp] = *(const unsigned long long*)&Ms[d * 132 + tx * 8 + jp * 2];
#pragma unroll
            for (int i = 0; i < 8; i++) {
                unsigned long long a2 = pack2(Ws[d * 132 + ty * 8 + i]);
#pragma unroll
                for (int jp = 0; jp < 4; jp++)
                    acc[i][jp] = ffma2(a2, b2[jp], acc[i][jp]);
            }
        }
        __syncthreads();
    }
#pragma unroll
    for (int i = 0; i < 8; i++) {
        float2 r0 = *(float2*)&acc[i][0];
        float2 r1 = *(float2*)&acc[i][1];
        float2 r2 = *(float2*)&acc[i][2];
        float2 r3 = *(float2*)&acc[i][3];
        float* dst = g_msgo + ((size_t)(b * CI + co0 + ty * 8 + i)) * N + n0 + tx * 8;
        *(float4*)dst       = make_float4(r0.x, r0.y, r1.x, r1.y);
        *(float4*)(dst + 4) = make_float4(r2.x, r2.y, r3.x, r3.y);
    }
}

// ------- bilinear x4 upsample + residual: 1 thread = 8 output px ----------
__global__ void upsample_add(const float* __restrict__ img,
                             const float* __restrict__ alpha,
                             float* __restrict__ out) {
    int t = blockIdx.x * blockDim.x + threadIdx.x;
    if (t >= B * CI * H * 48) return;
    int k2 = t % 48;
    int Y  = (t / 48) % H;
    int bc = t / (48 * H);

    int m = Y >> 2, i = Y & 3;
    int y0, y1;
    float wy;
    if (i < 2) { y0 = max(m - 1, 0); y1 = m; wy = (i == 0) ? 0.625f : 0.875f; }
    else       { y0 = m; y1 = min(m + 1, h_ - 1); wy = (i == 2) ? 0.125f : 0.375f; }

    const float* pl = g_msgo + (size_t)bc * N;
    int x0 = 2 * k2;
    int xm = max(x0 - 1, 0), x1 = x0 + 1, x2 = min(x0 + 2, w_ - 1);
    const float* r0p = pl + y0 * w_;
    const float* r1p = pl + y1 * w_;
    float wy1 = 1.f - wy;
    float pm = wy1 * r0p[xm] + wy * r1p[xm];
    float p0 = wy1 * r0p[x0] + wy * r1p[x0];
    float p1 = wy1 * r0p[x1] + wy * r1p[x1];
    float p2 = wy1 * r0p[x2] + wy * r1p[x2];

    float A = alpha[0];
    size_t base = (size_t)t * 8;
    float4 i0 = *(const float4*)(img + base);
    float4 i1 = *(const float4*)(img + base + 4);
    float4 o0, o1;
    o0.x = i0.x + A * (0.375f * pm + 0.625f * p0);
    o0.y = i0.y + A * (0.125f * pm + 0.875f * p0);
    o0.z = i0.z + A * (0.875f * p0 + 0.125f * p1);
    o0.w = i0.w + A * (0.625f * p0 + 0.375f * p1);
    o1.x = i1.x + A * (0.375f * p0 + 0.625f * p1);
    o1.y = i1.y + A * (0.125f * p0 + 0.875f * p1);
    o1.z = i1.z + A * (0.875f * p1 + 0.125f * p2);
    o1.w = i1.w + A * (0.625f * p1 + 0.375f * p2);
    *(float4*)(out + base)     = o0;
    *(float4*)(out + base + 4) = o1;
}

// ---------------- launch ----------------
extern "C" void kernel_launch(void* const* d_in, const int* in_sizes, int n_in,
                              void* d_out, int out_size) {
    const float* img_bev  = (const float*)d_in[0];
    const float* rad_bev  = (const float*)d_in[1];
    const float* occ_prob = (const float*)d_in[2];
    const float* Wq    = (const float*)d_in[3];
    const float* Wk    = (const float*)d_in[4];
    const float* Wv    = (const float*)d_in[5];
    const float* Wo    = (const float*)d_in[6];
    const float* gq_w  = (const float*)d_in[7];
    const float* gq_b  = (const float*)d_in[8];
    const float* gk_w  = (const float*)d_in[9];
    const float* gk_b  = (const float*)d_in[10];
    const float* alpha = (const float*)d_in[11];
    float* out = (float*)d_out;

    pool_occ<<<(B * N + 255) / 256, 256>>>(occ_prob);

    dim3 pg(N / 32, B);
    proj_q <<<pg, 256>>>(img_bev, Wq);
    proj_kv<<<pg, 256>>>(rad_bev, Wk, Wv);

    dim3 ag(w_ / TX, h_ / TY, B);
    attn_kernel<<<ag, 128>>>(gq_w, gq_b, gk_w, gk_b);

    dim3 wg(N / 128, CI / 128, B);
    wo_kernel<<<wg, 256>>>(Wo);

    upsample_add<<<(B * CI * H * 48 + 255) / 256, 256>>>(img_bev, alpha, out);
}

// round 8
// speedup vs baseline: 2.0227x; 1.0835x over previous
#include <cuda_runtime.h>

// ---------------- problem constants ----------------
constexpr int B   = 2;
constexpr int CI  = 256;
constexpr int CR  = 128;
constexpr int H   = 384;
constexpr int W   = 384;
constexpr int h_  = 96;
constexpr int w_  = 96;
constexpr int N   = h_ * w_;       // 9216
constexpr int D   = 64;
constexpr int GRP = 8;

// attention tile geometry: 8x4 pixels, lane = (pix, channel-quarter)
constexpr int TX = 8;
constexpr int TY = 4;
constexpr int HC = TX + 6;         // 14
constexpr int HR = TY + 6;         // 10
constexpr int NCOL = HC * HR;      // 140
constexpr int C4STR = 17;          // float4 stride per col (16 + pad)

// ---------------- scratch ----------------
__device__ float g_locc[B * N];            // 2*ln(clamp(occ,1e-6))
__device__ float g_gate[B * N];            // clamp(occ,0,1)
__device__ float g_q[B * N * D];           // [b, n, d]  (raw, pre-GN)
__device__ float g_k[B * N * D];           // raw, pre-GN
__device__ float g_v[B * N * D];
__device__ float g_msg[B * N * D];
__device__ float g_msgo[B * CI * N];       // [b, co, n]
__device__ float g_qstats[B * GRP * 2];    // (sum, sumsq) -- zero at load & re-zeroed by upsample tail
__device__ float g_kstats[B * GRP * 2];

// ---------------- f32x2 packed-FMA helpers ----------------
__device__ __forceinline__ unsigned long long ffma2(unsigned long long a,
                                                    unsigned long long b,
                                                    unsigned long long c) {
    unsigned long long d;
    asm("fma.rn.f32x2 %0, %1, %2, %3;" : "=l"(d) : "l"(a), "l"(b), "l"(c));
    return d;
}
__device__ __forceinline__ unsigned long long pack2(float x) {
    unsigned long long d;
    asm("mov.b64 %0, {%1, %2};" : "=l"(d)
        : "r"(__float_as_uint(x)), "r"(__float_as_uint(x)));
    return d;
}
__device__ __forceinline__ float2 ffma2v(float2 a, float2 b, float2 c) {
    float2 d;
    asm("fma.rn.f32x2 %0, %1, %2, %3;"
        : "=l"(reinterpret_cast<unsigned long long&>(d))
        : "l"(reinterpret_cast<unsigned long long&>(a)),
          "l"(reinterpret_cast<unsigned long long&>(b)),
          "l"(reinterpret_cast<unsigned long long&>(c)));
    return d;
}

// ================= merged front kernel =================
// blocks [0,576): fused avgpool+Wq proj (+GN q stats)
// blocks [576,1152): fused maxpool+Wk/Wv proj (+GN k stats)
// blocks [1152,1224): occ maxpool -> locc/gate
__global__ __launch_bounds__(256) void front_kernel(
    const float* __restrict__ img, const float* __restrict__ rad,
    const float* __restrict__ occ,
    const float* __restrict__ Wq, const float* __restrict__ Wk,
    const float* __restrict__ Wv) {
    __shared__ __align__(16) float sm[2 * 2080 + 1024];   // 20.7 KB
    int bid = blockIdx.x;
    int tid = threadIdx.x;

    if (bid < 576) {
        // ---------------- proj_q ----------------
        float* Ws = sm;            // [c][o] stride 65
        float* Is = sm + 2080;     // [c][n] 32x32
        int b  = bid / 288;
        int n0 = (bid % 288) * 32;
        int y  = n0 / w_, x0 = n0 % w_;
        int tx = tid & 7;
        int ty = tid >> 3;
        float acc[2][4] = {};

        for (int c0 = 0; c0 < CI; c0 += 32) {
            for (int i = tid; i < 2048; i += 256) {
                int c = i & 31, o = i >> 5;
                Ws[c * 65 + o] = Wq[o * CI + c0 + c];
            }
            for (int i = tid; i < 1024; i += 256) {
                int c = i >> 5, x = i & 31;
                const float* p = img + (((size_t)(b * CI + c0 + c) * H + y * 4) * W) + (x0 + x) * 4;
                float s = 0.f;
#pragma unroll
                for (int r = 0; r < 4; r++) {
                    float4 v = *(const float4*)(p + r * W);
                    s += v.x + v.y + v.z + v.w;
                }
                Is[c * 32 + x] = s * 0.0625f;
            }
            __syncthreads();
#pragma unroll
            for (int c = 0; c < 32; c++) {
                float a0 = Ws[c * 65 + ty * 2];
                float a1 = Ws[c * 65 + ty * 2 + 1];
                float4 bb = *(const float4*)&Is[c * 32 + tx * 4];
                acc[0][0] += a0 * bb.x; acc[0][1] += a0 * bb.y;
                acc[0][2] += a0 * bb.z; acc[0][3] += a0 * bb.w;
                acc[1][0] += a1 * bb.x; acc[1][1] += a1 * bb.y;
                acc[1][2] += a1 * bb.z; acc[1][3] += a1 * bb.w;
            }
            __syncthreads();
        }

        float s = 0.f, s2 = 0.f;
#pragma unroll
        for (int j = 0; j < 4; j++) {
            float2 o2 = make_float2(acc[0][j], acc[1][j]);
            *(float2*)(g_q + ((size_t)(b * N + n0 + tx * 4 + j)) * 64 + ty * 2) = o2;
            s  += o2.x + o2.y;
            s2 += o2.x * o2.x + o2.y * o2.y;
        }
#pragma unroll
        for (int off = 16; off; off >>= 1) {
            s  += __shfl_down_sync(0xffffffffu, s,  off);
            s2 += __shfl_down_sync(0xffffffffu, s2, off);
        }
        if ((tid & 31) == 0) {
            int g = tid >> 5;
            atomicAdd(&g_qstats[(b * 8 + g) * 2 + 0], s);
            atomicAdd(&g_qstats[(b * 8 + g) * 2 + 1], s2);
        }
    } else if (bid < 1152) {
        // ---------------- proj_kv ----------------
        float* Wks = sm;
        float* Wvs = sm + 2080;
        float* Is  = sm + 4160;
        int pb = bid - 576;
        int b  = pb / 288;
        int n0 = (pb % 288) * 32;
        int y  = n0 / w_, x0 = n0 % w_;
        int tx = tid & 7;
        int ty = tid >> 3;
        float ak[2][4] = {};
        float av[2][4] = {};

        for (int c0 = 0; c0 < CR; c0 += 32) {
            for (int i = tid; i < 2048; i += 256) {
                int c = i & 31, o = i >> 5;
                Wks[c * 65 + o] = Wk[o * CR + c0 + c];
                Wvs[c * 65 + o] = Wv[o * CR + c0 + c];
            }
            for (int i = tid; i < 1024; i += 256) {
                int c = i >> 5, x = i & 31;
                const float* p = rad + (((size_t)(b * CR + c0 + c) * H + y * 4) * W) + (x0 + x) * 4;
                float m = -3.4e38f;
#pragma unroll
                for (int r = 0; r < 4; r++) {
                    float4 v = *(const float4*)(p + r * W);
                    m = fmaxf(m, fmaxf(fmaxf(v.x, v.y), fmaxf(v.z, v.w)));
                }
                Is[c * 32 + x] = m;
            }
            __syncthreads();
#pragma unroll
            for (int c = 0; c < 32; c++) {
                float ka0 = Wks[c * 65 + ty * 2];
                float ka1 = Wks[c * 65 + ty * 2 + 1];
                float va0 = Wvs[c * 65 + ty * 2];
                float va1 = Wvs[c * 65 + ty * 2 + 1];
                float4 bb = *(const float4*)&Is[c * 32 + tx * 4];
                ak[0][0] += ka0 * bb.x; ak[0][1] += ka0 * bb.y;
                ak[0][2] += ka0 * bb.z; ak[0][3] += ka0 * bb.w;
                ak[1][0] += ka1 * bb.x; ak[1][1] += ka1 * bb.y;
                ak[1][2] += ka1 * bb.z; ak[1][3] += ka1 * bb.w;
                av[0][0] += va0 * bb.x; av[0][1] += va0 * bb.y;
                av[0][2] += va0 * bb.z; av[0][3] += va0 * bb.w;
                av[1][0] += va1 * bb.x; av[1][1] += va1 * bb.y;
                av[1][2] += va1 * bb.z; av[1][3] += va1 * bb.w;
            }
            __syncthreads();
        }

        float s = 0.f, s2 = 0.f;
#pragma unroll
        for (int j = 0; j < 4; j++) {
            size_t row = ((size_t)(b * N + n0 + tx * 4 + j)) * 64 + ty * 2;
            float2 k2 = make_float2(ak[0][j], ak[1][j]);
            float2 v2 = make_float2(av[0][j], av[1][j]);
            *(float2*)(g_k + row) = k2;
            *(float2*)(g_v + row) = v2;
            s  += k2.x + k2.y;
            s2 += k2.x * k2.x + k2.y * k2.y;
        }
#pragma unroll
        for (int off = 16; off; off >>= 1) {
            s  += __shfl_down_sync(0xffffffffu, s,  off);
            s2 += __shfl_down_sync(0xffffffffu, s2, off);
        }
        if ((tid & 31) == 0) {
            int g = tid >> 5;
            atomicAdd(&g_kstats[(b * 8 + g) * 2 + 0], s);
            atomicAdd(&g_kstats[(b * 8 + g) * 2 + 1], s2);
        }
    } else {
        // ---------------- pool_occ ----------------
        int t = (bid - 1152) * 256 + tid;
        if (t >= B * N) return;
        int x = t % w_;
        int y = (t / w_) % h_;
        int b = t / N;
        const float* p = occ + ((size_t)b * H + y * 4) * W + x * 4;
        float m = -3.4e38f;
#pragma unroll
        for (int r = 0; r < 4; r++) {
            float4 v = *(const float4*)(p + r * W);
            m = fmaxf(m, fmaxf(fmaxf(v.x, v.y), fmaxf(v.z, v.w)));
        }
        g_locc[t] = 2.f * logf(fmaxf(m, 1e-6f));
        g_gate[t] = fminf(fmaxf(m, 0.f), 1.f);
    }
}

// ---------------- attention: tiled, quarter-lane, float4 smem -------------
__global__ __launch_bounds__(128)
void attn_kernel(const float* __restrict__ gq_w, const float* __restrict__ gq_b,
                 const float* __restrict__ gk_w, const float* __restrict__ gk_b) {
    __shared__ float4 kv_s[NCOL * C4STR];     // 38080 B
    __shared__ float  w_s[32 * 49];           //  6272 B
    __shared__ float  locc_s[NCOL];
    __shared__ float  sQA[64], sQB[64], sAk[64], sBk[64];

    int x0 = blockIdx.x * TX, y0 = blockIdx.y * TY, b = blockIdx.z;
    int tid  = threadIdx.x;
    int wrp  = tid >> 5;          // tile row
    int lane = tid & 31;
    int pix  = lane & 7;          // x within tile
    int qtr  = lane >> 3;         // channel quarter (16 ch)
    int c0   = qtr * 16;

    if (tid < 64) {
        int d = tid, g = d >> 3;
        const float inv = 1.f / (float)(N * 8);
        float su  = g_qstats[(b * 8 + g) * 2 + 0];
        float su2 = g_qstats[(b * 8 + g) * 2 + 1];
        float mu = su * inv;
        float rs = rsqrtf(su2 * inv - mu * mu + 1e-5f);
        float A = rs * gq_w[d];
        sQA[d] = A;
        sQB[d] = gq_b[d] - mu * A;
        su  = g_kstats[(b * 8 + g) * 2 + 0];
        su2 = g_kstats[(b * 8 + g) * 2 + 1];
        mu = su * inv;
        rs = rsqrtf(su2 * inv - mu * mu + 1e-5f);
        A = rs * gk_w[d];
        sAk[d] = A;
        sBk[d] = gk_b[d] - mu * A;
    }

    // ---- stage k halo (+locc), zero-filled outside the image ----
    for (int i = tid; i < NCOL * 16; i += 128) {
        int col = i >> 4, quad = i & 15;
        int r = col / HC, cc = col - r * HC;
        int yy = y0 - 3 + r, xx = x0 - 3 + cc;
        bool ok = ((unsigned)yy < (unsigned)h_) && ((unsigned)xx < (unsigned)w_);
        int nn = b * N + yy * w_ + xx;
        float4 v = make_float4(0.f, 0.f, 0.f, 0.f);
        if (ok) v = *(const float4*)(g_k + (size_t)nn * 64 + quad * 4);
        kv_s[col * C4STR + quad] = v;
        if (quad == 0) locc_s[col] = ok ? g_locc[nn] : 0.f;
    }
    __syncthreads();

    int nq = b * N + (y0 + wrp) * w_ + x0 + pix;

    // ---- q: load 16 channels, fold q-GN and k-GN (A,B) ----
    float2 qp[8];
    float qB = 0.f;
    {
        const float* qr = g_q + (size_t)nq * 64 + c0;
#pragma unroll
        for (int c4 = 0; c4 < 16; c4 += 4) {
            float4 q4 = *(const float4*)(qr + c4);
            int d = c0 + c4;
            float n0 = q4.x * sQA[d + 0] + sQB[d + 0];
            float n1 = q4.y * sQA[d + 1] + sQB[d + 1];
            float n2 = q4.z * sQA[d + 2] + sQB[d + 2];
            float n3 = q4.w * sQA[d + 3] + sQB[d + 3];
            qB += n0 * sBk[d + 0] + n1 * sBk[d + 1]
                + n2 * sBk[d + 2] + n3 * sBk[d + 3];
            qp[c4 / 2]     = make_float2(n0 * sAk[d + 0] * 0.125f, n1 * sAk[d + 1] * 0.125f);
            qp[c4 / 2 + 1] = make_float2(n2 * sAk[d + 2] * 0.125f, n3 * sAk[d + 3] * 0.125f);
        }
    }
    qB += __shfl_xor_sync(0xffffffffu, qB, 8);
    qB += __shfl_xor_sync(0xffffffffu, qB, 16);
    float qB2 = qB * 0.125f;

    const float LPAD = -27.631021115928547f;  // 2*ln(1e-6)
    // position this thread owns within each group of 4: perm = [0,2,1,3]
    int pbase = ((qtr & 1) << 1) + (qtr >> 1);
    bool q_lo = (qtr & 1) == 0;
    bool q_hi = (qtr & 2) == 0;

    float lg[13];
    float m_own = -1e30f;

    // ---- pass 1: logits, 4 positions per step, 3-shuffle butterfly ----
    for (int g = 0; g < 13; g++) {
        int p0 = g * 4;
        float d4[4];
#pragma unroll
        for (int j = 0; j < 4; j++) {
            int p = min(p0 + j, 48);
            int dy = p / 7, dx = p - dy * 7;
            const float4* kp = &kv_s[((wrp + dy) * HC + pix + dx) * C4STR + qtr * 4];
            float2 a2 = make_float2(0.f, 0.f);
            float2 b2 = make_float2(0.f, 0.f);
#pragma unroll
            for (int c = 0; c < 4; c++) {
                float4 k4 = kp[c];
                a2 = ffma2v(qp[2 * c],     make_float2(k4.x, k4.y), a2);
                b2 = ffma2v(qp[2 * c + 1], make_float2(k4.z, k4.w), b2);
            }
            d4[j] = a2.x + a2.y + b2.x + b2.y;
        }
        // butterfly transpose-reduce: 3 shuffles for 4 full sums
        float x = __shfl_xor_sync(0xffffffffu, q_lo ? d4[2] : d4[0], 8);
        float y = __shfl_xor_sync(0xffffffffu, q_lo ? d4[3] : d4[1], 8);
        float s0 = (q_lo ? d4[0] : d4[2]) + x;
        float s1 = (q_lo ? d4[1] : d4[3]) + y;
        float z = __shfl_xor_sync(0xffffffffu, q_hi ? s1 : s0, 16);
        float dot = (q_hi ? s0 : s1) + z;

        int p_own = p0 + pbase;
        if (p_own <= 48) {
            int dy = p_own / 7, dx = p_own - dy * 7;
            int yy = y0 + wrp + dy - 3;
            int xx = x0 + pix + dx - 3;
            bool inb = ((unsigned)yy < (unsigned)h_) && ((unsigned)xx < (unsigned)w_);
            int col = (wrp + dy) * HC + pix + dx;
            float logit = inb ? (dot + qB2 + locc_s[col]) : LPAD;
            lg[g] = logit;
            m_own = fmaxf(m_own, logit);
        }
    }

    // ---- softmax: 2-shuffle max, exp own logits, 2-shuffle sum ----
    m_own = fmaxf(m_own, __shfl_xor_sync(0xffffffffu, m_own, 8));
    m_own = fmaxf(m_own, __shfl_xor_sync(0xffffffffu, m_own, 16));
    float* wr = &w_s[(wrp * 8 + pix) * 49];
    float ssum = 0.f;
#pragma unroll
    for (int g = 0; g < 13; g++) {
        int p_own = g * 4 + pbase;
        if (p_own <= 48) {
            float e = __expf(lg[g] - m_own);
            ssum += e;
            wr[p_own] = e;
        }
    }
    ssum += __shfl_xor_sync(0xffffffffu, ssum, 8);
    ssum += __shfl_xor_sync(0xffffffffu, ssum, 16);
    float gs = g_gate[nq] / ssum;   // occ gate commutes with Wo

    // ---- stage v halo into the same buffer ----
    __syncthreads();
    for (int i = tid; i < NCOL * 16; i += 128) {
        int col = i >> 4, quad = i & 15;
        int r = col / HC, cc = col - r * HC;
        int yy = y0 - 3 + r, xx = x0 - 3 + cc;
        bool ok = ((unsigned)yy < (unsigned)h_) && ((unsigned)xx < (unsigned)w_);
        float4 v = make_float4(0.f, 0.f, 0.f, 0.f);
        if (ok) v = *(const float4*)(g_v + ((size_t)(b * N + yy * w_ + xx)) * 64 + quad * 4);
        kv_s[col * C4STR + quad] = v;
    }
    __syncthreads();

    // ---- pass 2: weighted v accumulation (OOB v = 0; no shuffles) ----
    float2 acc[8];
#pragma unroll
    for (int c = 0; c < 8; c++) acc[c] = make_float2(0.f, 0.f);
    int p = 0;
    for (int dy = 0; dy < 7; dy++) {
        int colr = (wrp + dy) * HC + pix;
#pragma unroll
        for (int dx = 0; dx < 7; dx++, p++) {
            float wgt = wr[p];
            float2 w2 = make_float2(wgt, wgt);
            const float4* vp = &kv_s[(colr + dx) * C4STR + qtr * 4];
#pragma unroll
            for (int c = 0; c < 4; c++) {
                float4 v4 = vp[c];
                acc[2 * c]     = ffma2v(w2, make_float2(v4.x, v4.y), acc[2 * c]);
                acc[2 * c + 1] = ffma2v(w2, make_float2(v4.z, v4.w), acc[2 * c + 1]);
            }
        }
    }
    float* mp = g_msg + (size_t)nq * 64 + c0;
#pragma unroll
    for (int c = 0; c < 8; c += 2) {
        *(float4*)(mp + c * 2) = make_float4(acc[c].x * gs, acc[c].y * gs,
                                             acc[c + 1].x * gs, acc[c + 1].y * gs);
    }
}

// ---------------- Wo projection with packed f32x2 FMA ----------------
__global__ __launch_bounds__(256) void wo_kernel(const float* __restrict__ Wo) {
    __shared__ float Ws[32 * 132];   // [d][o]
    __shared__ float Ms[32 * 132];   // [d][n]
    int b   = blockIdx.z;
    int co0 = blockIdx.y * 128;
    int n0  = blockIdx.x * 128;
    int tid = threadIdx.x;
    int tx = tid & 15;   // n octet
    int ty = tid >> 4;   // co octet

    unsigned long long acc[8][4] = {};

    for (int kc = 0; kc < 2; kc++) {
        int d0 = kc * 32;
        for (int idx = tid; idx < 1024; idx += 256) {
            int r = idx >> 3, dq = idx & 7;
            float4 v = *(const float4*)(Wo + (size_t)(co0 + r) * 64 + d0 + dq * 4);
            Ws[(dq * 4 + 0) * 132 + r] = v.x;
            Ws[(dq * 4 + 1) * 132 + r] = v.y;
            Ws[(dq * 4 + 2) * 132 + r] = v.z;
            Ws[(dq * 4 + 3) * 132 + r] = v.w;
            float4 u = *(const float4*)(g_msg + ((size_t)(b * N + n0 + r)) * 64 + d0 + dq * 4);
            Ms[(dq * 4 + 0) * 132 + r] = u.x;
            Ms[(dq * 4 + 1) * 132 + r] = u.y;
            Ms[(dq * 4 + 2) * 132 + r] = u.z;
            Ms[(dq * 4 + 3) * 132 + r] = u.w;
        }
        __syncthreads();
#pragma unroll
        for (int d = 0; d < 32; d++) {
            unsigned long long b2[4];
#pragma unroll
            for (int jp = 0; jp < 4; jp++)
                b2[jp] = *(const unsigned long long*)&Ms[d * 132 + tx * 8 + jp * 2];
#pragma unroll
            for (int i = 0; i < 8; i++) {
                unsigned long long a2 = pack2(Ws[d * 132 + ty * 8 + i]);
#pragma unroll
                for (int jp = 0; jp < 4; jp++)
                    acc[i][jp] = ffma2(a2, b2[jp], acc[i][jp]);
            }
        }
        __syncthreads();
    }
#pragma unroll
    for (int i = 0; i < 8; i++) {
        float2 r0 = *(float2*)&acc[i][0];
        float2 r1 = *(float2*)&acc[i][1];
        float2 r2 = *(float2*)&acc[i][2];
        float2 r3 = *(float2*)&acc[i][3];
        float* dst = g_msgo + ((size_t)(b * CI + co0 + ty * 8 + i)) * N + n0 + tx * 8;
        *(float4*)dst       = make_float4(r0.x, r0.y, r1.x, r1.y);
        *(float4*)(dst + 4) = make_float4(r2.x, r2.y, r3.x, r3.y);
    }
}

// ------- bilinear x4 upsample + residual; block 0 re-zeroes GN stats -------
__global__ void upsample_add(const float* __restrict__ img,
                             const float* __restrict__ alpha,
                             float* __restrict__ out) {
    if (blockIdx.x == 0 && threadIdx.x < 64) {
        // stats were consumed by attn earlier in this replay; reset for next.
        if (threadIdx.x < 32) g_qstats[threadIdx.x] = 0.f;
        else                  g_kstats[threadIdx.x - 32] = 0.f;
    }
    int t = blockIdx.x * blockDim.x + threadIdx.x;
    if (t >= B * CI * H * 48) return;
    int k2 = t % 48;
    int Y  = (t / 48) % H;
    int bc = t / (48 * H);

    int m = Y >> 2, i = Y & 3;
    int y0, y1;
    float wy;
    if (i < 2) { y0 = max(m - 1, 0); y1 = m; wy = (i == 0) ? 0.625f : 0.875f; }
    else       { y0 = m; y1 = min(m + 1, h_ - 1); wy = (i == 2) ? 0.125f : 0.375f; }

    const float* pl = g_msgo + (size_t)bc * N;
    int x0 = 2 * k2;
    int xm = max(x0 - 1, 0), x1 = x0 + 1, x2 = min(x0 + 2, w_ - 1);
    const float* r0p = pl + y0 * w_;
    const float* r1p = pl + y1 * w_;
    float wy1 = 1.f - wy;
    float pm = wy1 * r0p[xm] + wy * r1p[xm];
    float p0 = wy1 * r0p[x0] + wy * r1p[x0];
    float p1 = wy1 * r0p[x1] + wy * r1p[x1];
    float p2 = wy1 * r0p[x2] + wy * r1p[x2];

    float A = alpha[0];
    size_t base = (size_t)t * 8;
    float4 i0 = *(const float4*)(img + base);
    float4 i1 = *(const float4*)(img + base + 4);
    float4 o0, o1;
    o0.x = i0.x + A * (0.375f * pm + 0.625f * p0);
    o0.y = i0.y + A * (0.125f * pm + 0.875f * p0);
    o0.z = i0.z + A * (0.875f * p0 + 0.125f * p1);
    o0.w = i0.w + A * (0.625f * p0 + 0.375f * p1);
    o1.x = i1.x + A * (0.375f * p0 + 0.625f * p1);
    o1.y = i1.y + A * (0.125f * p0 + 0.875f * p1);
    o1.z = i1.z + A * (0.875f * p1 + 0.125f * p2);
    o1.w = i1.w + A * (0.625f * p1 + 0.375f * p2);
    *(float4*)(out + base)     = o0;
    *(float4*)(out + base + 4) = o1;
}

// ---------------- launch ----------------
extern "C" void kernel_launch(void* const* d_in, const int* in_sizes, int n_in,
                              void* d_out, int out_size) {
    const float* img_bev  = (const float*)d_in[0];
    const float* rad_bev  = (const float*)d_in[1];
    const float* occ_prob = (const float*)d_in[2];
    const float* Wq    = (const float*)d_in[3];
    const float* Wk    = (const float*)d_in[4];
    const float* Wv    = (const float*)d_in[5];
    const float* Wo    = (const float*)d_in[6];
    const float* gq_w  = (const float*)d_in[7];
    const float* gq_b  = (const float*)d_in[8];
    const float* gk_w  = (const float*)d_in[9];
    const float* gk_b  = (const float*)d_in[10];
    const float* alpha = (const float*)d_in[11];
    float* out = (float*)d_out;

    front_kernel<<<1224, 256>>>(img_bev, rad_bev, occ_prob, Wq, Wk, Wv);

    dim3 ag(w_ / TX, h_ / TY, B);
    attn_kernel<<<ag, 128>>>(gq_w, gq_b, gk_w, gk_b);

    dim3 wg(N / 128, CI / 128, B);
    wo_kernel<<<wg, 256>>>(Wo);

    upsample_add<<<(B * CI * H * 48 + 255) / 256, 256>>>(img_bev, alpha, out);
}

// round 9
// speedup vs baseline: 2.0359x; 1.0065x over previous
#include <cuda_runtime.h>

// ---------------- problem constants ----------------
constexpr int B   = 2;
constexpr int CI  = 256;
constexpr int CR  = 128;
constexpr int H   = 384;
constexpr int W   = 384;
constexpr int h_  = 96;
constexpr int w_  = 96;
constexpr int N   = h_ * w_;       // 9216
constexpr int D   = 64;
constexpr int GRP = 8;

// attention tile geometry: 8x4 pixels, lane = (pix, channel-quarter)
constexpr int TX = 8;
constexpr int TY = 4;
constexpr int HC = TX + 6;         // 14
constexpr int HR = TY + 6;         // 10
constexpr int NCOL = HC * HR;      // 140
constexpr int C4STR = 17;          // float4 stride per col (16 + pad)

// ---------------- scratch ----------------
__device__ float g_locc[B * N];            // 2*ln(clamp(occ,1e-6))
__device__ float g_gate[B * N];            // clamp(occ,0,1)
__device__ float g_q[B * N * D];           // [b, n, d]  (raw, pre-GN)
__device__ float g_k[B * N * D];           // raw, pre-GN
__device__ float g_v[B * N * D];
__device__ float g_msg[B * N * D];
__device__ float g_msgo[B * CI * N];       // [b, co, n]
__device__ float g_qstats[B * GRP * 2];    // (sum, sumsq) -- zeroed at load & by upsample tail
__device__ float g_kstats[B * GRP * 2];

// ---------------- f32x2 packed-FMA helpers ----------------
__device__ __forceinline__ unsigned long long ffma2(unsigned long long a,
                                                    unsigned long long b,
                                                    unsigned long long c) {
    unsigned long long d;
    asm("fma.rn.f32x2 %0, %1, %2, %3;" : "=l"(d) : "l"(a), "l"(b), "l"(c));
    return d;
}
__device__ __forceinline__ unsigned long long pack2(float x) {
    unsigned long long d;
    asm("mov.b64 %0, {%1, %2};" : "=l"(d)
        : "r"(__float_as_uint(x)), "r"(__float_as_uint(x)));
    return d;
}
__device__ __forceinline__ float2 ffma2v(float2 a, float2 b, float2 c) {
    float2 d;
    asm("fma.rn.f32x2 %0, %1, %2, %3;"
        : "=l"(reinterpret_cast<unsigned long long&>(d))
        : "l"(reinterpret_cast<unsigned long long&>(a)),
          "l"(reinterpret_cast<unsigned long long&>(b)),
          "l"(reinterpret_cast<unsigned long long&>(c)));
    return d;
}

// ================= merged front kernel =================
// blocks [0,576): fused avgpool+Wq proj (+GN q stats)
// blocks [576,1152): fused maxpool+Wk/Wv proj (+GN k stats)
// blocks [1152,1224): occ maxpool -> locc/gate
__global__ __launch_bounds__(256) void front_kernel(
    const float* __restrict__ img, const float* __restrict__ rad,
    const float* __restrict__ occ,
    const float* __restrict__ Wq, const float* __restrict__ Wk,
    const float* __restrict__ Wv) {
    __shared__ __align__(16) float sm[2 * 2080 + 1024];   // 20.7 KB
    int bid = blockIdx.x;
    int tid = threadIdx.x;

    if (bid < 576) {
        // ---------------- proj_q ----------------
        float* Ws = sm;            // [c][o] stride 65
        float* Is = sm + 2080;     // [c][n] 32x32
        int b  = bid / 288;
        int n0 = (bid % 288) * 32;
        int y  = n0 / w_, x0 = n0 % w_;
        int tx = tid & 7;
        int ty = tid >> 3;
        float acc[2][4] = {};

        for (int c0 = 0; c0 < CI; c0 += 32) {
            for (int i = tid; i < 2048; i += 256) {
                int c = i & 31, o = i >> 5;
                Ws[c * 65 + o] = Wq[o * CI + c0 + c];
            }
            for (int i = tid; i < 1024; i += 256) {
                int c = i >> 5, x = i & 31;
                const float* p = img + (((size_t)(b * CI + c0 + c) * H + y * 4) * W) + (x0 + x) * 4;
                float s = 0.f;
#pragma unroll
                for (int r = 0; r < 4; r++) {
                    float4 v = *(const float4*)(p + r * W);
                    s += v.x + v.y + v.z + v.w;
                }
                Is[c * 32 + x] = s * 0.0625f;
            }
            __syncthreads();
#pragma unroll
            for (int c = 0; c < 32; c++) {
                float a0 = Ws[c * 65 + ty * 2];
                float a1 = Ws[c * 65 + ty * 2 + 1];
                float4 bb = *(const float4*)&Is[c * 32 + tx * 4];
                acc[0][0] += a0 * bb.x; acc[0][1] += a0 * bb.y;
                acc[0][2] += a0 * bb.z; acc[0][3] += a0 * bb.w;
                acc[1][0] += a1 * bb.x; acc[1][1] += a1 * bb.y;
                acc[1][2] += a1 * bb.z; acc[1][3] += a1 * bb.w;
            }
            __syncthreads();
        }

        float s = 0.f, s2 = 0.f;
#pragma unroll
        for (int j = 0; j < 4; j++) {
            float2 o2 = make_float2(acc[0][j], acc[1][j]);
            *(float2*)(g_q + ((size_t)(b * N + n0 + tx * 4 + j)) * 64 + ty * 2) = o2;
            s  += o2.x + o2.y;
            s2 += o2.x * o2.x + o2.y * o2.y;
        }
#pragma unroll
        for (int off = 16; off; off >>= 1) {
            s  += __shfl_down_sync(0xffffffffu, s,  off);
            s2 += __shfl_down_sync(0xffffffffu, s2, off);
        }
        if ((tid & 31) == 0) {
            int g = tid >> 5;
            atomicAdd(&g_qstats[(b * 8 + g) * 2 + 0], s);
            atomicAdd(&g_qstats[(b * 8 + g) * 2 + 1], s2);
        }
    } else if (bid < 1152) {
        // ---------------- proj_kv ----------------
        float* Wks = sm;
        float* Wvs = sm + 2080;
        float* Is  = sm + 4160;
        int pb = bid - 576;
        int b  = pb / 288;
        int n0 = (pb % 288) * 32;
        int y  = n0 / w_, x0 = n0 % w_;
        int tx = tid & 7;
        int ty = tid >> 3;
        float ak[2][4] = {};
        float av[2][4] = {};

        for (int c0 = 0; c0 < CR; c0 += 32) {
            for (int i = tid; i < 2048; i += 256) {
                int c = i & 31, o = i >> 5;
                Wks[c * 65 + o] = Wk[o * CR + c0 + c];
                Wvs[c * 65 + o] = Wv[o * CR + c0 + c];
            }
            for (int i = tid; i < 1024; i += 256) {
                int c = i >> 5, x = i & 31;
                const float* p = rad + (((size_t)(b * CR + c0 + c) * H + y * 4) * W) + (x0 + x) * 4;
                float m = -3.4e38f;
#pragma unroll
                for (int r = 0; r < 4; r++) {
                    float4 v = *(const float4*)(p + r * W);
                    m = fmaxf(m, fmaxf(fmaxf(v.x, v.y), fmaxf(v.z, v.w)));
                }
                Is[c * 32 + x] = m;
            }
            __syncthreads();
#pragma unroll
            for (int c = 0; c < 32; c++) {
                float ka0 = Wks[c * 65 + ty * 2];
                float ka1 = Wks[c * 65 + ty * 2 + 1];
                float va0 = Wvs[c * 65 + ty * 2];
                float va1 = Wvs[c * 65 + ty * 2 + 1];
                float4 bb = *(const float4*)&Is[c * 32 + tx * 4];
                ak[0][0] += ka0 * bb.x; ak[0][1] += ka0 * bb.y;
                ak[0][2] += ka0 * bb.z; ak[0][3] += ka0 * bb.w;
                ak[1][0] += ka1 * bb.x; ak[1][1] += ka1 * bb.y;
                ak[1][2] += ka1 * bb.z; ak[1][3] += ka1 * bb.w;
                av[0][0] += va0 * bb.x; av[0][1] += va0 * bb.y;
                av[0][2] += va0 * bb.z; av[0][3] += va0 * bb.w;
                av[1][0] += va1 * bb.x; av[1][1] += va1 * bb.y;
                av[1][2] += va1 * bb.z; av[1][3] += va1 * bb.w;
            }
            __syncthreads();
        }

        float s = 0.f, s2 = 0.f;
#pragma unroll
        for (int j = 0; j < 4; j++) {
            size_t row = ((size_t)(b * N + n0 + tx * 4 + j)) * 64 + ty * 2;
            float2 k2 = make_float2(ak[0][j], ak[1][j]);
            float2 v2 = make_float2(av[0][j], av[1][j]);
            *(float2*)(g_k + row) = k2;
            *(float2*)(g_v + row) = v2;
            s  += k2.x + k2.y;
            s2 += k2.x * k2.x + k2.y * k2.y;
        }
#pragma unroll
        for (int off = 16; off; off >>= 1) {
            s  += __shfl_down_sync(0xffffffffu, s,  off);
            s2 += __shfl_down_sync(0xffffffffu, s2, off);
        }
        if ((tid & 31) == 0) {
            int g = tid >> 5;
            atomicAdd(&g_kstats[(b * 8 + g) * 2 + 0], s);
            atomicAdd(&g_kstats[(b * 8 + g) * 2 + 1], s2);
        }
    } else {
        // ---------------- pool_occ ----------------
        int t = (bid - 1152) * 256 + tid;
        if (t >= B * N) return;
        int x = t % w_;
        int y = (t / w_) % h_;
        int b = t / N;
        const float* p = occ + ((size_t)b * H + y * 4) * W + x * 4;
        float m = -3.4e38f;
#pragma unroll
        for (int r = 0; r < 4; r++) {
            float4 v = *(const float4*)(p + r * W);
            m = fmaxf(m, fmaxf(fmaxf(v.x, v.y), fmaxf(v.z, v.w)));
        }
        g_locc[t] = 2.f * logf(fmaxf(m, 1e-6f));
        g_gate[t] = fminf(fmaxf(m, 0.f), 1.f);
    }
}

// ---------------- attention: tiled, quarter-lane, fully unrolled ----------
__global__ __launch_bounds__(128)
void attn_kernel(const float* __restrict__ gq_w, const float* __restrict__ gq_b,
                 const float* __restrict__ gk_w, const float* __restrict__ gk_b) {
    __shared__ float4 kv_s[NCOL * C4STR];     // 38080 B
    __shared__ float  w_s[32 * 49];           //  6272 B
    __shared__ float  locc_s[NCOL];
    __shared__ float  sQA[64], sQB[64], sAk[64], sBk[64];

    int x0 = blockIdx.x * TX, y0 = blockIdx.y * TY, b = blockIdx.z;
    int tid  = threadIdx.x;
    int wrp  = tid >> 5;          // tile row
    int lane = tid & 31;
    int pix  = lane & 7;          // x within tile
    int qtr  = lane >> 3;         // channel quarter (16 ch)
    int c0   = qtr * 16;

    if (tid < 64) {
        int d = tid, g = d >> 3;
        const float inv = 1.f / (float)(N * 8);
        float su  = g_qstats[(b * 8 + g) * 2 + 0];
        float su2 = g_qstats[(b * 8 + g) * 2 + 1];
        float mu = su * inv;
        float rs = rsqrtf(su2 * inv - mu * mu + 1e-5f);
        float A = rs * gq_w[d];
        sQA[d] = A;
        sQB[d] = gq_b[d] - mu * A;
        su  = g_kstats[(b * 8 + g) * 2 + 0];
        su2 = g_kstats[(b * 8 + g) * 2 + 1];
        mu = su * inv;
        rs = rsqrtf(su2 * inv - mu * mu + 1e-5f);
        A = rs * gk_w[d];
        sAk[d] = A;
        sBk[d] = gk_b[d] - mu * A;
    }

    // ---- stage k halo (+locc), zero-filled outside the image ----
    for (int i = tid; i < NCOL * 16; i += 128) {
        int col = i >> 4, quad = i & 15;
        int r = col / HC, cc = col - r * HC;
        int yy = y0 - 3 + r, xx = x0 - 3 + cc;
        bool ok = ((unsigned)yy < (unsigned)h_) && ((unsigned)xx < (unsigned)w_);
        int nn = b * N + yy * w_ + xx;
        float4 v = make_float4(0.f, 0.f, 0.f, 0.f);
        if (ok) v = *(const float4*)(g_k + (size_t)nn * 64 + quad * 4);
        kv_s[col * C4STR + quad] = v;
        if (quad == 0) locc_s[col] = ok ? g_locc[nn] : 0.f;
    }
    __syncthreads();

    int nq = b * N + (y0 + wrp) * w_ + x0 + pix;

    // ---- q: load 16 channels, fold q-GN and k-GN (A,B) ----
    float2 qp[8];
    float qB = 0.f;
    {
        const float* qr = g_q + (size_t)nq * 64 + c0;
#pragma unroll
        for (int c4 = 0; c4 < 16; c4 += 4) {
            float4 q4 = *(const float4*)(qr + c4);
            int d = c0 + c4;
            float n0 = q4.x * sQA[d + 0] + sQB[d + 0];
            float n1 = q4.y * sQA[d + 1] + sQB[d + 1];
            float n2 = q4.z * sQA[d + 2] + sQB[d + 2];
            float n3 = q4.w * sQA[d + 3] + sQB[d + 3];
            qB += n0 * sBk[d + 0] + n1 * sBk[d + 1]
                + n2 * sBk[d + 2] + n3 * sBk[d + 3];
            qp[c4 / 2]     = make_float2(n0 * sAk[d + 0] * 0.125f, n1 * sAk[d + 1] * 0.125f);
            qp[c4 / 2 + 1] = make_float2(n2 * sAk[d + 2] * 0.125f, n3 * sAk[d + 3] * 0.125f);
        }
    }
    qB += __shfl_xor_sync(0xffffffffu, qB, 8);
    qB += __shfl_xor_sync(0xffffffffu, qB, 16);
    float qB2 = qB * 0.125f;

    const float LPAD = -27.631021115928547f;  // 2*ln(1e-6)
    // position this thread owns within each group of 4: perm = [0,2,1,3]
    int pbase = ((qtr & 1) << 1) + (qtr >> 1);
    bool q_lo = (qtr & 1) == 0;
    bool q_hi = (qtr & 2) == 0;

    // base smem index of this thread's (row, pix) anchor, and quarter offset
    const float4* kbase = &kv_s[(wrp * HC + pix) * C4STR + qtr * 4];

    float lg[13];
    float m_own = -1e30f;

    // ---- pass 1: logits, FULLY UNROLLED (compile-time dy/dx offsets) ----
#pragma unroll
    for (int g = 0; g < 13; g++) {
        float d4[4];
#pragma unroll
        for (int j = 0; j < 4; j++) {
            constexpr int pmax = 48;
            int p = g * 4 + j; if (p > pmax) p = pmax;   // compile-time
            int dy = p / 7, dx = p - dy * 7;             // compile-time
            const float4* kp = kbase + (dy * HC + dx) * C4STR;
            float2 a2 = make_float2(0.f, 0.f);
            float2 b2 = make_float2(0.f, 0.f);
#pragma unroll
            for (int c = 0; c < 4; c++) {
                float4 k4 = kp[c];
                a2 = ffma2v(qp[2 * c],     make_float2(k4.x, k4.y), a2);
                b2 = ffma2v(qp[2 * c + 1], make_float2(k4.z, k4.w), b2);
            }
            d4[j] = a2.x + a2.y + b2.x + b2.y;
        }
        // butterfly transpose-reduce: 3 shuffles for 4 full sums
        float x = __shfl_xor_sync(0xffffffffu, q_lo ? d4[2] : d4[0], 8);
        float y = __shfl_xor_sync(0xffffffffu, q_lo ? d4[3] : d4[1], 8);
        float s0 = (q_lo ? d4[0] : d4[2]) + x;
        float s1 = (q_lo ? d4[1] : d4[3]) + y;
        float z = __shfl_xor_sync(0xffffffffu, q_hi ? s1 : s0, 16);
        float dot = (q_hi ? s0 : s1) + z;

        int p_own = g * 4 + pbase;   // runtime only through pbase (uniform per thread)
        if (p_own <= 48) {
            int dy = p_own / 7, dx = p_own - dy * 7;
            int yy = y0 + wrp + dy - 3;
            int xx = x0 + pix + dx - 3;
            bool inb = ((unsigned)yy < (unsigned)h_) && ((unsigned)xx < (unsigned)w_);
            int col = (wrp + dy) * HC + pix + dx;
            float logit = inb ? (dot + qB2 + locc_s[col]) : LPAD;
            lg[g] = logit;
            m_own = fmaxf(m_own, logit);
        }
    }

    // ---- softmax: 2-shuffle max, exp own logits, 2-shuffle sum ----
    m_own = fmaxf(m_own, __shfl_xor_sync(0xffffffffu, m_own, 8));
    m_own = fmaxf(m_own, __shfl_xor_sync(0xffffffffu, m_own, 16));
    float* wr = &w_s[(wrp * 8 + pix) * 49];
    float ssum = 0.f;
#pragma unroll
    for (int g = 0; g < 13; g++) {
        int p_own = g * 4 + pbase;
        if (p_own <= 48) {
            float e = __expf(lg[g] - m_own);
            ssum += e;
            wr[p_own] = e;
        }
    }
    ssum += __shfl_xor_sync(0xffffffffu, ssum, 8);
    ssum += __shfl_xor_sync(0xffffffffu, ssum, 16);
    float gs = g_gate[nq] / ssum;   // occ gate commutes with Wo

    // ---- stage v halo into the same buffer ----
    __syncthreads();
    for (int i = tid; i < NCOL * 16; i += 128) {
        int col = i >> 4, quad = i & 15;
        int r = col / HC, cc = col - r * HC;
        int yy = y0 - 3 + r, xx = x0 - 3 + cc;
        bool ok = ((unsigned)yy < (unsigned)h_) && ((unsigned)xx < (unsigned)w_);
        float4 v = make_float4(0.f, 0.f, 0.f, 0.f);
        if (ok) v = *(const float4*)(g_v + ((size_t)(b * N + yy * w_ + xx)) * 64 + quad * 4);
        kv_s[col * C4STR + quad] = v;
    }
    __syncthreads();

    // ---- pass 2: weighted v accumulation, FULLY UNROLLED ----
    float2 acc[8];
#pragma unroll
    for (int c = 0; c < 8; c++) acc[c] = make_float2(0.f, 0.f);
#pragma unroll
    for (int dy = 0; dy < 7; dy++) {
#pragma unroll
        for (int dx = 0; dx < 7; dx++) {
            int p = dy * 7 + dx;                         // compile-time
            float wgt = wr[p];
            float2 w2 = make_float2(wgt, wgt);
            const float4* vp = kbase + (dy * HC + dx) * C4STR;
#pragma unroll
            for (int c = 0; c < 4; c++) {
                float4 v4 = vp[c];
                acc[2 * c]     = ffma2v(w2, make_float2(v4.x, v4.y), acc[2 * c]);
                acc[2 * c + 1] = ffma2v(w2, make_float2(v4.z, v4.w), acc[2 * c + 1]);
            }
        }
    }
    float* mp = g_msg + (size_t)nq * 64 + c0;
#pragma unroll
    for (int c = 0; c < 8; c += 2) {
        *(float4*)(mp + c * 2) = make_float4(acc[c].x * gs, acc[c].y * gs,
                                             acc[c + 1].x * gs, acc[c + 1].y * gs);
    }
}

// ---------------- Wo projection with packed f32x2 FMA ----------------
__global__ __launch_bounds__(256) void wo_kernel(const float* __restrict__ Wo) {
    __shared__ float Ws[32 * 132];   // [d][o]
    __shared__ float Ms[32 * 132];   // [d][n]
    int b   = blockIdx.z;
    int co0 = blockIdx.y * 128;
    int n0  = blockIdx.x * 128;
    int tid = threadIdx.x;
    int tx = tid & 15;   // n octet
    int ty = tid >> 4;   // co octet

    unsigned long long acc[8][4] = {};

    for (int kc = 0; kc < 2; kc++) {
        int d0 = kc * 32;
        for (int idx = tid; idx < 1024; idx += 256) {
            int r = idx >> 3, dq = idx & 7;
            float4 v = *(const float4*)(Wo + (size_t)(co0 + r) * 64 + d0 + dq * 4);
            Ws[(dq * 4 + 0) * 132 + r] = v.x;
            Ws[(dq * 4 + 1) * 132 + r] = v.y;
            Ws[(dq * 4 + 2) * 132 + r] = v.z;
            Ws[(dq * 4 + 3) * 132 + r] = v.w;
            float4 u = *(const float4*)(g_msg + ((size_t)(b * N + n0 + r)) * 64 + d0 + dq * 4);
            Ms[(dq * 4 + 0) * 132 + r] = u.x;
            Ms[(dq * 4 + 1) * 132 + r] = u.y;
            Ms[(dq * 4 + 2) * 132 + r] = u.z;
            Ms[(dq * 4 + 3) * 132 + r] = u.w;
        }
        __syncthreads();
#pragma unroll
        for (int d = 0; d < 32; d++) {
            unsigned long long b2[4];
#pragma unroll
            for (int jp = 0; jp < 4; jp++)
                b2[jp] = *(const unsigned long long*)&Ms[d * 132 + tx * 8 + jp * 2];
#pragma unroll
            for (int i = 0; i < 8; i++) {
                unsigned long long a2 = pack2(Ws[d * 132 + ty * 8 + i]);
#pragma unroll
                for (int jp = 0; jp < 4; jp++)
                    acc[i][jp] = ffma2(a2, b2[jp], acc[i][jp]);
            }
        }
        __syncthreads();
    }
#pragma unroll
    for (int i = 0; i < 8; i++) {
        float2 r0 = *(float2*)&acc[i][0];
        float2 r1 = *(float2*)&acc[i][1];
        float2 r2 = *(float2*)&acc[i][2];
        float2 r3 = *(float2*)&acc[i][3];
        float* dst = g_msgo + ((size_t)(b * CI + co0 + ty * 8 + i)) * N + n0 + tx * 8;
        *(float4*)dst       = make_float4(r0.x, r0.y, r1.x, r1.y);
        *(float4*)(dst + 4) = make_float4(r2.x, r2.y, r3.x, r3.y);
    }
}

// ------- bilinear x4 upsample + residual; block 0 re-zeroes GN stats -------
__global__ void upsample_add(const float* __restrict__ img,
                             const float* __restrict__ alpha,
                             float* __restrict__ out) {
    if (blockIdx.x == 0 && threadIdx.x < 64) {
        // stats were consumed by attn earlier in this replay; reset for next.
        if (threadIdx.x < 32) g_qstats[threadIdx.x] = 0.f;
        else                  g_kstats[threadIdx.x - 32] = 0.f;
    }
    int t = blockIdx.x * blockDim.x + threadIdx.x;
    if (t >= B * CI * H * 48) return;
    int k2 = t % 48;
    int Y  = (t / 48) % H;
    int bc = t / (48 * H);

    int m = Y >> 2, i = Y & 3;
    int y0, y1;
    float wy;
    if (i < 2) { y0 = max(m - 1, 0); y1 = m; wy = (i == 0) ? 0.625f : 0.875f; }
    else       { y0 = m; y1 = min(m + 1, h_ - 1); wy = (i == 2) ? 0.125f : 0.375f; }

    const float* pl = g_msgo + (size_t)bc * N;
    int x0 = 2 * k2;
    int xm = max(x0 - 1, 0), x1 = x0 + 1, x2 = min(x0 + 2, w_ - 1);
    const float* r0p = pl + y0 * w_;
    const float* r1p = pl + y1 * w_;
    float wy1 = 1.f - wy;
    float pm = wy1 * r0p[xm] + wy * r1p[xm];
    float p0 = wy1 * r0p[x0] + wy * r1p[x0];
    float p1 = wy1 * r0p[x1] + wy * r1p[x1];
    float p2 = wy1 * r0p[x2] + wy * r1p[x2];

    float A = alpha[0];
    size_t base = (size_t)t * 8;
    float4 i0 = *(const float4*)(img + base);
    float4 i1 = *(const float4*)(img + base + 4);
    float4 o0, o1;
    o0.x = i0.x + A * (0.375f * pm + 0.625f * p0);
    o0.y = i0.y + A * (0.125f * pm + 0.875f * p0);
    o0.z = i0.z + A * (0.875f * p0 + 0.125f * p1);
    o0.w = i0.w + A * (0.625f * p0 + 0.375f * p1);
    o1.x = i1.x + A * (0.375f * p0 + 0.625f * p1);
    o1.y = i1.y + A * (0.125f * p0 + 0.875f * p1);
    o1.z = i1.z + A * (0.875f * p1 + 0.125f * p2);
    o1.w = i1.w + A * (0.625f * p1 + 0.375f * p2);
    *(float4*)(out + base)     = o0;
    *(float4*)(out + base + 4) = o1;
}

// ---------------- launch ----------------
extern "C" void kernel_launch(void* const* d_in, const int* in_sizes, int n_in,
                              void* d_out, int out_size) {
    const float* img_bev  = (const float*)d_in[0];
    const float* rad_bev  = (const float*)d_in[1];
    const float* occ_prob = (const float*)d_in[2];
    const float* Wq    = (const float*)d_in[3];
    const float* Wk    = (const float*)d_in[4];
    const float* Wv    = (const float*)d_in[5];
    const float* Wo    = (const float*)d_in[6];
    const float* gq_w  = (const float*)d_in[7];
    const float* gq_b  = (const float*)d_in[8];
    const float* gk_w  = (const float*)d_in[9];
    const float* gk_b  = (const float*)d_in[10];
    const float* alpha = (const float*)d_in[11];
    float* out = (float*)d_out;

    front_kernel<<<1224, 256>>>(img_bev, rad_bev, occ_prob, Wq, Wk, Wv);

    dim3 ag(w_ / TX, h_ / TY, B);
    attn_kernel<<<ag, 128>>>(gq_w, gq_b, gk_w, gk_b);

    dim3 wg(N / 128, CI / 128, B);
    wo_kernel<<<wg, 256>>>(Wo);

    upsample_add<<<(B * CI * H * 48 + 255) / 256, 256>>>(img_bev, alpha, out);
}

// round 10
// speedup vs baseline: 2.0505x; 1.0072x over previous
#include <cuda_runtime.h>

// ---------------- problem constants ----------------
constexpr int B   = 2;
constexpr int CI  = 256;
constexpr int CR  = 128;
constexpr int H   = 384;
constexpr int W   = 384;
constexpr int h_  = 96;
constexpr int w_  = 96;
constexpr int N   = h_ * w_;       // 9216
constexpr int D   = 64;
constexpr int GRP = 8;

// attention tile geometry: 8x4 pixels, 8 threads/pixel (channel octets)
constexpr int TX = 8;
constexpr int TY = 4;
constexpr int HC = TX + 6;         // 14
constexpr int HR = TY + 6;         // 10
constexpr int NCOL = HC * HR;      // 140
constexpr int C4STR = 18;          // float4 stride per col (16 + 2 pad) => ≡2 mod 8, conflict-free

// ---------------- scratch ----------------
__device__ float g_locc[B * N];
__device__ float g_gate[B * N];
__device__ float g_q[B * N * D];
__device__ float g_k[B * N * D];
__device__ float g_v[B * N * D];
__device__ float g_msg[B * N * D];
__device__ float g_msgo[B * CI * N];
__device__ float g_qstats[B * GRP * 2];
__device__ float g_kstats[B * GRP * 2];

// ---------------- f32x2 packed-FMA helpers ----------------
__device__ __forceinline__ unsigned long long ffma2(unsigned long long a,
                                                    unsigned long long b,
                                                    unsigned long long c) {
    unsigned long long d;
    asm("fma.rn.f32x2 %0, %1, %2, %3;" : "=l"(d) : "l"(a), "l"(b), "l"(c));
    return d;
}
__device__ __forceinline__ unsigned long long pack2(float x) {
    unsigned long long d;
    asm("mov.b64 %0, {%1, %2};" : "=l"(d)
        : "r"(__float_as_uint(x)), "r"(__float_as_uint(x)));
    return d;
}
__device__ __forceinline__ float2 ffma2v(float2 a, float2 b, float2 c) {
    float2 d;
    asm("fma.rn.f32x2 %0, %1, %2, %3;"
        : "=l"(reinterpret_cast<unsigned long long&>(d))
        : "l"(reinterpret_cast<unsigned long long&>(a)),
          "l"(reinterpret_cast<unsigned long long&>(b)),
          "l"(reinterpret_cast<unsigned long long&>(c)));
    return d;
}

// ================= merged front kernel (unchanged from R8/R9) =============
__global__ __launch_bounds__(256) void front_kernel(
    const float* __restrict__ img, const float* __restrict__ rad,
    const float* __restrict__ occ,
    const float* __restrict__ Wq, const float* __restrict__ Wk,
    const float* __restrict__ Wv) {
    __shared__ __align__(16) float sm[2 * 2080 + 1024];
    int bid = blockIdx.x;
    int tid = threadIdx.x;

    if (bid < 576) {
        float* Ws = sm;
        float* Is = sm + 2080;
        int b  = bid / 288;
        int n0 = (bid % 288) * 32;
        int y  = n0 / w_, x0 = n0 % w_;
        int tx = tid & 7;
        int ty = tid >> 3;
        float acc[2][4] = {};

        for (int c0 = 0; c0 < CI; c0 += 32) {
            for (int i = tid; i < 2048; i += 256) {
                int c = i & 31, o = i >> 5;
                Ws[c * 65 + o] = Wq[o * CI + c0 + c];
            }
            for (int i = tid; i < 1024; i += 256) {
                int c = i >> 5, x = i & 31;
                const float* p = img + (((size_t)(b * CI + c0 + c) * H + y * 4) * W) + (x0 + x) * 4;
                float s = 0.f;
#pragma unroll
                for (int r = 0; r < 4; r++) {
                    float4 v = *(const float4*)(p + r * W);
                    s += v.x + v.y + v.z + v.w;
                }
                Is[c * 32 + x] = s * 0.0625f;
            }
            __syncthreads();
#pragma unroll
            for (int c = 0; c < 32; c++) {
                float a0 = Ws[c * 65 + ty * 2];
                float a1 = Ws[c * 65 + ty * 2 + 1];
                float4 bb = *(const float4*)&Is[c * 32 + tx * 4];
                acc[0][0] += a0 * bb.x; acc[0][1] += a0 * bb.y;
                acc[0][2] += a0 * bb.z; acc[0][3] += a0 * bb.w;
                acc[1][0] += a1 * bb.x; acc[1][1] += a1 * bb.y;
                acc[1][2] += a1 * bb.z; acc[1][3] += a1 * bb.w;
            }
            __syncthreads();
        }

        float s = 0.f, s2 = 0.f;
#pragma unroll
        for (int j = 0; j < 4; j++) {
            float2 o2 = make_float2(acc[0][j], acc[1][j]);
            *(float2*)(g_q + ((size_t)(b * N + n0 + tx * 4 + j)) * 64 + ty * 2) = o2;
            s  += o2.x + o2.y;
            s2 += o2.x * o2.x + o2.y * o2.y;
        }
#pragma unroll
        for (int off = 16; off; off >>= 1) {
            s  += __shfl_down_sync(0xffffffffu, s,  off);
            s2 += __shfl_down_sync(0xffffffffu, s2, off);
        }
        if ((tid & 31) == 0) {
            int g = tid >> 5;
            atomicAdd(&g_qstats[(b * 8 + g) * 2 + 0], s);
            atomicAdd(&g_qstats[(b * 8 + g) * 2 + 1], s2);
        }
    } else if (bid < 1152) {
        float* Wks = sm;
        float* Wvs = sm + 2080;
        float* Is  = sm + 4160;
        int pb = bid - 576;
        int b  = pb / 288;
        int n0 = (pb % 288) * 32;
        int y  = n0 / w_, x0 = n0 % w_;
        int tx = tid & 7;
        int ty = tid >> 3;
        float ak[2][4] = {};
        float av[2][4] = {};

        for (int c0 = 0; c0 < CR; c0 += 32) {
            for (int i = tid; i < 2048; i += 256) {
                int c = i & 31, o = i >> 5;
                Wks[c * 65 + o] = Wk[o * CR + c0 + c];
                Wvs[c * 65 + o] = Wv[o * CR + c0 + c];
            }
            for (int i = tid; i < 1024; i += 256) {
                int c = i >> 5, x = i & 31;
                const float* p = rad + (((size_t)(b * CR + c0 + c) * H + y * 4) * W) + (x0 + x) * 4;
                float m = -3.4e38f;
#pragma unroll
                for (int r = 0; r < 4; r++) {
                    float4 v = *(const float4*)(p + r * W);
                    m = fmaxf(m, fmaxf(fmaxf(v.x, v.y), fmaxf(v.z, v.w)));
                }
                Is[c * 32 + x] = m;
            }
            __syncthreads();
#pragma unroll
            for (int c = 0; c < 32; c++) {
                float ka0 = Wks[c * 65 + ty * 2];
                float ka1 = Wks[c * 65 + ty * 2 + 1];
                float va0 = Wvs[c * 65 + ty * 2];
                float va1 = Wvs[c * 65 + ty * 2 + 1];
                float4 bb = *(const float4*)&Is[c * 32 + tx * 4];
                ak[0][0] += ka0 * bb.x; ak[0][1] += ka0 * bb.y;
                ak[0][2] += ka0 * bb.z; ak[0][3] += ka0 * bb.w;
                ak[1][0] += ka1 * bb.x; ak[1][1] += ka1 * bb.y;
                ak[1][2] += ka1 * bb.z; ak[1][3] += ka1 * bb.w;
                av[0][0] += va0 * bb.x; av[0][1] += va0 * bb.y;
                av[0][2] += va0 * bb.z; av[0][3] += va0 * bb.w;
                av[1][0] += va1 * bb.x; av[1][1] += va1 * bb.y;
                av[1][2] += va1 * bb.z; av[1][3] += va1 * bb.w;
            }
            __syncthreads();
        }

        float s = 0.f, s2 = 0.f;
#pragma unroll
        for (int j = 0; j < 4; j++) {
            size_t row = ((size_t)(b * N + n0 + tx * 4 + j)) * 64 + ty * 2;
            float2 k2 = make_float2(ak[0][j], ak[1][j]);
            float2 v2 = make_float2(av[0][j], av[1][j]);
            *(float2*)(g_k + row) = k2;
            *(float2*)(g_v + row) = v2;
            s  += k2.x + k2.y;
            s2 += k2.x * k2.x + k2.y * k2.y;
        }
#pragma unroll
        for (int off = 16; off; off >>= 1) {
            s  += __shfl_down_sync(0xffffffffu, s,  off);
            s2 += __shfl_down_sync(0xffffffffu, s2, off);
        }
        if ((tid & 31) == 0) {
            int g = tid >> 5;
            atomicAdd(&g_kstats[(b * 8 + g) * 2 + 0], s);
            atomicAdd(&g_kstats[(b * 8 + g) * 2 + 1], s2);
        }
    } else {
        int t = (bid - 1152) * 256 + tid;
        if (t >= B * N) return;
        int x = t % w_;
        int y = (t / w_) % h_;
        int b = t / N;
        const float* p = occ + ((size_t)b * H + y * 4) * W + x * 4;
        float m = -3.4e38f;
#pragma unroll
        for (int r = 0; r < 4; r++) {
            float4 v = *(const float4*)(p + r * W);
            m = fmaxf(m, fmaxf(fmaxf(v.x, v.y), fmaxf(v.z, v.w)));
        }
        g_locc[t] = 2.f * logf(fmaxf(m, 1e-6f));
        g_gate[t] = fminf(fmaxf(m, 0.f), 1.f);
    }
}

// ------------- attention: 8 threads/pixel (channel octets) ----------------
// block = 256 threads (8 warps), tile 8x4 px. warp w: row = w>>1,
// xhalf = (w&1)*4. lane = oct*4 + pxl: pxl = lane&3 (pixel), oct = lane>>2.
// Thread owns channel quads {oct, oct+8} (8 channels).
__global__ __launch_bounds__(256, 4)
void attn_kernel(const float* __restrict__ gq_w, const float* __restrict__ gq_b,
                 const float* __restrict__ gk_w, const float* __restrict__ gk_b) {
    __shared__ float4 kv_s[NCOL * C4STR];     // 40320 B, stride ≡2 mod 8
    __shared__ float  w_s[32 * 49];           //  6272 B
    __shared__ float  locc_s[NCOL];           //   560 B
    __shared__ float  sQA[64], sQB[64], sAk[64], sBk[64];   // 1024 B

    int x0 = blockIdx.x * TX, y0 = blockIdx.y * TY, b = blockIdx.z;
    int tid  = threadIdx.x;
    int wrp  = tid >> 5;
    int lane = tid & 31;
    int r    = wrp >> 1;                 // tile row 0..3
    int pix  = (wrp & 1) * 4 + (lane & 3);
    int oct  = lane >> 2;                // channel octet 0..7

    if (tid < 64) {
        int d = tid, g = d >> 3;
        const float inv = 1.f / (float)(N * 8);
        float su  = g_qstats[(b * 8 + g) * 2 + 0];
        float su2 = g_qstats[(b * 8 + g) * 2 + 1];
        float mu = su * inv;
        float rs = rsqrtf(su2 * inv - mu * mu + 1e-5f);
        float A = rs * gq_w[d];
        sQA[d] = A;
        sQB[d] = gq_b[d] - mu * A;
        su  = g_kstats[(b * 8 + g) * 2 + 0];
        su2 = g_kstats[(b * 8 + g) * 2 + 1];
        mu = su * inv;
        rs = rsqrtf(su2 * inv - mu * mu + 1e-5f);
        A = rs * gk_w[d];
        sAk[d] = A;
        sBk[d] = gk_b[d] - mu * A;
    }

    // ---- stage k halo (+locc), zero-filled outside the image ----
    for (int i = tid; i < NCOL * 16; i += 256) {
        int col = i >> 4, quad = i & 15;
        int rr = col / HC, cc = col - rr * HC;
        int yy = y0 - 3 + rr, xx = x0 - 3 + cc;
        bool ok = ((unsigned)yy < (unsigned)h_) && ((unsigned)xx < (unsigned)w_);
        int nn = b * N + yy * w_ + xx;
        float4 v = make_float4(0.f, 0.f, 0.f, 0.f);
        if (ok) v = *(const float4*)(g_k + (size_t)nn * 64 + quad * 4);
        kv_s[col * C4STR + quad] = v;
        if (quad == 0) locc_s[col] = ok ? g_locc[nn] : 0.f;
    }
    __syncthreads();

    int nq = b * N + (y0 + r) * w_ + x0 + pix;

    // ---- q: 8 channels (quads oct, oct+8), fold q-GN and k-GN ----
    float2 qp[4];
    float qB;
    {
        const float* qr = g_q + (size_t)nq * 64;
        float4 qa = *(const float4*)(qr + oct * 4);
        float4 qb = *(const float4*)(qr + 32 + oct * 4);
        int da = oct * 4, db = 32 + oct * 4;
        float n0 = qa.x * sQA[da + 0] + sQB[da + 0];
        float n1 = qa.y * sQA[da + 1] + sQB[da + 1];
        float n2 = qa.z * sQA[da + 2] + sQB[da + 2];
        float n3 = qa.w * sQA[da + 3] + sQB[da + 3];
        float n4 = qb.x * sQA[db + 0] + sQB[db + 0];
        float n5 = qb.y * sQA[db + 1] + sQB[db + 1];
        float n6 = qb.z * sQA[db + 2] + sQB[db + 2];
        float n7 = qb.w * sQA[db + 3] + sQB[db + 3];
        qB = n0 * sBk[da + 0] + n1 * sBk[da + 1] + n2 * sBk[da + 2] + n3 * sBk[da + 3]
           + n4 * sBk[db + 0] + n5 * sBk[db + 1] + n6 * sBk[db + 2] + n7 * sBk[db + 3];
        qp[0] = make_float2(n0 * sAk[da + 0] * 0.125f, n1 * sAk[da + 1] * 0.125f);
        qp[1] = make_float2(n2 * sAk[da + 2] * 0.125f, n3 * sAk[da + 3] * 0.125f);
        qp[2] = make_float2(n4 * sAk[db + 0] * 0.125f, n5 * sAk[db + 1] * 0.125f);
        qp[3] = make_float2(n6 * sAk[db + 2] * 0.125f, n7 * sAk[db + 3] * 0.125f);
    }
    qB += __shfl_xor_sync(0xffffffffu, qB, 4);
    qB += __shfl_xor_sync(0xffffffffu, qB, 8);
    qB += __shfl_xor_sync(0xffffffffu, qB, 16);
    float qB2 = qB * 0.125f;

    const float LPAD = -27.631021115928547f;  // 2*ln(1e-6)
    const float4* kbase = &kv_s[(r * HC + pix) * C4STR];

    float lg[7];
    float m_own = -1e30f;

    // ---- pass 1: logits, fully unrolled; owner oct = p % 8 ----
#pragma unroll
    for (int p = 0; p < 49; p++) {
        int dy = p / 7, dx = p - dy * 7;             // compile-time
        const float4* kp = kbase + (dy * HC + dx) * C4STR;
        float4 ka = kp[oct];
        float4 kb = kp[oct + 8];
        float2 a2 = make_float2(0.f, 0.f);
        a2 = ffma2v(qp[0], make_float2(ka.x, ka.y), a2);
        a2 = ffma2v(qp[2], make_float2(kb.x, kb.y), a2);
        float2 b2 = make_float2(0.f, 0.f);
        b2 = ffma2v(qp[1], make_float2(ka.z, ka.w), b2);
        b2 = ffma2v(qp[3], make_float2(kb.z, kb.w), b2);
        float dot = a2.x + a2.y + b2.x + b2.y;
        dot += __shfl_xor_sync(0xffffffffu, dot, 4);
        dot += __shfl_xor_sync(0xffffffffu, dot, 8);
        dot += __shfl_xor_sync(0xffffffffu, dot, 16);

        if (oct == (p & 7)) {
            int yy = y0 + r + dy - 3;
            int xx = x0 + pix + dx - 3;
            bool inb = ((unsigned)yy < (unsigned)h_) && ((unsigned)xx < (unsigned)w_);
            int col = (r + dy) * HC + pix + dx;
            float logit = inb ? (dot + qB2 + locc_s[col]) : LPAD;
            lg[p >> 3] = logit;
            m_own = fmaxf(m_own, logit);
        }
    }

    // ---- softmax: 3-shuffle max, exp own logits, 3-shuffle sum ----
    m_own = fmaxf(m_own, __shfl_xor_sync(0xffffffffu, m_own, 4));
    m_own = fmaxf(m_own, __shfl_xor_sync(0xffffffffu, m_own, 8));
    m_own = fmaxf(m_own, __shfl_xor_sync(0xffffffffu, m_own, 16));
    int px_idx = r * 8 + pix;
    float* wr = &w_s[px_idx * 49];
    float ssum = 0.f;
#pragma unroll
    for (int g = 0; g < 7; g++) {
        if (g < 6 || oct == 0) {
            float e = __expf(lg[g] - m_own);
            ssum += e;
            wr[g * 8 + oct] = e;
        }
    }
    ssum += __shfl_xor_sync(0xffffffffu, ssum, 4);
    ssum += __shfl_xor_sync(0xffffffffu, ssum, 8);
    ssum += __shfl_xor_sync(0xffffffffu, ssum, 16);
    float gs = g_gate[nq] / ssum;   // occ gate commutes with Wo

    // ---- stage v halo into the same buffer ----
    __syncthreads();
    for (int i = tid; i < NCOL * 16; i += 256) {
        int col = i >> 4, quad = i & 15;
        int rr = col / HC, cc = col - rr * HC;
        int yy = y0 - 3 + rr, xx = x0 - 3 + cc;
        bool ok = ((unsigned)yy < (unsigned)h_) && ((unsigned)xx < (unsigned)w_);
        float4 v = make_float4(0.f, 0.f, 0.f, 0.f);
        if (ok) v = *(const float4*)(g_v + ((size_t)(b * N + yy * w_ + xx)) * 64 + quad * 4);
        kv_s[col * C4STR + quad] = v;
    }
    __syncthreads();

    // ---- pass 2: weighted v accumulation (OOB v = 0; no shuffles) ----
    float2 acc[4];
#pragma unroll
    for (int c = 0; c < 4; c++) acc[c] = make_float2(0.f, 0.f);
#pragma unroll
    for (int p = 0; p < 49; p++) {
        int dy = p / 7, dx = p - dy * 7;             // compile-time
        float wgt = wr[p];
        float2 w2 = make_float2(wgt, wgt);
        const float4* vp = kbase + (dy * HC + dx) * C4STR;
        float4 va = vp[oct];
        float4 vb = vp[oct + 8];
        acc[0] = ffma2v(w2, make_float2(va.x, va.y), acc[0]);
        acc[1] = ffma2v(w2, make_float2(va.z, va.w), acc[1]);
        acc[2] = ffma2v(w2, make_float2(vb.x, vb.y), acc[2]);
        acc[3] = ffma2v(w2, make_float2(vb.z, vb.w), acc[3]);
    }
    float* mp = g_msg + (size_t)nq * 64;
    *(float4*)(mp + oct * 4)      = make_float4(acc[0].x * gs, acc[0].y * gs,
                                                acc[1].x * gs, acc[1].y * gs);
    *(float4*)(mp + 32 + oct * 4) = make_float4(acc[2].x * gs, acc[2].y * gs,
                                                acc[3].x * gs, acc[3].y * gs);
}

// ---------------- Wo projection with packed f32x2 FMA (unchanged) ---------
__global__ __launch_bounds__(256) void wo_kernel(const float* __restrict__ Wo) {
    __shared__ float Ws[32 * 132];
    __shared__ float Ms[32 * 132];
    int b   = blockIdx.z;
    int co0 = blockIdx.y * 128;
    int n0  = blockIdx.x * 128;
    int tid = threadIdx.x;
    int tx = tid & 15;
    int ty = tid >> 4;

    unsigned long long acc[8][4] = {};

    for (int kc = 0; kc < 2; kc++) {
        int d0 = kc * 32;
        for (int idx = tid; idx < 1024; idx += 256) {
            int r = idx >> 3, dq = idx & 7;
            float4 v = *(const float4*)(Wo + (size_t)(co0 + r) * 64 + d0 + dq * 4);
            Ws[(dq * 4 + 0) * 132 + r] = v.x;
            Ws[(dq * 4 + 1) * 132 + r] = v.y;
            Ws[(dq * 4 + 2) * 132 + r] = v.z;
            Ws[(dq * 4 + 3) * 132 + r] = v.w;
            float4 u = *(const float4*)(g_msg + ((size_t)(b * N + n0 + r)) * 64 + d0 + dq * 4);
            Ms[(dq * 4 + 0) * 132 + r] = u.x;
            Ms[(dq * 4 + 1) * 132 + r] = u.y;
            Ms[(dq * 4 + 2) * 132 + r] = u.z;
            Ms[(dq * 4 + 3) * 132 + r] = u.w;
        }
        __syncthreads();
#pragma unroll
        for (int d = 0; d < 32; d++) {
            unsigned long long b2[4];
#pragma unroll
            for (int jp = 0; jp < 4; jp++)
                b2[jp] = *(const unsigned long long*)&Ms[d * 132 + tx * 8 + jp * 2];
#pragma unroll
            for (int i = 0; i < 8; i++) {
                unsigned long long a2 = pack2(Ws[d * 132 + ty * 8 + i]);
#pragma unroll
                for (int jp = 0; jp < 4; jp++)
                    acc[i][jp] = ffma2(a2, b2[jp], acc[i][jp]);
            }
        }
        __syncthreads();
    }
#pragma unroll
    for (int i = 0; i < 8; i++) {
        float2 r0 = *(float2*)&acc[i][0];
        float2 r1 = *(float2*)&acc[i][1];
        float2 r2 = *(float2*)&acc[i][2];
        float2 r3 = *(float2*)&acc[i][3];
        float* dst = g_msgo + ((size_t)(b * CI + co0 + ty * 8 + i)) * N + n0 + tx * 8;
        *(float4*)dst       = make_float4(r0.x, r0.y, r1.x, r1.y);
        *(float4*)(dst + 4) = make_float4(r2.x, r2.y, r3.x, r3.y);
    }
}

// ------- bilinear x4 upsample + residual; block 0 re-zeroes GN stats -------
__global__ void upsample_add(const float* __restrict__ img,
                             const float* __restrict__ alpha,
                             float* __restrict__ out) {
    if (blockIdx.x == 0 && threadIdx.x < 64) {
        if (threadIdx.x < 32) g_qstats[threadIdx.x] = 0.f;
        else                  g_kstats[threadIdx.x - 32] = 0.f;
    }
    int t = blockIdx.x * blockDim.x + threadIdx.x;
    if (t >= B * CI * H * 48) return;
    int k2 = t % 48;
    int Y  = (t / 48) % H;
    int bc = t / (48 * H);

    int m = Y >> 2, i = Y & 3;
    int y0, y1;
    float wy;
    if (i < 2) { y0 = max(m - 1, 0); y1 = m; wy = (i == 0) ? 0.625f : 0.875f; }
    else       { y0 = m; y1 = min(m + 1, h_ - 1); wy = (i == 2) ? 0.125f : 0.375f; }

    const float* pl = g_msgo + (size_t)bc * N;
    int x0 = 2 * k2;
    int xm = max(x0 - 1, 0), x1 = x0 + 1, x2 = min(x0 + 2, w_ - 1);
    const float* r0p = pl + y0 * w_;
    const float* r1p = pl + y1 * w_;
    float wy1 = 1.f - wy;
    float pm = wy1 * r0p[xm] + wy * r1p[xm];
    float p0 = wy1 * r0p[x0] + wy * r1p[x0];
    float p1 = wy1 * r0p[x1] + wy * r1p[x1];
    float p2 = wy1 * r0p[x2] + wy * r1p[x2];

    float A = alpha[0];
    size_t base = (size_t)t * 8;
    float4 i0 = *(const float4*)(img + base);
    float4 i1 = *(const float4*)(img + base + 4);
    float4 o0, o1;
    o0.x = i0.x + A * (0.375f * pm + 0.625f * p0);
    o0.y = i0.y + A * (0.125f * pm + 0.875f * p0);
    o0.z = i0.z + A * (0.875f * p0 + 0.125f * p1);
    o0.w = i0.w + A * (0.625f * p0 + 0.375f * p1);
    o1.x = i1.x + A * (0.375f * p0 + 0.625f * p1);
    o1.y = i1.y + A * (0.125f * p0 + 0.875f * p1);
    o1.z = i1.z + A * (0.875f * p1 + 0.125f * p2);
    o1.w = i1.w + A * (0.625f * p1 + 0.375f * p2);
    *(float4*)(out + base)     = o0;
    *(float4*)(out + base + 4) = o1;
}

// ---------------- launch ----------------
extern "C" void kernel_launch(void* const* d_in, const int* in_sizes, int n_in,
                              void* d_out, int out_size) {
    const float* img_bev  = (const float*)d_in[0];
    const float* rad_bev  = (const float*)d_in[1];
    const float* occ_prob = (const float*)d_in[2];
    const float* Wq    = (const float*)d_in[3];
    const float* Wk    = (const float*)d_in[4];
    const float* Wv    = (const float*)d_in[5];
    const float* Wo    = (const float*)d_in[6];
    const float* gq_w  = (const float*)d_in[7];
    const float* gq_b  = (const float*)d_in[8];
    const float* gk_w  = (const float*)d_in[9];
    const float* gk_b  = (const float*)d_in[10];
    const float* alpha = (const float*)d_in[11];
    float* out = (float*)d_out;

    front_kernel<<<1224, 256>>>(img_bev, rad_bev, occ_prob, Wq, Wk, Wv);

    dim3 ag(w_ / TX, h_ / TY, B);
    attn_kernel<<<ag, 256>>>(gq_w, gq_b, gk_w, gk_b);

    dim3 wg(N / 128, CI / 128, B);
    wo_kernel<<<wg, 256>>>(Wo);

    upsample_add<<<(B * CI * H * 48 + 255) / 256, 256>>>(img_bev, alpha, out);
}

// round 11
// speedup vs baseline: 2.0844x; 1.0165x over previous
#include <cuda_runtime.h>

// ---------------- problem constants ----------------
constexpr int B   = 2;
constexpr int CI  = 256;
constexpr int CR  = 128;
constexpr int H   = 384;
constexpr int W   = 384;
constexpr int h_  = 96;
constexpr int w_  = 96;
constexpr int N   = h_ * w_;       // 9216
constexpr int D   = 64;
constexpr int GRP = 8;

// attention tile geometry: 8x4 pixels, 8 threads/pixel (channel octets)
constexpr int TX = 8;
constexpr int TY = 4;
constexpr int HC = TX + 6;         // 14
constexpr int HR = TY + 6;         // 10
constexpr int NCOL = HC * HR;      // 140
constexpr int C4STR = 18;          // float4 stride per col => ≡2 mod 8, conflict-free

// ---------------- scratch ----------------
__device__ float g_locc[B * N];
__device__ float g_gate[B * N];
__device__ float g_q[B * N * D];
__device__ float g_k[B * N * D];
__device__ float g_v[B * N * D];
__device__ float g_msg[B * N * D];
__device__ float g_msgo[B * CI * N];
__device__ float g_qstats[B * GRP * 2];
__device__ float g_kstats[B * GRP * 2];

// ---------------- f32x2 packed-FMA helpers ----------------
__device__ __forceinline__ unsigned long long ffma2(unsigned long long a,
                                                    unsigned long long b,
                                                    unsigned long long c) {
    unsigned long long d;
    asm("fma.rn.f32x2 %0, %1, %2, %3;" : "=l"(d) : "l"(a), "l"(b), "l"(c));
    return d;
}
__device__ __forceinline__ unsigned long long pack2(float x) {
    unsigned long long d;
    asm("mov.b64 %0, {%1, %2};" : "=l"(d)
        : "r"(__float_as_uint(x)), "r"(__float_as_uint(x)));
    return d;
}
__device__ __forceinline__ float2 ffma2v(float2 a, float2 b, float2 c) {
    float2 d;
    asm("fma.rn.f32x2 %0, %1, %2, %3;"
        : "=l"(reinterpret_cast<unsigned long long&>(d))
        : "l"(reinterpret_cast<unsigned long long&>(a)),
          "l"(reinterpret_cast<unsigned long long&>(b)),
          "l"(reinterpret_cast<unsigned long long&>(c)));
    return d;
}

// ================= merged front kernel, 64-pixel tiles =================
// blocks [0,288): fused avgpool+Wq proj (+GN q stats), 64n x 64o tile
// blocks [288,576): fused maxpool+Wk/Wv proj (+GN k stats)
// blocks [576,648): occ maxpool -> locc/gate
__global__ __launch_bounds__(256) void front_kernel(
    const float* __restrict__ img, const float* __restrict__ rad,
    const float* __restrict__ occ,
    const float* __restrict__ Wq, const float* __restrict__ Wk,
    const float* __restrict__ Wv) {
    __shared__ __align__(16) float sm[2 * 2176 + 2048];   // 25.6 KB
    int bid = blockIdx.x;
    int tid = threadIdx.x;

    if (bid < 288) {
        // ---------------- proj_q: 64n x 64o, K-tile 32 ----------------
        float* Ws = sm;            // [c][o] stride 68 (float4-aligned)
        float* Is = sm + 2176;     // [c][n] 32x64
        int b  = bid / 144;
        int n0 = (bid % 144) * 64;
        int tx = tid & 15;         // n quad
        int ty = tid >> 4;         // o quad (0..15)
        float acc[4][4] = {};

        for (int c0 = 0; c0 < CI; c0 += 32) {
            for (int i = tid; i < 2048; i += 256) {
                int c = i & 31, o = i >> 5;
                Ws[c * 68 + o] = Wq[o * CI + c0 + c];
            }
            for (int i = tid; i < 2048; i += 256) {
                int c = i >> 6, x = i & 63;
                int n = n0 + x;
                int yy = n / 96, xx = n - yy * 96;
                const float* p = img + (((size_t)(b * CI + c0 + c) * H + yy * 4) * W) + xx * 4;
                float s = 0.f;
#pragma unroll
                for (int r = 0; r < 4; r++) {
                    float4 v = __ldcs((const float4*)(p + r * W));
                    s += v.x + v.y + v.z + v.w;
                }
                Is[c * 64 + x] = s * 0.0625f;
            }
            __syncthreads();
#pragma unroll
            for (int c = 0; c < 32; c++) {
                float4 a4 = *(const float4*)&Ws[c * 68 + ty * 4];
                float4 b4 = *(const float4*)&Is[c * 64 + tx * 4];
                acc[0][0] += a4.x * b4.x; acc[0][1] += a4.x * b4.y;
                acc[0][2] += a4.x * b4.z; acc[0][3] += a4.x * b4.w;
                acc[1][0] += a4.y * b4.x; acc[1][1] += a4.y * b4.y;
                acc[1][2] += a4.y * b4.z; acc[1][3] += a4.y * b4.w;
                acc[2][0] += a4.z * b4.x; acc[2][1] += a4.z * b4.y;
                acc[2][2] += a4.z * b4.z; acc[2][3] += a4.z * b4.w;
                acc[3][0] += a4.w * b4.x; acc[3][1] += a4.w * b4.y;
                acc[3][2] += a4.w * b4.z; acc[3][3] += a4.w * b4.w;
            }
            __syncthreads();
        }

        float s = 0.f, s2 = 0.f;
#pragma unroll
        for (int j = 0; j < 4; j++) {
            float4 o4 = make_float4(acc[0][j], acc[1][j], acc[2][j], acc[3][j]);
            *(float4*)(g_q + ((size_t)(b * N + n0 + tx * 4 + j)) * 64 + ty * 4) = o4;
            s  += o4.x + o4.y + o4.z + o4.w;
            s2 += o4.x * o4.x + o4.y * o4.y + o4.z * o4.z + o4.w * o4.w;
        }
        // warp w covers o in [8w, 8w+8) == group w
#pragma unroll
        for (int off = 16; off; off >>= 1) {
            s  += __shfl_down_sync(0xffffffffu, s,  off);
            s2 += __shfl_down_sync(0xffffffffu, s2, off);
        }
        if ((tid & 31) == 0) {
            int g = tid >> 5;
            atomicAdd(&g_qstats[(b * 8 + g) * 2 + 0], s);
            atomicAdd(&g_qstats[(b * 8 + g) * 2 + 1], s2);
        }
    } else if (bid < 576) {
        // ---------------- proj_kv: 64n x 64o ----------------
        float* Wks = sm;
        float* Wvs = sm + 2176;
        float* Is  = sm + 4352;
        int pb = bid - 288;
        int b  = pb / 144;
        int n0 = (pb % 144) * 64;
        int tx = tid & 15;
        int ty = tid >> 4;
        float ak[4][4] = {};
        float av[4][4] = {};

        for (int c0 = 0; c0 < CR; c0 += 32) {
            for (int i = tid; i < 2048; i += 256) {
                int c = i & 31, o = i >> 5;
                Wks[c * 68 + o] = Wk[o * CR + c0 + c];
                Wvs[c * 68 + o] = Wv[o * CR + c0 + c];
            }
            for (int i = tid; i < 2048; i += 256) {
                int c = i >> 6, x = i & 63;
                int n = n0 + x;
                int yy = n / 96, xx = n - yy * 96;
                const float* p = rad + (((size_t)(b * CR + c0 + c) * H + yy * 4) * W) + xx * 4;
                float m = -3.4e38f;
#pragma unroll
                for (int r = 0; r < 4; r++) {
                    float4 v = __ldcs((const float4*)(p + r * W));
                    m = fmaxf(m, fmaxf(fmaxf(v.x, v.y), fmaxf(v.z, v.w)));
                }
                Is[c * 64 + x] = m;
            }
            __syncthreads();
#pragma unroll
            for (int c = 0; c < 32; c++) {
                float4 ka = *(const float4*)&Wks[c * 68 + ty * 4];
                float4 va = *(const float4*)&Wvs[c * 68 + ty * 4];
                float4 b4 = *(const float4*)&Is[c * 64 + tx * 4];
                ak[0][0] += ka.x * b4.x; ak[0][1] += ka.x * b4.y;
                ak[0][2] += ka.x * b4.z; ak[0][3] += ka.x * b4.w;
                ak[1][0] += ka.y * b4.x; ak[1][1] += ka.y * b4.y;
                ak[1][2] += ka.y * b4.z; ak[1][3] += ka.y * b4.w;
                ak[2][0] += ka.z * b4.x; ak[2][1] += ka.z * b4.y;
                ak[2][2] += ka.z * b4.z; ak[2][3] += ka.z * b4.w;
                ak[3][0] += ka.w * b4.x; ak[3][1] += ka.w * b4.y;
                ak[3][2] += ka.w * b4.z; ak[3][3] += ka.w * b4.w;
                av[0][0] += va.x * b4.x; av[0][1] += va.x * b4.y;
                av[0][2] += va.x * b4.z; av[0][3] += va.x * b4.w;
                av[1][0] += va.y * b4.x; av[1][1] += va.y * b4.y;
                av[1][2] += va.y * b4.z; av[1][3] += va.y * b4.w;
                av[2][0] += va.z * b4.x; av[2][1] += va.z * b4.y;
                av[2][2] += va.z * b4.z; av[2][3] += va.z * b4.w;
                av[3][0] += va.w * b4.x; av[3][1] += va.w * b4.y;
                av[3][2] += va.w * b4.z; av[3][3] += va.w * b4.w;
            }
            __syncthreads();
        }

        float s = 0.f, s2 = 0.f;
#pragma unroll
        for (int j = 0; j < 4; j++) {
            size_t row = ((size_t)(b * N + n0 + tx * 4 + j)) * 64 + ty * 4;
            float4 k4 = make_float4(ak[0][j], ak[1][j], ak[2][j], ak[3][j]);
            float4 v4 = make_float4(av[0][j], av[1][j], av[2][j], av[3][j]);
            *(float4*)(g_k + row) = k4;
            *(float4*)(g_v + row) = v4;
            s  += k4.x + k4.y + k4.z + k4.w;
            s2 += k4.x * k4.x + k4.y * k4.y + k4.z * k4.z + k4.w * k4.w;
        }
#pragma unroll
        for (int off = 16; off; off >>= 1) {
            s  += __shfl_down_sync(0xffffffffu, s,  off);
            s2 += __shfl_down_sync(0xffffffffu, s2, off);
        }
        if ((tid & 31) == 0) {
            int g = tid >> 5;
            atomicAdd(&g_kstats[(b * 8 + g) * 2 + 0], s);
            atomicAdd(&g_kstats[(b * 8 + g) * 2 + 1], s2);
        }
    } else {
        // ---------------- pool_occ ----------------
        int t = (bid - 576) * 256 + tid;
        if (t >= B * N) return;
        int x = t % w_;
        int y = (t / w_) % h_;
        int b = t / N;
        const float* p = occ + ((size_t)b * H + y * 4) * W + x * 4;
        float m = -3.4e38f;
#pragma unroll
        for (int r = 0; r < 4; r++) {
            float4 v = __ldcs((const float4*)(p + r * W));
            m = fmaxf(m, fmaxf(fmaxf(v.x, v.y), fmaxf(v.z, v.w)));
        }
        g_locc[t] = 2.f * logf(fmaxf(m, 1e-6f));
        g_gate[t] = fminf(fmaxf(m, 0.f), 1.f);
    }
}

// ------------- attention: 8 threads/pixel (unchanged from R10) ------------
__global__ __launch_bounds__(256, 4)
void attn_kernel(const float* __restrict__ gq_w, const float* __restrict__ gq_b,
                 const float* __restrict__ gk_w, const float* __restrict__ gk_b) {
    __shared__ float4 kv_s[NCOL * C4STR];
    __shared__ float  w_s[32 * 49];
    __shared__ float  locc_s[NCOL];
    __shared__ float  sQA[64], sQB[64], sAk[64], sBk[64];

    int x0 = blockIdx.x * TX, y0 = blockIdx.y * TY, b = blockIdx.z;
    int tid  = threadIdx.x;
    int wrp  = tid >> 5;
    int lane = tid & 31;
    int r    = wrp >> 1;
    int pix  = (wrp & 1) * 4 + (lane & 3);
    int oct  = lane >> 2;

    if (tid < 64) {
        int d = tid, g = d >> 3;
        const float inv = 1.f / (float)(N * 8);
        float su  = g_qstats[(b * 8 + g) * 2 + 0];
        float su2 = g_qstats[(b * 8 + g) * 2 + 1];
        float mu = su * inv;
        float rs = rsqrtf(su2 * inv - mu * mu + 1e-5f);
        float A = rs * gq_w[d];
        sQA[d] = A;
        sQB[d] = gq_b[d] - mu * A;
        su  = g_kstats[(b * 8 + g) * 2 + 0];
        su2 = g_kstats[(b * 8 + g) * 2 + 1];
        mu = su * inv;
        rs = rsqrtf(su2 * inv - mu * mu + 1e-5f);
        A = rs * gk_w[d];
        sAk[d] = A;
        sBk[d] = gk_b[d] - mu * A;
    }

    for (int i = tid; i < NCOL * 16; i += 256) {
        int col = i >> 4, quad = i & 15;
        int rr = col / HC, cc = col - rr * HC;
        int yy = y0 - 3 + rr, xx = x0 - 3 + cc;
        bool ok = ((unsigned)yy < (unsigned)h_) && ((unsigned)xx < (unsigned)w_);
        int nn = b * N + yy * w_ + xx;
        float4 v = make_float4(0.f, 0.f, 0.f, 0.f);
        if (ok) v = *(const float4*)(g_k + (size_t)nn * 64 + quad * 4);
        kv_s[col * C4STR + quad] = v;
        if (quad == 0) locc_s[col] = ok ? g_locc[nn] : 0.f;
    }
    __syncthreads();

    int nq = b * N + (y0 + r) * w_ + x0 + pix;

    float2 qp[4];
    float qB;
    {
        const float* qr = g_q + (size_t)nq * 64;
        float4 qa = *(const float4*)(qr + oct * 4);
        float4 qb = *(const float4*)(qr + 32 + oct * 4);
        int da = oct * 4, db = 32 + oct * 4;
        float n0 = qa.x * sQA[da + 0] + sQB[da + 0];
        float n1 = qa.y * sQA[da + 1] + sQB[da + 1];
        float n2 = qa.z * sQA[da + 2] + sQB[da + 2];
        float n3 = qa.w * sQA[da + 3] + sQB[da + 3];
        float n4 = qb.x * sQA[db + 0] + sQB[db + 0];
        float n5 = qb.y * sQA[db + 1] + sQB[db + 1];
        float n6 = qb.z * sQA[db + 2] + sQB[db + 2];
        float n7 = qb.w * sQA[db + 3] + sQB[db + 3];
        qB = n0 * sBk[da + 0] + n1 * sBk[da + 1] + n2 * sBk[da + 2] + n3 * sBk[da + 3]
           + n4 * sBk[db + 0] + n5 * sBk[db + 1] + n6 * sBk[db + 2] + n7 * sBk[db + 3];
        qp[0] = make_float2(n0 * sAk[da + 0] * 0.125f, n1 * sAk[da + 1] * 0.125f);
        qp[1] = make_float2(n2 * sAk[da + 2] * 0.125f, n3 * sAk[da + 3] * 0.125f);
        qp[2] = make_float2(n4 * sAk[db + 0] * 0.125f, n5 * sAk[db + 1] * 0.125f);
        qp[3] = make_float2(n6 * sAk[db + 2] * 0.125f, n7 * sAk[db + 3] * 0.125f);
    }
    qB += __shfl_xor_sync(0xffffffffu, qB, 4);
    qB += __shfl_xor_sync(0xffffffffu, qB, 8);
    qB += __shfl_xor_sync(0xffffffffu, qB, 16);
    float qB2 = qB * 0.125f;

    const float LPAD = -27.631021115928547f;
    const float4* kbase = &kv_s[(r * HC + pix) * C4STR];

    float lg[7];
    float m_own = -1e30f;

#pragma unroll
    for (int p = 0; p < 49; p++) {
        int dy = p / 7, dx = p - dy * 7;
        const float4* kp = kbase + (dy * HC + dx) * C4STR;
        float4 ka = kp[oct];
        float4 kb = kp[oct + 8];
        float2 a2 = make_float2(0.f, 0.f);
        a2 = ffma2v(qp[0], make_float2(ka.x, ka.y), a2);
        a2 = ffma2v(qp[2], make_float2(kb.x, kb.y), a2);
        float2 b2 = make_float2(0.f, 0.f);
        b2 = ffma2v(qp[1], make_float2(ka.z, ka.w), b2);
        b2 = ffma2v(qp[3], make_float2(kb.z, kb.w), b2);
        float dot = a2.x + a2.y + b2.x + b2.y;
        dot += __shfl_xor_sync(0xffffffffu, dot, 4);
        dot += __shfl_xor_sync(0xffffffffu, dot, 8);
        dot += __shfl_xor_sync(0xffffffffu, dot, 16);

        if (oct == (p & 7)) {
            int yy = y0 + r + dy - 3;
            int xx = x0 + pix + dx - 3;
            bool inb = ((unsigned)yy < (unsigned)h_) && ((unsigned)xx < (unsigned)w_);
            int col = (r + dy) * HC + pix + dx;
            float logit = inb ? (dot + qB2 + locc_s[col]) : LPAD;
            lg[p >> 3] = logit;
            m_own = fmaxf(m_own, logit);
        }
    }

    m_own = fmaxf(m_own, __shfl_xor_sync(0xffffffffu, m_own, 4));
    m_own = fmaxf(m_own, __shfl_xor_sync(0xffffffffu, m_own, 8));
    m_own = fmaxf(m_own, __shfl_xor_sync(0xffffffffu, m_own, 16));
    int px_idx = r * 8 + pix;
    float* wr = &w_s[px_idx * 49];
    float ssum = 0.f;
#pragma unroll
    for (int g = 0; g < 7; g++) {
        if (g < 6 || oct == 0) {
            float e = __expf(lg[g] - m_own);
            ssum += e;
            wr[g * 8 + oct] = e;
        }
    }
    ssum += __shfl_xor_sync(0xffffffffu, ssum, 4);
    ssum += __shfl_xor_sync(0xffffffffu, ssum, 8);
    ssum += __shfl_xor_sync(0xffffffffu, ssum, 16);
    float gs = g_gate[nq] / ssum;

    __syncthreads();
    for (int i = tid; i < NCOL * 16; i += 256) {
        int col = i >> 4, quad = i & 15;
        int rr = col / HC, cc = col - rr * HC;
        int yy = y0 - 3 + rr, xx = x0 - 3 + cc;
        bool ok = ((unsigned)yy < (unsigned)h_) && ((unsigned)xx < (unsigned)w_);
        float4 v = make_float4(0.f, 0.f, 0.f, 0.f);
        if (ok) v = *(const float4*)(g_v + ((size_t)(b * N + yy * w_ + xx)) * 64 + quad * 4);
        kv_s[col * C4STR + quad] = v;
    }
    __syncthreads();

    float2 acc[4];
#pragma unroll
    for (int c = 0; c < 4; c++) acc[c] = make_float2(0.f, 0.f);
#pragma unroll
    for (int p = 0; p < 49; p++) {
        int dy = p / 7, dx = p - dy * 7;
        float wgt = wr[p];
        float2 w2 = make_float2(wgt, wgt);
        const float4* vp = kbase + (dy * HC + dx) * C4STR;
        float4 va = vp[oct];
        float4 vb = vp[oct + 8];
        acc[0] = ffma2v(w2, make_float2(va.x, va.y), acc[0]);
        acc[1] = ffma2v(w2, make_float2(va.z, va.w), acc[1]);
        acc[2] = ffma2v(w2, make_float2(vb.x, vb.y), acc[2]);
        acc[3] = ffma2v(w2, make_float2(vb.z, vb.w), acc[3]);
    }
    float* mp = g_msg + (size_t)nq * 64;
    *(float4*)(mp + oct * 4)      = make_float4(acc[0].x * gs, acc[0].y * gs,
                                                acc[1].x * gs, acc[1].y * gs);
    *(float4*)(mp + 32 + oct * 4) = make_float4(acc[2].x * gs, acc[2].y * gs,
                                                acc[3].x * gs, acc[3].y * gs);
}

// ---------------- Wo projection with packed f32x2 FMA (unchanged) ---------
__global__ __launch_bounds__(256) void wo_kernel(const float* __restrict__ Wo) {
    __shared__ float Ws[32 * 132];
    __shared__ float Ms[32 * 132];
    int b   = blockIdx.z;
    int co0 = blockIdx.y * 128;
    int n0  = blockIdx.x * 128;
    int tid = threadIdx.x;
    int tx = tid & 15;
    int ty = tid >> 4;

    unsigned long long acc[8][4] = {};

    for (int kc = 0; kc < 2; kc++) {
        int d0 = kc * 32;
        for (int idx = tid; idx < 1024; idx += 256) {
            int r = idx >> 3, dq = idx & 7;
            float4 v = *(const float4*)(Wo + (size_t)(co0 + r) * 64 + d0 + dq * 4);
            Ws[(dq * 4 + 0) * 132 + r] = v.x;
            Ws[(dq * 4 + 1) * 132 + r] = v.y;
            Ws[(dq * 4 + 2) * 132 + r] = v.z;
            Ws[(dq * 4 + 3) * 132 + r] = v.w;
            float4 u = *(const float4*)(g_msg + ((size_t)(b * N + n0 + r)) * 64 + d0 + dq * 4);
            Ms[(dq * 4 + 0) * 132 + r] = u.x;
            Ms[(dq * 4 + 1) * 132 + r] = u.y;
            Ms[(dq * 4 + 2) * 132 + r] = u.z;
            Ms[(dq * 4 + 3) * 132 + r] = u.w;
        }
        __syncthreads();
#pragma unroll
        for (int d = 0; d < 32; d++) {
            unsigned long long b2[4];
#pragma unroll
            for (int jp = 0; jp < 4; jp++)
                b2[jp] = *(const unsigned long long*)&Ms[d * 132 + tx * 8 + jp * 2];
#pragma unroll
            for (int i = 0; i < 8; i++) {
                unsigned long long a2 = pack2(Ws[d * 132 + ty * 8 + i]);
#pragma unroll
                for (int jp = 0; jp < 4; jp++)
                    acc[i][jp] = ffma2(a2, b2[jp], acc[i][jp]);
            }
        }
        __syncthreads();
    }
#pragma unroll
    for (int i = 0; i < 8; i++) {
        float2 r0 = *(float2*)&acc[i][0];
        float2 r1 = *(float2*)&acc[i][1];
        float2 r2 = *(float2*)&acc[i][2];
        float2 r3 = *(float2*)&acc[i][3];
        float* dst = g_msgo + ((size_t)(b * CI + co0 + ty * 8 + i)) * N + n0 + tx * 8;
        *(float4*)dst       = make_float4(r0.x, r0.y, r1.x, r1.y);
        *(float4*)(dst + 4) = make_float4(r2.x, r2.y, r3.x, r3.y);
    }
}

// ------- bilinear x4 upsample + residual; streaming loads/stores ----------
__global__ void upsample_add(const float* __restrict__ img,
                             const float* __restrict__ alpha,
                             float* __restrict__ out) {
    if (blockIdx.x == 0 && threadIdx.x < 64) {
        if (threadIdx.x < 32) g_qstats[threadIdx.x] = 0.f;
        else                  g_kstats[threadIdx.x - 32] = 0.f;
    }
    int t = blockIdx.x * blockDim.x + threadIdx.x;
    if (t >= B * CI * H * 48) return;
    int k2 = t % 48;
    int Y  = (t / 48) % H;
    int bc = t / (48 * H);

    int m = Y >> 2, i = Y & 3;
    int y0, y1;
    float wy;
    if (i < 2) { y0 = max(m - 1, 0); y1 = m; wy = (i == 0) ? 0.625f : 0.875f; }
    else       { y0 = m; y1 = min(m + 1, h_ - 1); wy = (i == 2) ? 0.125f : 0.375f; }

    const float* pl = g_msgo + (size_t)bc * N;
    int x0 = 2 * k2;
    int xm = max(x0 - 1, 0), x1 = x0 + 1, x2 = min(x0 + 2, w_ - 1);
    const float* r0p = pl + y0 * w_;
    const float* r1p = pl + y1 * w_;
    float wy1 = 1.f - wy;
    float pm = wy1 * r0p[xm] + wy * r1p[xm];
    float p0 = wy1 * r0p[x0] + wy * r1p[x0];
    float p1 = wy1 * r0p[x1] + wy * r1p[x1];
    float p2 = wy1 * r0p[x2] + wy * r1p[x2];

    float A = alpha[0];
    size_t base = (size_t)t * 8;
    float4 i0 = __ldcs((const float4*)(img + base));
    float4 i1 = __ldcs((const float4*)(img + base + 4));
    float4 o0, o1;
    o0.x = i0.x + A * (0.375f * pm + 0.625f * p0);
    o0.y = i0.y + A * (0.125f * pm + 0.875f * p0);
    o0.z = i0.z + A * (0.875f * p0 + 0.125f * p1);
    o0.w = i0.w + A * (0.625f * p0 + 0.375f * p1);
    o1.x = i1.x + A * (0.375f * p0 + 0.625f * p1);
    o1.y = i1.y + A * (0.125f * p0 + 0.875f * p1);
    o1.z = i1.z + A * (0.875f * p1 + 0.125f * p2);
    o1.w = i1.w + A * (0.625f * p1 + 0.375f * p2);
    __stcs((float4*)(out + base),     o0);
    __stcs((float4*)(out + base + 4), o1);
}

// ---------------- launch ----------------
extern "C" void kernel_launch(void* const* d_in, const int* in_sizes, int n_in,
                              void* d_out, int out_size) {
    const float* img_bev  = (const float*)d_in[0];
    const float* rad_bev  = (const float*)d_in[1];
    const float* occ_prob = (const float*)d_in[2];
    const float* Wq    = (const float*)d_in[3];
    const float* Wk    = (const float*)d_in[4];
    const float* Wv    = (const float*)d_in[5];
    const float* Wo    = (const float*)d_in[6];
    const float* gq_w  = (const float*)d_in[7];
    const float* gq_b  = (const float*)d_in[8];
    const float* gk_w  = (const float*)d_in[9];
    const float* gk_b  = (const float*)d_in[10];
    const float* alpha = (const float*)d_in[11];
    float* out = (float*)d_out;

    front_kernel<<<648, 256>>>(img_bev, rad_bev, occ_prob, Wq, Wk, Wv);

    dim3 ag(w_ / TX, h_ / TY, B);
    attn_kernel<<<ag, 256>>>(gq_w, gq_b, gk_w, gk_b);

    dim3 wg(N / 128, CI / 128, B);
    wo_kernel<<<wg, 256>>>(Wo);

    upsample_add<<<(B * CI * H * 48 + 255) / 256, 256>>>(img_bev, alpha, out);
}

// round 12
// speedup vs baseline: 2.2025x; 1.0567x over previous
#include <cuda_runtime.h>

// ---------------- problem constants ----------------
constexpr int B   = 2;
constexpr int CI  = 256;
constexpr int CR  = 128;
constexpr int H   = 384;
constexpr int W   = 384;
constexpr int h_  = 96;
constexpr int w_  = 96;
constexpr int N   = h_ * w_;       // 9216
constexpr int D   = 64;
constexpr int GRP = 8;

// attention tile geometry: 8x4 pixels, 8 threads/pixel (channel octets)
constexpr int TX = 8;
constexpr int TY = 4;
constexpr int HC = TX + 6;         // 14
constexpr int HR = TY + 6;         // 10
constexpr int NCOL = HC * HR;      // 140
constexpr int C4STR = 18;          // float4 stride per col => ≡2 mod 8, conflict-free

// ---------------- scratch ----------------
__device__ float g_locc[B * N];
__device__ float g_gate[B * N];
__device__ float g_q[B * N * D];
__device__ float g_k[B * N * D];
__device__ float g_v[B * N * D];
__device__ float g_msg[B * N * D];
__device__ float g_msgo[B * CI * N];
__device__ float g_qstats[B * GRP * 2];   // [b*16 .. b*16+16)
__device__ float g_kstats[B * GRP * 2];

// ---------------- f32x2 packed-FMA helpers ----------------
__device__ __forceinline__ unsigned long long ffma2(unsigned long long a,
                                                    unsigned long long b,
                                                    unsigned long long c) {
    unsigned long long d;
    asm("fma.rn.f32x2 %0, %1, %2, %3;" : "=l"(d) : "l"(a), "l"(b), "l"(c));
    return d;
}
__device__ __forceinline__ unsigned long long pack2(float x) {
    unsigned long long d;
    asm("mov.b64 %0, {%1, %2};" : "=l"(d)
        : "r"(__float_as_uint(x)), "r"(__float_as_uint(x)));
    return d;
}
__device__ __forceinline__ float2 ffma2v(float2 a, float2 b, float2 c) {
    float2 d;
    asm("fma.rn.f32x2 %0, %1, %2, %3;"
        : "=l"(reinterpret_cast<unsigned long long&>(d))
        : "l"(reinterpret_cast<unsigned long long&>(a)),
          "l"(reinterpret_cast<unsigned long long&>(b)),
          "l"(reinterpret_cast<unsigned long long&>(c)));
    return d;
}

// ================= per-batch front kernel =================
// blocks [0,144): fused avgpool+Wq proj (+GN q stats), 64n x 64o tile
// blocks [144,288): fused maxpool+Wk/Wv proj (+GN k stats)
// blocks [288,324): occ maxpool -> locc/gate
__global__ __launch_bounds__(256) void front_kernel(
    int b,
    const float* __restrict__ img, const float* __restrict__ rad,
    const float* __restrict__ occ,
    const float* __restrict__ Wq, const float* __restrict__ Wk,
    const float* __restrict__ Wv) {
    __shared__ __align__(16) float sm[2 * 2176 + 2048];   // 25.6 KB
    int bid = blockIdx.x;
    int tid = threadIdx.x;

    if (bid < 144) {
        // ---------------- proj_q: 64n x 64o, K-tile 32 ----------------
        float* Ws = sm;            // [c][o] stride 68
        float* Is = sm + 2176;     // [c][n] 32x64
        int n0 = bid * 64;
        int tx = tid & 15;
        int ty = tid >> 4;
        float acc[4][4] = {};

        for (int c0 = 0; c0 < CI; c0 += 32) {
            for (int i = tid; i < 2048; i += 256) {
                int c = i & 31, o = i >> 5;
                Ws[c * 68 + o] = Wq[o * CI + c0 + c];
            }
            for (int i = tid; i < 2048; i += 256) {
                int c = i >> 6, x = i & 63;
                int n = n0 + x;
                int yy = n / 96, xx = n - yy * 96;
                const float* p = img + (((size_t)(b * CI + c0 + c) * H + yy * 4) * W) + xx * 4;
                float s = 0.f;
#pragma unroll
                for (int r = 0; r < 4; r++) {
                    float4 v = __ldcs((const float4*)(p + r * W));
                    s += v.x + v.y + v.z + v.w;
                }
                Is[c * 64 + x] = s * 0.0625f;
            }
            __syncthreads();
#pragma unroll
            for (int c = 0; c < 32; c++) {
                float4 a4 = *(const float4*)&Ws[c * 68 + ty * 4];
                float4 b4 = *(const float4*)&Is[c * 64 + tx * 4];
                acc[0][0] += a4.x * b4.x; acc[0][1] += a4.x * b4.y;
                acc[0][2] += a4.x * b4.z; acc[0][3] += a4.x * b4.w;
                acc[1][0] += a4.y * b4.x; acc[1][1] += a4.y * b4.y;
                acc[1][2] += a4.y * b4.z; acc[1][3] += a4.y * b4.w;
                acc[2][0] += a4.z * b4.x; acc[2][1] += a4.z * b4.y;
                acc[2][2] += a4.z * b4.z; acc[2][3] += a4.z * b4.w;
                acc[3][0] += a4.w * b4.x; acc[3][1] += a4.w * b4.y;
                acc[3][2] += a4.w * b4.z; acc[3][3] += a4.w * b4.w;
            }
            __syncthreads();
        }

        float s = 0.f, s2 = 0.f;
#pragma unroll
        for (int j = 0; j < 4; j++) {
            float4 o4 = make_float4(acc[0][j], acc[1][j], acc[2][j], acc[3][j]);
            *(float4*)(g_q + ((size_t)(b * N + n0 + tx * 4 + j)) * 64 + ty * 4) = o4;
            s  += o4.x + o4.y + o4.z + o4.w;
            s2 += o4.x * o4.x + o4.y * o4.y + o4.z * o4.z + o4.w * o4.w;
        }
#pragma unroll
        for (int off = 16; off; off >>= 1) {
            s  += __shfl_down_sync(0xffffffffu, s,  off);
            s2 += __shfl_down_sync(0xffffffffu, s2, off);
        }
        if ((tid & 31) == 0) {
            int g = tid >> 5;
            atomicAdd(&g_qstats[(b * 8 + g) * 2 + 0], s);
            atomicAdd(&g_qstats[(b * 8 + g) * 2 + 1], s2);
        }
    } else if (bid < 288) {
        // ---------------- proj_kv: 64n x 64o ----------------
        float* Wks = sm;
        float* Wvs = sm + 2176;
        float* Is  = sm + 4352;
        int n0 = (bid - 144) * 64;
        int tx = tid & 15;
        int ty = tid >> 4;
        float ak[4][4] = {};
        float av[4][4] = {};

        for (int c0 = 0; c0 < CR; c0 += 32) {
            for (int i = tid; i < 2048; i += 256) {
                int c = i & 31, o = i >> 5;
                Wks[c * 68 + o] = Wk[o * CR + c0 + c];
                Wvs[c * 68 + o] = Wv[o * CR + c0 + c];
            }
            for (int i = tid; i < 2048; i += 256) {
                int c = i >> 6, x = i & 63;
                int n = n0 + x;
                int yy = n / 96, xx = n - yy * 96;
                const float* p = rad + (((size_t)(b * CR + c0 + c) * H + yy * 4) * W) + xx * 4;
                float m = -3.4e38f;
#pragma unroll
                for (int r = 0; r < 4; r++) {
                    float4 v = __ldcs((const float4*)(p + r * W));
                    m = fmaxf(m, fmaxf(fmaxf(v.x, v.y), fmaxf(v.z, v.w)));
                }
                Is[c * 64 + x] = m;
            }
            __syncthreads();
#pragma unroll
            for (int c = 0; c < 32; c++) {
                float4 ka = *(const float4*)&Wks[c * 68 + ty * 4];
                float4 va = *(const float4*)&Wvs[c * 68 + ty * 4];
                float4 b4 = *(const float4*)&Is[c * 64 + tx * 4];
                ak[0][0] += ka.x * b4.x; ak[0][1] += ka.x * b4.y;
                ak[0][2] += ka.x * b4.z; ak[0][3] += ka.x * b4.w;
                ak[1][0] += ka.y * b4.x; ak[1][1] += ka.y * b4.y;
                ak[1][2] += ka.y * b4.z; ak[1][3] += ka.y * b4.w;
                ak[2][0] += ka.z * b4.x; ak[2][1] += ka.z * b4.y;
                ak[2][2] += ka.z * b4.z; ak[2][3] += ka.z * b4.w;
                ak[3][0] += ka.w * b4.x; ak[3][1] += ka.w * b4.y;
                ak[3][2] += ka.w * b4.z; ak[3][3] += ka.w * b4.w;
                av[0][0] += va.x * b4.x; av[0][1] += va.x * b4.y;
                av[0][2] += va.x * b4.z; av[0][3] += va.x * b4.w;
                av[1][0] += va.y * b4.x; av[1][1] += va.y * b4.y;
                av[1][2] += va.y * b4.z; av[1][3] += va.y * b4.w;
                av[2][0] += va.z * b4.x; av[2][1] += va.z * b4.y;
                av[2][2] += va.z * b4.z; av[2][3] += va.z * b4.w;
                av[3][0] += va.w * b4.x; av[3][1] += va.w * b4.y;
                av[3][2] += va.w * b4.z; av[3][3] += va.w * b4.w;
            }
            __syncthreads();
        }

        float s = 0.f, s2 = 0.f;
#pragma unroll
        for (int j = 0; j < 4; j++) {
            size_t row = ((size_t)(b * N + n0 + tx * 4 + j)) * 64 + ty * 4;
            float4 k4 = make_float4(ak[0][j], ak[1][j], ak[2][j], ak[3][j]);
            float4 v4 = make_float4(av[0][j], av[1][j], av[2][j], av[3][j]);
            *(float4*)(g_k + row) = k4;
            *(float4*)(g_v + row) = v4;
            s  += k4.x + k4.y + k4.z + k4.w;
            s2 += k4.x * k4.x + k4.y * k4.y + k4.z * k4.z + k4.w * k4.w;
        }
#pragma unroll
        for (int off = 16; off; off >>= 1) {
            s  += __shfl_down_sync(0xffffffffu, s,  off);
            s2 += __shfl_down_sync(0xffffffffu, s2, off);
        }
        if ((tid & 31) == 0) {
            int g = tid >> 5;
            atomicAdd(&g_kstats[(b * 8 + g) * 2 + 0], s);
            atomicAdd(&g_kstats[(b * 8 + g) * 2 + 1], s2);
        }
    } else {
        // ---------------- pool_occ (per batch) ----------------
        int t = (bid - 288) * 256 + tid;
        if (t >= N) return;
        int x = t % w_;
        int y = t / w_;
        const float* p = occ + ((size_t)b * H + y * 4) * W + x * 4;
        float m = -3.4e38f;
#pragma unroll
        for (int r = 0; r < 4; r++) {
            float4 v = __ldcs((const float4*)(p + r * W));
            m = fmaxf(m, fmaxf(fmaxf(v.x, v.y), fmaxf(v.z, v.w)));
        }
        g_locc[b * N + t] = 2.f * logf(fmaxf(m, 1e-6f));
        g_gate[b * N + t] = fminf(fmaxf(m, 0.f), 1.f);
    }
}

// ------------- attention: 8 threads/pixel (per batch) ----------------
__global__ __launch_bounds__(256, 4)
void attn_kernel(int b,
                 const float* __restrict__ gq_w, const float* __restrict__ gq_b,
                 const float* __restrict__ gk_w, const float* __restrict__ gk_b) {
    __shared__ float4 kv_s[NCOL * C4STR];
    __shared__ float  w_s[32 * 49];
    __shared__ float  locc_s[NCOL];
    __shared__ float  sQA[64], sQB[64], sAk[64], sBk[64];

    int x0 = blockIdx.x * TX, y0 = blockIdx.y * TY;
    int tid  = threadIdx.x;
    int wrp  = tid >> 5;
    int lane = tid & 31;
    int r    = wrp >> 1;
    int pix  = (wrp & 1) * 4 + (lane & 3);
    int oct  = lane >> 2;

    if (tid < 64) {
        int d = tid, g = d >> 3;
        const float inv = 1.f / (float)(N * 8);
        float su  = g_qstats[(b * 8 + g) * 2 + 0];
        float su2 = g_qstats[(b * 8 + g) * 2 + 1];
        float mu = su * inv;
        float rs = rsqrtf(su2 * inv - mu * mu + 1e-5f);
        float A = rs * gq_w[d];
        sQA[d] = A;
        sQB[d] = gq_b[d] - mu * A;
        su  = g_kstats[(b * 8 + g) * 2 + 0];
        su2 = g_kstats[(b * 8 + g) * 2 + 1];
        mu = su * inv;
        rs = rsqrtf(su2 * inv - mu * mu + 1e-5f);
        A = rs * gk_w[d];
        sAk[d] = A;
        sBk[d] = gk_b[d] - mu * A;
    }

    for (int i = tid; i < NCOL * 16; i += 256) {
        int col = i >> 4, quad = i & 15;
        int rr = col / HC, cc = col - rr * HC;
        int yy = y0 - 3 + rr, xx = x0 - 3 + cc;
        bool ok = ((unsigned)yy < (unsigned)h_) && ((unsigned)xx < (unsigned)w_);
        int nn = b * N + yy * w_ + xx;
        float4 v = make_float4(0.f, 0.f, 0.f, 0.f);
        if (ok) v = *(const float4*)(g_k + (size_t)nn * 64 + quad * 4);
        kv_s[col * C4STR + quad] = v;
        if (quad == 0) locc_s[col] = ok ? g_locc[nn] : 0.f;
    }
    __syncthreads();

    int nq = b * N + (y0 + r) * w_ + x0 + pix;

    float2 qp[4];
    float qB;
    {
        const float* qr = g_q + (size_t)nq * 64;
        float4 qa = *(const float4*)(qr + oct * 4);
        float4 qb = *(const float4*)(qr + 32 + oct * 4);
        int da = oct * 4, db = 32 + oct * 4;
        float n0 = qa.x * sQA[da + 0] + sQB[da + 0];
        float n1 = qa.y * sQA[da + 1] + sQB[da + 1];
        float n2 = qa.z * sQA[da + 2] + sQB[da + 2];
        float n3 = qa.w * sQA[da + 3] + sQB[da + 3];
        float n4 = qb.x * sQA[db + 0] + sQB[db + 0];
        float n5 = qb.y * sQA[db + 1] + sQB[db + 1];
        float n6 = qb.z * sQA[db + 2] + sQB[db + 2];
        float n7 = qb.w * sQA[db + 3] + sQB[db + 3];
        qB = n0 * sBk[da + 0] + n1 * sBk[da + 1] + n2 * sBk[da + 2] + n3 * sBk[da + 3]
           + n4 * sBk[db + 0] + n5 * sBk[db + 1] + n6 * sBk[db + 2] + n7 * sBk[db + 3];
        qp[0] = make_float2(n0 * sAk[da + 0] * 0.125f, n1 * sAk[da + 1] * 0.125f);
        qp[1] = make_float2(n2 * sAk[da + 2] * 0.125f, n3 * sAk[da + 3] * 0.125f);
        qp[2] = make_float2(n4 * sAk[db + 0] * 0.125f, n5 * sAk[db + 1] * 0.125f);
        qp[3] = make_float2(n6 * sAk[db + 2] * 0.125f, n7 * sAk[db + 3] * 0.125f);
    }
    qB += __shfl_xor_sync(0xffffffffu, qB, 4);
    qB += __shfl_xor_sync(0xffffffffu, qB, 8);
    qB += __shfl_xor_sync(0xffffffffu, qB, 16);
    float qB2 = qB * 0.125f;

    const float LPAD = -27.631021115928547f;
    const float4* kbase = &kv_s[(r * HC + pix) * C4STR];

    float lg[7];
    float m_own = -1e30f;

#pragma unroll
    for (int p = 0; p < 49; p++) {
        int dy = p / 7, dx = p - dy * 7;
        const float4* kp = kbase + (dy * HC + dx) * C4STR;
        float4 ka = kp[oct];
        float4 kb = kp[oct + 8];
        float2 a2 = make_float2(0.f, 0.f);
        a2 = ffma2v(qp[0], make_float2(ka.x, ka.y), a2);
        a2 = ffma2v(qp[2], make_float2(kb.x, kb.y), a2);
        float2 b2 = make_float2(0.f, 0.f);
        b2 = ffma2v(qp[1], make_float2(ka.z, ka.w), b2);
        b2 = ffma2v(qp[3], make_float2(kb.z, kb.w), b2);
        float dot = a2.x + a2.y + b2.x + b2.y;
        dot += __shfl_xor_sync(0xffffffffu, dot, 4);
        dot += __shfl_xor_sync(0xffffffffu, dot, 8);
        dot += __shfl_xor_sync(0xffffffffu, dot, 16);

        if (oct == (p & 7)) {
            int yy = y0 + r + dy - 3;
            int xx = x0 + pix + dx - 3;
            bool inb = ((unsigned)yy < (unsigned)h_) && ((unsigned)xx < (unsigned)w_);
            int col = (r + dy) * HC + pix + dx;
            float logit = inb ? (dot + qB2 + locc_s[col]) : LPAD;
            lg[p >> 3] = logit;
            m_own = fmaxf(m_own, logit);
        }
    }

    m_own = fmaxf(m_own, __shfl_xor_sync(0xffffffffu, m_own, 4));
    m_own = fmaxf(m_own, __shfl_xor_sync(0xffffffffu, m_own, 8));
    m_own = fmaxf(m_own, __shfl_xor_sync(0xffffffffu, m_own, 16));
    int px_idx = r * 8 + pix;
    float* wr = &w_s[px_idx * 49];
    float ssum = 0.f;
#pragma unroll
    for (int g = 0; g < 7; g++) {
        if (g < 6 || oct == 0) {
            float e = __expf(lg[g] - m_own);
            ssum += e;
            wr[g * 8 + oct] = e;
        }
    }
    ssum += __shfl_xor_sync(0xffffffffu, ssum, 4);
    ssum += __shfl_xor_sync(0xffffffffu, ssum, 8);
    ssum += __shfl_xor_sync(0xffffffffu, ssum, 16);
    float gs = g_gate[nq] / ssum;

    __syncthreads();
    for (int i = tid; i < NCOL * 16; i += 256) {
        int col = i >> 4, quad = i & 15;
        int rr = col / HC, cc = col - rr * HC;
        int yy = y0 - 3 + rr, xx = x0 - 3 + cc;
        bool ok = ((unsigned)yy < (unsigned)h_) && ((unsigned)xx < (unsigned)w_);
        float4 v = make_float4(0.f, 0.f, 0.f, 0.f);
        if (ok) v = *(const float4*)(g_v + ((size_t)(b * N + yy * w_ + xx)) * 64 + quad * 4);
        kv_s[col * C4STR + quad] = v;
    }
    __syncthreads();

    float2 acc[4];
#pragma unroll
    for (int c = 0; c < 4; c++) acc[c] = make_float2(0.f, 0.f);
#pragma unroll
    for (int p = 0; p < 49; p++) {
        int dy = p / 7, dx = p - dy * 7;
        float wgt = wr[p];
        float2 w2 = make_float2(wgt, wgt);
        const float4* vp = kbase + (dy * HC + dx) * C4STR;
        float4 va = vp[oct];
        float4 vb = vp[oct + 8];
        acc[0] = ffma2v(w2, make_float2(va.x, va.y), acc[0]);
        acc[1] = ffma2v(w2, make_float2(va.z, va.w), acc[1]);
        acc[2] = ffma2v(w2, make_float2(vb.x, vb.y), acc[2]);
        acc[3] = ffma2v(w2, make_float2(vb.z, vb.w), acc[3]);
    }
    float* mp = g_msg + (size_t)nq * 64;
    *(float4*)(mp + oct * 4)      = make_float4(acc[0].x * gs, acc[0].y * gs,
                                                acc[1].x * gs, acc[1].y * gs);
    *(float4*)(mp + 32 + oct * 4) = make_float4(acc[2].x * gs, acc[2].y * gs,
                                                acc[3].x * gs, acc[3].y * gs);
}

// ---------------- Wo projection with packed f32x2 FMA (per batch) ---------
__global__ __launch_bounds__(256) void wo_kernel(int b, const float* __restrict__ Wo) {
    __shared__ float Ws[32 * 132];
    __shared__ float Ms[32 * 132];
    int co0 = blockIdx.y * 128;
    int n0  = blockIdx.x * 128;
    int tid = threadIdx.x;
    int tx = tid & 15;
    int ty = tid >> 4;

    unsigned long long acc[8][4] = {};

    for (int kc = 0; kc < 2; kc++) {
        int d0 = kc * 32;
        for (int idx = tid; idx < 1024; idx += 256) {
            int r = idx >> 3, dq = idx & 7;
            float4 v = *(const float4*)(Wo + (size_t)(co0 + r) * 64 + d0 + dq * 4);
            Ws[(dq * 4 + 0) * 132 + r] = v.x;
            Ws[(dq * 4 + 1) * 132 + r] = v.y;
            Ws[(dq * 4 + 2) * 132 + r] = v.z;
            Ws[(dq * 4 + 3) * 132 + r] = v.w;
            float4 u = *(const float4*)(g_msg + ((size_t)(b * N + n0 + r)) * 64 + d0 + dq * 4);
            Ms[(dq * 4 + 0) * 132 + r] = u.x;
            Ms[(dq * 4 + 1) * 132 + r] = u.y;
            Ms[(dq * 4 + 2) * 132 + r] = u.z;
            Ms[(dq * 4 + 3) * 132 + r] = u.w;
        }
        __syncthreads();
#pragma unroll
        for (int d = 0; d < 32; d++) {
            unsigned long long b2[4];
#pragma unroll
            for (int jp = 0; jp < 4; jp++)
                b2[jp] = *(const unsigned long long*)&Ms[d * 132 + tx * 8 + jp * 2];
#pragma unroll
            for (int i = 0; i < 8; i++) {
                unsigned long long a2 = pack2(Ws[d * 132 + ty * 8 + i]);
#pragma unroll
                for (int jp = 0; jp < 4; jp++)
                    acc[i][jp] = ffma2(a2, b2[jp], acc[i][jp]);
            }
        }
        __syncthreads();
    }
#pragma unroll
    for (int i = 0; i < 8; i++) {
        float2 r0 = *(float2*)&acc[i][0];
        float2 r1 = *(float2*)&acc[i][1];
        float2 r2 = *(float2*)&acc[i][2];
        float2 r3 = *(float2*)&acc[i][3];
        float* dst = g_msgo + ((size_t)(b * CI + co0 + ty * 8 + i)) * N + n0 + tx * 8;
        *(float4*)dst       = make_float4(r0.x, r0.y, r1.x, r1.y);
        *(float4*)(dst + 4) = make_float4(r2.x, r2.y, r3.x, r3.y);
    }
}

// ------- bilinear x4 upsample + residual (per batch); zero own stats ------
__global__ void upsample_add(int b, const float* __restrict__ img,
                             const float* __restrict__ alpha,
                             float* __restrict__ out) {
    if (blockIdx.x == 0 && threadIdx.x < 32) {
        if (threadIdx.x < 16) g_qstats[b * 16 + threadIdx.x] = 0.f;
        else                  g_kstats[b * 16 + threadIdx.x - 16] = 0.f;
    }
    int t = blockIdx.x * blockDim.x + threadIdx.x;
    if (t >= CI * H * 48) return;
    int k2 = t % 48;
    int Y  = (t / 48) % H;
    int ch = t / (48 * H);

    int m = Y >> 2, i = Y & 3;
    int y0, y1;
    float wy;
    if (i < 2) { y0 = max(m - 1, 0); y1 = m; wy = (i == 0) ? 0.625f : 0.875f; }
    else       { y0 = m; y1 = min(m + 1, h_ - 1); wy = (i == 2) ? 0.125f : 0.375f; }

    const float* pl = g_msgo + (size_t)(b * CI + ch) * N;
    int x0 = 2 * k2;
    int xm = max(x0 - 1, 0), x1 = x0 + 1, x2 = min(x0 + 2, w_ - 1);
    const float* r0p = pl + y0 * w_;
    const float* r1p = pl + y1 * w_;
    float wy1 = 1.f - wy;
    float pm = wy1 * r0p[xm] + wy * r1p[xm];
    float p0 = wy1 * r0p[x0] + wy * r1p[x0];
    float p1 = wy1 * r0p[x1] + wy * r1p[x1];
    float p2 = wy1 * r0p[x2] + wy * r1p[x2];

    float A = alpha[0];
    size_t base = ((size_t)b * CI * H * 48 + t) * 8;
    float4 i0 = __ldcs((const float4*)(img + base));
    float4 i1 = __ldcs((const float4*)(img + base + 4));
    float4 o0, o1;
    o0.x = i0.x + A * (0.375f * pm + 0.625f * p0);
    o0.y = i0.y + A * (0.125f * pm + 0.875f * p0);
    o0.z = i0.z + A * (0.875f * p0 + 0.125f * p1);
    o0.w = i0.w + A * (0.625f * p0 + 0.375f * p1);
    o1.x = i1.x + A * (0.375f * p0 + 0.625f * p1);
    o1.y = i1.y + A * (0.125f * p0 + 0.875f * p1);
    o1.z = i1.z + A * (0.875f * p1 + 0.125f * p2);
    o1.w = i1.w + A * (0.625f * p1 + 0.375f * p2);
    __stcs((float4*)(out + base),     o0);
    __stcs((float4*)(out + base + 4), o1);
}

// ---------------- launch: fork the two batch pipelines --------------------
extern "C" void kernel_launch(void* const* d_in, const int* in_sizes, int n_in,
                              void* d_out, int out_size) {
    const float* img_bev  = (const float*)d_in[0];
    const float* rad_bev  = (const float*)d_in[1];
    const float* occ_prob = (const float*)d_in[2];
    const float* Wq    = (const float*)d_in[3];
    const float* Wk    = (const float*)d_in[4];
    const float* Wv    = (const float*)d_in[5];
    const float* Wo    = (const float*)d_in[6];
    const float* gq_w  = (const float*)d_in[7];
    const float* gq_b  = (const float*)d_in[8];
    const float* gk_w  = (const float*)d_in[9];
    const float* gk_b  = (const float*)d_in[10];
    const float* alpha = (const float*)d_in[11];
    float* out = (float*)d_out;

    // Lazily create streams/events on the FIRST call (the uncaptured
    // correctness run), so no resource creation happens during capture.
    static cudaStream_t s[2];
    static cudaEvent_t ev_root, ev_done[2];
    static bool init = false;
    if (!init) {
        cudaStreamCreateWithFlags(&s[0], cudaStreamNonBlocking);
        cudaStreamCreateWithFlags(&s[1], cudaStreamNonBlocking);
        cudaEventCreateWithFlags(&ev_root,    cudaEventDisableTiming);
        cudaEventCreateWithFlags(&ev_done[0], cudaEventDisableTiming);
        cudaEventCreateWithFlags(&ev_done[1], cudaEventDisableTiming);
        init = true;
    }

    // fork from the launch (captured) stream
    cudaEventRecord(ev_root, 0);
    cudaStreamWaitEvent(s[0], ev_root, 0);
    cudaStreamWaitEvent(s[1], ev_root, 0);

    dim3 ag(w_ / TX, h_ / TY, 1);
    dim3 wg(N / 128, CI / 128, 1);
    for (int b = 0; b < 2; b++) {
        front_kernel<<<324, 256, 0, s[b]>>>(b, img_bev, rad_bev, occ_prob, Wq, Wk, Wv);
        attn_kernel<<<ag, 256, 0, s[b]>>>(b, gq_w, gq_b, gk_w, gk_b);
        wo_kernel<<<wg, 256, 0, s[b]>>>(b, Wo);
        upsample_add<<<CI * H * 48 / 256, 256, 0, s[b]>>>(b, img_bev, alpha, out);
    }

    // join back to the captured stream
    cudaEventRecord(ev_done[0], s[0]);
    cudaEventRecord(ev_done[1], s[1]);
    cudaStreamWaitEvent(0, ev_done[0], 0);
    cudaStreamWaitEvent(0, ev_done[1], 0);
}